// round 9
// baseline (speedup 1.0000x reference)
#include <cuda_runtime.h>
#include <cstddef>

#define D 64
#define MAXN 100000

typedef unsigned long long u64;

// Scratch buffers (no allocation allowed) -----------------------------------
__device__ float g_A[MAXN * D];
__device__ float g_B[MAXN * D];
__device__ float g_C[MAXN * D];
__device__ float g_M[MAXN * D];   // per-node messages
__device__ float g_AG[MAXN * D];  // aggregation
__device__ int   g_IDX[MAXN];     // composite index scratch

// ---------------------------------------------------------------------------
// packed f32x2 helpers (sm_103a: fma.rn.f32x2 doubles fp32 FMA throughput)
__device__ __forceinline__ u64 fma2(u64 a, u64 b, u64 c) {
    u64 d;
    asm("fma.rn.f32x2 %0, %1, %2, %3;" : "=l"(d) : "l"(a), "l"(b), "l"(c));
    return d;
}
__device__ __forceinline__ u64 pk2(float lo, float hi) {
    u64 r;
    asm("mov.b64 %0, {%1, %2};" : "=l"(r)
        : "r"(__float_as_uint(lo)), "r"(__float_as_uint(hi)));
    return r;
}
__device__ __forceinline__ float2 unpk(u64 p) {
    unsigned int lo, hi;
    asm("mov.b64 {%0, %1}, %2;" : "=r"(lo), "=r"(hi) : "l"(p));
    return make_float2(__uint_as_float(lo), __uint_as_float(hi));
}
union F4U { float4 v; u64 u[2]; };

// ---------------------------------------------------------------------------
__global__ __launch_bounds__(512) void zero_kernel(float4* __restrict__ p, int n4) {
    int i = blockIdx.x * blockDim.x + threadIdx.x;
    if (i < n4) p[i] = make_float4(0.f, 0.f, 0.f, 0.f);
}

// cidx[i] = a[b[i]]
__global__ __launch_bounds__(256) void compose_idx_kernel(const int* __restrict__ a,
                                                          const int* __restrict__ b,
                                                          int* __restrict__ cidx, int n) {
    int i = blockIdx.x * blockDim.x + threadIdx.x;
    if (i < n) cidx[i] = a[b[i]];
}

// aggr[r[e],:] += msg[(map?map[s[e]]:s[e]),:]   via red.global.add.v4.f32
__global__ __launch_bounds__(256) void scatter_kernel(const float* __restrict__ msg,
                                                      const int* __restrict__ s,
                                                      const int* __restrict__ r,
                                                      const int* __restrict__ map,
                                                      float* __restrict__ aggr, long E16) {
    for (long i = (long)blockIdx.x * 256 + threadIdx.x; i < E16;
         i += (long)gridDim.x * 256) {
        int e = (int)(i >> 4);
        int c = (int)(i & 15);
        int se = __ldg(&s[e]);
        if (map) se = __ldg(&map[se]);
        int re = __ldg(&r[e]);
        float4 v = __ldg((const float4*)msg + (size_t)se * 16 + c);
        float* dst = aggr + (size_t)re * 64 + c * 4;
        asm volatile("red.global.add.v4.f32 [%0], {%1,%2,%3,%4};"
                     :: "l"(dst), "f"(v.x), "f"(v.y), "f"(v.z), "f"(v.w)
                     : "memory");
    }
}

// ---------------------------------------------------------------------------
// Register-tiled 2-layer MLP, f32x2-FMA, K-paired weights, low-smem (~50KB)
// for 4 blocks/SM.  out[row] = relu(X[row]@W1+b1)@W2+b2 (+skip[row]).
// X rows: [in0 | in1] when IN==128 (two 64-col halves through one staging
// buffer), else in0 (row width IN). in0 rows indexed via rowidx0 (if set),
// in1 rows via rowidx1 (if set); out/skip rows are compact (direct).
// The X buffer is re-used for Y between GEMM1 and GEMM2 (sync-guarded).
// If zero_out != null, those rows of zero_out are zeroed (fused zeroing).
// 256 threads; tile = 64 rows x 64 cols; thread tile = 4 rows x 4 cols,
// cols {2tc, 2tc+1, 2tc+32, 2tc+33}; accumulator b64 halves = even/odd k.
// ---------------------------------------------------------------------------
template <int IN>
__global__ __launch_bounds__(256, 4) void mlp2_tiled(const float* __restrict__ in0,
                                                     const float* __restrict__ in1,
                                                     const int* __restrict__ rowidx0,
                                                     const int* __restrict__ rowidx1,
                                                     const float* __restrict__ W1,
                                                     const float* __restrict__ b1,
                                                     const float* __restrict__ W2,
                                                     const float* __restrict__ b2,
                                                     const float* __restrict__ skip,
                                                     float* __restrict__ out,
                                                     float* __restrict__ zero_out, int n) {
    extern __shared__ __align__(16) float sm[];
    u64* Wp  = (u64*)sm;                           // 32*64 u64: W1 (or half)
    u64* W2p = Wp + 32 * 64;                       // 32*64 u64
    float* b1s = (float*)(W2p + 32 * 64);          // 64
    float* b2s = b1s + 64;                         // 64
    float* xy  = b2s + 64;                         // 64*68 floats (X half / Y)

    const int t = threadIdx.x;
    constexpr int XC = (IN < 64) ? IN : 64;        // X cols staged per phase
    constexpr int NH = (IN == 128) ? 2 : 1;        // halves

    // stage W2 pairs + biases once
    for (int i = t; i < 32 * 64; i += 256) {
        int k2 = i >> 6, c = i & 63;
        W2p[i] = pk2(W2[(2 * k2) * 64 + c], W2[(2 * k2 + 1) * 64 + c]);
    }
    if (t < 64) { b1s[t] = b1[t]; b2s[t] = b2[t]; }
    __syncthreads();   // b1s/b2s/W2p visible before ANY use

    const int tc = t & 15;
    const int tr = t >> 4;
    const int c0 = tc * 2, c2 = c0 + 32;
    const int r0 = tr * 4;
    const int tiles = (n + 63) >> 6;

    for (int tile = blockIdx.x; tile < tiles; tile += gridDim.x) {
        const int base = tile * 64;

        u64 a[4][4];
#pragma unroll
        for (int i = 0; i < 4; i++) {
            a[i][0] = pk2(b1s[c0], 0.f);
            a[i][1] = pk2(b1s[c0 + 1], 0.f);
            a[i][2] = pk2(b1s[c2], 0.f);
            a[i][3] = pk2(b1s[c2 + 1], 0.f);
        }

#pragma unroll
        for (int h = 0; h < NH; h++) {
            // stage W1 half (K-paired): whole W1 when IN<=64
            for (int i = t; i < (XC / 2) * 64; i += 256) {
                int k2 = i >> 6, c = i & 63;
                const float* Ws = W1 + h * 64 * 64;
                Wp[i] = pk2(Ws[(2 * k2) * 64 + c], Ws[(2 * k2 + 1) * 64 + c]);
            }
            // stage X columns for this half
            constexpr int C4 = XC / 4;
            for (int i = t; i < 64 * C4; i += 256) {
                int row = i / C4, col = (i % C4) * 4;
                int node = base + row;
                float4 v = make_float4(0.f, 0.f, 0.f, 0.f);
                if (node < n) {
                    const float* p;
                    int src;
                    if (h == 0) {
                        p = in0;
                        src = rowidx0 ? rowidx0[node] : node;
                    } else {
                        p = in1;
                        src = rowidx1 ? rowidx1[node] : node;
                    }
                    v = *(const float4*)&p[(size_t)src * XC + col];
                }
                *(float4*)&xy[row * 68 + col] = v;
            }
            __syncthreads();
            // accumulate over this half's K
#pragma unroll 8
            for (int k = 0; k < XC; k += 4) {
                F4U xq[4];
#pragma unroll
                for (int i = 0; i < 4; i++)
                    xq[i].v = *(const float4*)&xy[(r0 + i) * 68 + k];
#pragma unroll
                for (int kk2 = 0; kk2 < 2; kk2++) {
                    ulonglong2 wA = *(const ulonglong2*)&Wp[(k / 2 + kk2) * 64 + c0];
                    ulonglong2 wB = *(const ulonglong2*)&Wp[(k / 2 + kk2) * 64 + c2];
#pragma unroll
                    for (int i = 0; i < 4; i++) {
                        u64 xp = xq[i].u[kk2];
                        a[i][0] = fma2(xp, wA.x, a[i][0]);
                        a[i][1] = fma2(xp, wA.y, a[i][1]);
                        a[i][2] = fma2(xp, wB.x, a[i][2]);
                        a[i][3] = fma2(xp, wB.y, a[i][3]);
                    }
                }
            }
            __syncthreads();   // all reads of xy/Wp done before overwrite
        }

        // relu + write Y into xy (aliased, safe after sync)
#pragma unroll
        for (int i = 0; i < 4; i++) {
            float2 q0 = unpk(a[i][0]), q1 = unpk(a[i][1]);
            float2 q2 = unpk(a[i][2]), q3 = unpk(a[i][3]);
            float2 vA = make_float2(fmaxf(q0.x + q0.y, 0.f), fmaxf(q1.x + q1.y, 0.f));
            float2 vB = make_float2(fmaxf(q2.x + q2.y, 0.f), fmaxf(q3.x + q3.y, 0.f));
            *(float2*)&xy[(r0 + i) * 68 + c0] = vA;
            *(float2*)&xy[(r0 + i) * 68 + c2] = vB;
        }
        __syncthreads();

        // ---- GEMM2: out = Y @ W2 + b2 (+skip) ----
#pragma unroll
        for (int i = 0; i < 4; i++) {
            a[i][0] = pk2(b2s[c0], 0.f);
            a[i][1] = pk2(b2s[c0 + 1], 0.f);
            a[i][2] = pk2(b2s[c2], 0.f);
            a[i][3] = pk2(b2s[c2 + 1], 0.f);
        }
#pragma unroll 8
        for (int k = 0; k < 64; k += 4) {
            F4U xq[4];
#pragma unroll
            for (int i = 0; i < 4; i++)
                xq[i].v = *(const float4*)&xy[(r0 + i) * 68 + k];
#pragma unroll
            for (int kk2 = 0; kk2 < 2; kk2++) {
                ulonglong2 wA = *(const ulonglong2*)&W2p[(k / 2 + kk2) * 64 + c0];
                ulonglong2 wB = *(const ulonglong2*)&W2p[(k / 2 + kk2) * 64 + c2];
#pragma unroll
                for (int i = 0; i < 4; i++) {
                    u64 xp = xq[i].u[kk2];
                    a[i][0] = fma2(xp, wA.x, a[i][0]);
                    a[i][1] = fma2(xp, wA.y, a[i][1]);
                    a[i][2] = fma2(xp, wB.x, a[i][2]);
                    a[i][3] = fma2(xp, wB.y, a[i][3]);
                }
            }
        }
#pragma unroll
        for (int i = 0; i < 4; i++) {
            int node = base + r0 + i;
            if (node < n) {
                float2 q0 = unpk(a[i][0]), q1 = unpk(a[i][1]);
                float2 q2 = unpk(a[i][2]), q3 = unpk(a[i][3]);
                float2 vA = make_float2(q0.x + q0.y, q1.x + q1.y);
                float2 vB = make_float2(q2.x + q2.y, q3.x + q3.y);
                if (skip) {
                    float2 sA = *(const float2*)&skip[(size_t)node * 64 + c0];
                    float2 sB = *(const float2*)&skip[(size_t)node * 64 + c2];
                    vA.x += sA.x; vA.y += sA.y;
                    vB.x += sB.x; vB.y += sB.y;
                }
                *(float2*)&out[(size_t)node * 64 + c0] = vA;
                *(float2*)&out[(size_t)node * 64 + c2] = vB;
                if (zero_out) {
                    float2 z = make_float2(0.f, 0.f);
                    *(float2*)&zero_out[(size_t)node * 64 + c0] = z;
                    *(float2*)&zero_out[(size_t)node * 64 + c2] = z;
                }
            }
        }
        __syncthreads();   // xy reads done before next tile overwrites
    }
}

// decode: out[n,2] = relu(h@Wd1+bd1)@Wd2+bd2
__global__ __launch_bounds__(512) void decode_kernel(const float* __restrict__ hin,
                                                     const float* __restrict__ W1,
                                                     const float* __restrict__ b1,
                                                     const float* __restrict__ W2,
                                                     const float* __restrict__ b2,
                                                     float* __restrict__ out, int n) {
    __shared__ __align__(16) float W1s[D * D];
    __shared__ __align__(16) float b1s[D];
    __shared__ __align__(16) float W2s[D * 2];
    __shared__ __align__(16) float b2s[4];
    __shared__ __align__(16) float inb[8][D];
    __shared__ __align__(16) float yb[8][D];
    int t = threadIdx.x;
    for (int i = t; i < D * D; i += 512) W1s[i] = W1[i];
    if (t < D) b1s[t] = b1[t];
    if (t < D * 2) W2s[t] = W2[t];
    if (t < 2) b2s[t] = b2[t];
    __syncthreads();
    int g = t >> 6, j = t & 63;
    for (long base = (long)blockIdx.x * 8; base < n; base += (long)gridDim.x * 8) {
        int node = (int)base + g;
        bool valid = node < n;
        if (valid) inb[g][j] = hin[(size_t)node * D + j];
        __syncthreads();
        if (valid) {
            float acc = b1s[j];
            const float4* h4 = (const float4*)&inb[g][0];
#pragma unroll
            for (int kk = 0; kk < 16; kk++) {
                float4 v = h4[kk];
                int k = kk * 4;
                acc += v.x * W1s[(k + 0) * D + j];
                acc += v.y * W1s[(k + 1) * D + j];
                acc += v.z * W1s[(k + 2) * D + j];
                acc += v.w * W1s[(k + 3) * D + j];
            }
            yb[g][j] = fmaxf(acc, 0.0f);
        }
        __syncthreads();
        if (valid && j < 2) {
            float acc = b2s[j];
#pragma unroll
            for (int k = 0; k < D; k++) acc += yb[g][k] * W2s[k * 2 + j];
            out[(size_t)node * 2 + j] = acc;
        }
        __syncthreads();
    }
}

// ---------------------------------------------------------------------------
static inline int mini(long a, long b) { return (int)(a < b ? a : b); }

static constexpr size_t MLP_SMEM =
    (size_t)(32 * 64 * 8) * 2 + 128 * 4 + 64 * 68 * 4;   // ~49.5 KB

extern "C" void kernel_launch(void* const* d_in, const int* in_sizes, int n_in,
                              void* d_out, int out_size) {
    const float* x   = (const float*)d_in[0];
    const float* We1 = (const float*)d_in[1];
    const float* be1 = (const float*)d_in[2];
    const float* We2 = (const float*)d_in[3];
    const float* be2 = (const float*)d_in[4];
    const float* Wm1 = (const float*)d_in[5];
    const float* bm1 = (const float*)d_in[6];
    const float* Wm2 = (const float*)d_in[7];
    const float* bm2 = (const float*)d_in[8];
    const float* Wn1 = (const float*)d_in[9];
    const float* bn1 = (const float*)d_in[10];
    const float* Wn2 = (const float*)d_in[11];
    const float* bn2 = (const float*)d_in[12];
    const float* Wd1 = (const float*)d_in[13];
    const float* bd1 = (const float*)d_in[14];
    const float* Wd2 = (const float*)d_in[15];
    const float* bd2 = (const float*)d_in[16];
    const int* s_f  = (const int*)d_in[17];
    const int* r_f  = (const int*)d_in[18];
    const int* s_ds = (const int*)d_in[19];
    const int* r_ds = (const int*)d_in[20];
    const int* s_p  = (const int*)d_in[21];
    const int* r_p  = (const int*)d_in[22];
    const int* s_us = (const int*)d_in[23];
    const int* r_us = (const int*)d_in[24];
    const int* uppool   = (const int*)d_in[25];
    const int* downpool = (const int*)d_in[26];

    int N   = in_sizes[0] / 16;
    int NP  = in_sizes[26];
    int E   = in_sizes[17];
    int EDS = in_sizes[19];
    int EP  = in_sizes[21];
    int EUS = in_sizes[23];
    float* out = (float*)d_out;

    float *A, *B, *C, *M, *AG;
    int* IDX;
    cudaGetSymbolAddress((void**)&A, g_A);
    cudaGetSymbolAddress((void**)&B, g_B);
    cudaGetSymbolAddress((void**)&C, g_C);
    cudaGetSymbolAddress((void**)&M, g_M);
    cudaGetSymbolAddress((void**)&AG, g_AG);
    cudaGetSymbolAddress((void**)&IDX, g_IDX);

    static bool attr_done = false;
    if (!attr_done) {
        cudaFuncSetAttribute(mlp2_tiled<16>, cudaFuncAttributeMaxDynamicSharedMemorySize,
                             (int)MLP_SMEM);
        cudaFuncSetAttribute(mlp2_tiled<64>, cudaFuncAttributeMaxDynamicSharedMemorySize,
                             (int)MLP_SMEM);
        cudaFuncSetAttribute(mlp2_tiled<128>, cudaFuncAttributeMaxDynamicSharedMemorySize,
                             (int)MLP_SMEM);
        attr_done = true;
    }

    auto grid_for = [](int n) { return mini(((long)n + 63) / 64, 4096); };

    // one message-passing layer.
    //  nmsg:    rows the message MLP runs over (distinct sender features)
    //  smap:    optional map applied to s inside scatter (msg row = smap[s[e]])
    //  ri0/ri1: node-MLP input row indices (in0 = hin[ri0[i]], in1 = AG[ri1[i]])
    //  zeroN:   if >0, AG must be zeroed explicitly over zeroN rows (receivers
    //           exceed the message-MLP row range); else zeroing is fused.
    auto mp = [&](int l, const float* hin, float* hout, const int* s, const int* r,
                  int Ecnt, int nmsg, const int* smap, const int* ri0, const int* ri1,
                  const float* skip, int nout, int zeroN) {
        if (zeroN > 0)
            zero_kernel<<<(zeroN * 16 + 511) / 512, 512>>>((float4*)AG, zeroN * 16);
        mlp2_tiled<64><<<grid_for(nmsg), 256, MLP_SMEM>>>(
            hin, nullptr, nullptr, nullptr, Wm1 + (size_t)l * D * D, bm1 + (size_t)l * D,
            Wm2 + (size_t)l * D * D, bm2 + (size_t)l * D, nullptr, M,
            zeroN > 0 ? nullptr : AG, nmsg);
        long E16 = (long)Ecnt * 16;
        scatter_kernel<<<mini((E16 + 255) / 256, 8192), 256>>>(M, s, r, smap, AG, E16);
        mlp2_tiled<128><<<grid_for(nout), 256, MLP_SMEM>>>(
            hin, AG, ri0, ri1, Wn1 + (size_t)l * 128 * D, bn1 + (size_t)l * D,
            Wn2 + (size_t)l * D * D, bn2 + (size_t)l * D, skip, hout, nullptr, nout);
    };

    // composite index for mp2 node MLP in0: IDX[i] = uppool[downpool[i]]
    compose_idx_kernel<<<(NP + 255) / 256, 256>>>(uppool, downpool, IDX, NP);

    // encode
    mlp2_tiled<16><<<grid_for(N), 256, MLP_SMEM>>>(
        x, nullptr, nullptr, nullptr, We1, be1, We2, be2, nullptr, A, nullptr, N);
    // two fine MP layers
    mp(0, A, B, s_f, r_f, E, N, nullptr, nullptr, nullptr, nullptr, N, 0);
    mp(1, B, C, s_f, r_f, E, N, nullptr, nullptr, nullptr, nullptr, N, 0);
    // skip = C
    // downsample MP: h_ds = C[uppool] has only NP distinct rows (uppool < NP).
    // msg MLP on C[0:NP); scatter maps s through uppool; node MLP restricted
    // to downpool rows with in0 = C[uppool[downpool[i]]], in1 = AG[downpool[i]].
    mp(2, C, B, s_ds, r_ds, EDS, NP, uppool, IDX, downpool, nullptr, NP, N);
    // bottleneck
    mp(3, B, A, s_p, r_p, EP, NP, nullptr, nullptr, nullptr, nullptr, NP, 0);
    mp(4, A, B, s_p, r_p, EP, NP, nullptr, nullptr, nullptr, nullptr, NP, 0);
    // upsample MP: h_us = B[downpool]; msg MLP on B; scatter maps s through
    // downpool; node MLP in0 = B[downpool[i]], in1 = AG[i].  -> A = g [NP]
    mp(5, B, A, s_us, r_us, EUS, NP, downpool, downpool, nullptr, nullptr, NP, 0);
    // decode MP layer 6: h = A[uppool] (only NP distinct rows). msg MLP on A;
    // scatter maps s through uppool; node MLP in0 = A[uppool[i]], in1 = AG[i].
    mp(6, A, B, s_f, r_f, E, NP, uppool, uppool, nullptr, C, N, N);
    // decode MP layer 7 (plain fine layer)
    mp(7, B, A, s_f, r_f, E, N, nullptr, nullptr, nullptr, C, N, 0);
    // decode head
    decode_kernel<<<mini(((long)N + 7) / 8, 4096), 512>>>(A, Wd1, bd1, Wd2, bd2, out, N);
}

// round 10
// speedup vs baseline: 1.5794x; 1.5794x over previous
#include <cuda_runtime.h>
#include <cstddef>

#define D 64
#define MAXN 100000

typedef unsigned long long u64;

// Scratch buffers (no allocation allowed) -----------------------------------
__device__ float g_A[MAXN * D];
__device__ float g_B[MAXN * D];
__device__ float g_C[MAXN * D];
__device__ float g_M[MAXN * D];   // per-node messages
__device__ float g_AG[MAXN * D];  // aggregation

// ---------------------------------------------------------------------------
// packed f32x2 helpers (sm_103a: fma.rn.f32x2 doubles fp32 FMA throughput)
__device__ __forceinline__ u64 fma2(u64 a, u64 b, u64 c) {
    u64 d;
    asm("fma.rn.f32x2 %0, %1, %2, %3;" : "=l"(d) : "l"(a), "l"(b), "l"(c));
    return d;
}
__device__ __forceinline__ u64 pk2(float lo, float hi) {
    u64 r;
    asm("mov.b64 %0, {%1, %2};" : "=l"(r)
        : "r"(__float_as_uint(lo)), "r"(__float_as_uint(hi)));
    return r;
}
__device__ __forceinline__ float2 unpk(u64 p) {
    unsigned int lo, hi;
    asm("mov.b64 {%0, %1}, %2;" : "=r"(lo), "=r"(hi) : "l"(p));
    return make_float2(__uint_as_float(lo), __uint_as_float(hi));
}
union F4U { float4 v; u64 u[2]; };

// ---------------------------------------------------------------------------
// out[i,:] = in[idx[i],:]  (row width 64)
__global__ __launch_bounds__(512) void gather_kernel(const float* __restrict__ in,
                                                     const int* __restrict__ idx,
                                                     float* __restrict__ out, int n) {
    int i = blockIdx.x * blockDim.x + threadIdx.x;
    if (i < n * 16) {
        int row = i >> 4;
        int c = i & 15;
        ((float4*)out)[i] = ((const float4*)in)[(size_t)idx[row] * 16 + c];
    }
}

// aggr[r[e],:] += msg[s[e],:]   via red.global.add.v4.f32
__global__ __launch_bounds__(256) void scatter_kernel(const float* __restrict__ msg,
                                                      const int* __restrict__ s,
                                                      const int* __restrict__ r,
                                                      float* __restrict__ aggr, long E16) {
    for (long i = (long)blockIdx.x * 256 + threadIdx.x; i < E16;
         i += (long)gridDim.x * 256) {
        int e = (int)(i >> 4);
        int c = (int)(i & 15);
        int se = __ldg(&s[e]);
        int re = __ldg(&r[e]);
        float4 v = __ldg((const float4*)msg + (size_t)se * 16 + c);
        float* dst = aggr + (size_t)re * 64 + c * 4;
        asm volatile("red.global.add.v4.f32 [%0], {%1,%2,%3,%4};"
                     :: "l"(dst), "f"(v.x), "f"(v.y), "f"(v.z), "f"(v.w)
                     : "memory");
    }
}

// ---------------------------------------------------------------------------
// Register-tiled 2-layer MLP, f32x2-FMA, K-paired weights, low-smem (~50KB)
// for 4 blocks/SM.  out[row] = relu(X[row]@W1+b1)@W2+b2 (+skip[row]).
// X rows: [in0 | in1] when IN==128 (processed as two 64-col halves reusing
// one staging buffer), else in0 (row width IN). The X buffer is re-used for
// Y between GEMM1 and GEMM2 (sync-guarded). W1 (or its active half) lives in
// one 32x64-u64 buffer, restaged per half.
// If rowidx != null, X rows are in0/in1[rowidx[row]]; out rows compact.
// If zero_out != null, those rows of zero_out are zeroed (fused zeroing).
// 256 threads; tile = 64 rows x 64 cols; thread tile = 4 rows x 4 cols,
// cols {2tc, 2tc+1, 2tc+32, 2tc+33}; accumulator b64 halves = even/odd k.
// ---------------------------------------------------------------------------
template <int IN>
__global__ __launch_bounds__(256, 4) void mlp2_tiled(const float* __restrict__ in0,
                                                     const float* __restrict__ in1,
                                                     const int* __restrict__ rowidx,
                                                     const float* __restrict__ W1,
                                                     const float* __restrict__ b1,
                                                     const float* __restrict__ W2,
                                                     const float* __restrict__ b2,
                                                     const float* __restrict__ skip,
                                                     float* __restrict__ out,
                                                     float* __restrict__ zero_out, int n) {
    extern __shared__ __align__(16) float sm[];
    u64* Wp  = (u64*)sm;                           // 32*64 u64: W1 (or half)
    u64* W2p = Wp + 32 * 64;                       // 32*64 u64
    float* b1s = (float*)(W2p + 32 * 64);          // 64
    float* b2s = b1s + 64;                         // 64
    float* xy  = b2s + 64;                         // 64*68 floats (X half / Y)

    const int t = threadIdx.x;
    constexpr int XC = (IN < 64) ? IN : 64;        // X cols staged per phase
    constexpr int NH = (IN == 128) ? 2 : 1;        // halves

    // stage W2 pairs + biases once
    for (int i = t; i < 32 * 64; i += 256) {
        int k2 = i >> 6, c = i & 63;
        W2p[i] = pk2(W2[(2 * k2) * 64 + c], W2[(2 * k2 + 1) * 64 + c]);
    }
    if (t < 64) { b1s[t] = b1[t]; b2s[t] = b2[t]; }
    __syncthreads();   // b1s/b2s/W2p visible before ANY use

    const int tc = t & 15;
    const int tr = t >> 4;
    const int c0 = tc * 2, c2 = c0 + 32;
    const int r0 = tr * 4;
    const int tiles = (n + 63) >> 6;

    for (int tile = blockIdx.x; tile < tiles; tile += gridDim.x) {
        const int base = tile * 64;

        u64 a[4][4];
#pragma unroll
        for (int i = 0; i < 4; i++) {
            a[i][0] = pk2(b1s[c0], 0.f);
            a[i][1] = pk2(b1s[c0 + 1], 0.f);
            a[i][2] = pk2(b1s[c2], 0.f);
            a[i][3] = pk2(b1s[c2 + 1], 0.f);
        }

#pragma unroll
        for (int h = 0; h < NH; h++) {
            // stage W1 half (K-paired): whole W1 when IN<=64
            for (int i = t; i < (XC / 2) * 64; i += 256) {
                int k2 = i >> 6, c = i & 63;
                const float* Ws = W1 + h * 64 * 64;
                Wp[i] = pk2(Ws[(2 * k2) * 64 + c], Ws[(2 * k2 + 1) * 64 + c]);
            }
            // stage X columns for this half
            constexpr int C4 = XC / 4;
            for (int i = t; i < 64 * C4; i += 256) {
                int row = i / C4, col = (i % C4) * 4;
                int node = base + row;
                float4 v = make_float4(0.f, 0.f, 0.f, 0.f);
                if (node < n) {
                    int src = rowidx ? rowidx[node] : node;
                    const float* p = (h == 0) ? in0 : in1;
                    v = *(const float4*)&p[(size_t)src * XC + col];
                }
                *(float4*)&xy[row * 68 + col] = v;
            }
            __syncthreads();
            // accumulate over this half's K
#pragma unroll 8
            for (int k = 0; k < XC; k += 4) {
                F4U xq[4];
#pragma unroll
                for (int i = 0; i < 4; i++)
                    xq[i].v = *(const float4*)&xy[(r0 + i) * 68 + k];
#pragma unroll
                for (int kk2 = 0; kk2 < 2; kk2++) {
                    ulonglong2 wA = *(const ulonglong2*)&Wp[(k / 2 + kk2) * 64 + c0];
                    ulonglong2 wB = *(const ulonglong2*)&Wp[(k / 2 + kk2) * 64 + c2];
#pragma unroll
                    for (int i = 0; i < 4; i++) {
                        u64 xp = xq[i].u[kk2];
                        a[i][0] = fma2(xp, wA.x, a[i][0]);
                        a[i][1] = fma2(xp, wA.y, a[i][1]);
                        a[i][2] = fma2(xp, wB.x, a[i][2]);
                        a[i][3] = fma2(xp, wB.y, a[i][3]);
                    }
                }
            }
            __syncthreads();   // all reads of xy/Wp done before overwrite
        }

        // relu + write Y into xy (aliased, safe after sync)
#pragma unroll
        for (int i = 0; i < 4; i++) {
            float2 q0 = unpk(a[i][0]), q1 = unpk(a[i][1]);
            float2 q2 = unpk(a[i][2]), q3 = unpk(a[i][3]);
            float2 vA = make_float2(fmaxf(q0.x + q0.y, 0.f), fmaxf(q1.x + q1.y, 0.f));
            float2 vB = make_float2(fmaxf(q2.x + q2.y, 0.f), fmaxf(q3.x + q3.y, 0.f));
            *(float2*)&xy[(r0 + i) * 68 + c0] = vA;
            *(float2*)&xy[(r0 + i) * 68 + c2] = vB;
        }
        __syncthreads();

        // ---- GEMM2: out = Y @ W2 + b2 (+skip) ----
#pragma unroll
        for (int i = 0; i < 4; i++) {
            a[i][0] = pk2(b2s[c0], 0.f);
            a[i][1] = pk2(b2s[c0 + 1], 0.f);
            a[i][2] = pk2(b2s[c2], 0.f);
            a[i][3] = pk2(b2s[c2 + 1], 0.f);
        }
#pragma unroll 8
        for (int k = 0; k < 64; k += 4) {
            F4U xq[4];
#pragma unroll
            for (int i = 0; i < 4; i++)
                xq[i].v = *(const float4*)&xy[(r0 + i) * 68 + k];
#pragma unroll
            for (int kk2 = 0; kk2 < 2; kk2++) {
                ulonglong2 wA = *(const ulonglong2*)&W2p[(k / 2 + kk2) * 64 + c0];
                ulonglong2 wB = *(const ulonglong2*)&W2p[(k / 2 + kk2) * 64 + c2];
#pragma unroll
                for (int i = 0; i < 4; i++) {
                    u64 xp = xq[i].u[kk2];
                    a[i][0] = fma2(xp, wA.x, a[i][0]);
                    a[i][1] = fma2(xp, wA.y, a[i][1]);
                    a[i][2] = fma2(xp, wB.x, a[i][2]);
                    a[i][3] = fma2(xp, wB.y, a[i][3]);
                }
            }
        }
#pragma unroll
        for (int i = 0; i < 4; i++) {
            int node = base + r0 + i;
            if (node < n) {
                float2 q0 = unpk(a[i][0]), q1 = unpk(a[i][1]);
                float2 q2 = unpk(a[i][2]), q3 = unpk(a[i][3]);
                float2 vA = make_float2(q0.x + q0.y, q1.x + q1.y);
                float2 vB = make_float2(q2.x + q2.y, q3.x + q3.y);
                if (skip) {
                    float2 sA = *(const float2*)&skip[(size_t)node * 64 + c0];
                    float2 sB = *(const float2*)&skip[(size_t)node * 64 + c2];
                    vA.x += sA.x; vA.y += sA.y;
                    vB.x += sB.x; vB.y += sB.y;
                }
                *(float2*)&out[(size_t)node * 64 + c0] = vA;
                *(float2*)&out[(size_t)node * 64 + c2] = vB;
                if (zero_out) {
                    float2 z = make_float2(0.f, 0.f);
                    *(float2*)&zero_out[(size_t)node * 64 + c0] = z;
                    *(float2*)&zero_out[(size_t)node * 64 + c2] = z;
                }
            }
        }
        __syncthreads();   // xy reads done before next tile overwrites
    }
}

// ---------------------------------------------------------------------------
// Tiled decode: out[n,2] = relu(h@Wd1+bd1)@Wd2+bd2
// GEMM1 identical structure to mlp2_tiled (IN=64); GEMM2 is 64->2 done by
// 128 threads (row = t/2, col = t&1) reading Y from shared.
// ---------------------------------------------------------------------------
__global__ __launch_bounds__(256, 4) void decode_tiled(const float* __restrict__ hin,
                                                       const float* __restrict__ W1,
                                                       const float* __restrict__ b1,
                                                       const float* __restrict__ W2,
                                                       const float* __restrict__ b2,
                                                       float* __restrict__ out, int n) {
    extern __shared__ __align__(16) float sm[];
    u64* Wp  = (u64*)sm;                           // 32*64 u64: W1 pairs
    float* b1s = (float*)(Wp + 32 * 64);           // 64
    float* W2s = b1s + 64;                         // 128 (64x2)
    float* b2s = W2s + 128;                        // 2 (+pad)
    float* xy  = b2s + 4;                          // 64*68 floats (X / Y)

    const int t = threadIdx.x;
    for (int i = t; i < 32 * 64; i += 256) {
        int k2 = i >> 6, c = i & 63;
        Wp[i] = pk2(W1[(2 * k2) * 64 + c], W1[(2 * k2 + 1) * 64 + c]);
    }
    if (t < 64) b1s[t] = b1[t];
    if (t < 128) W2s[t] = W2[t];
    if (t < 2) b2s[t] = b2[t];
    __syncthreads();

    const int tc = t & 15;
    const int tr = t >> 4;
    const int c0 = tc * 2, c2 = c0 + 32;
    const int r0 = tr * 4;
    const int tiles = (n + 63) >> 6;

    for (int tile = blockIdx.x; tile < tiles; tile += gridDim.x) {
        const int base = tile * 64;
        // stage X
        for (int i = t; i < 64 * 16; i += 256) {
            int row = i >> 4, col = (i & 15) * 4;
            int node = base + row;
            float4 v = make_float4(0.f, 0.f, 0.f, 0.f);
            if (node < n) v = *(const float4*)&hin[(size_t)node * 64 + col];
            *(float4*)&xy[row * 68 + col] = v;
        }
        __syncthreads();

        // GEMM1
        u64 a[4][4];
#pragma unroll
        for (int i = 0; i < 4; i++) {
            a[i][0] = pk2(b1s[c0], 0.f);
            a[i][1] = pk2(b1s[c0 + 1], 0.f);
            a[i][2] = pk2(b1s[c2], 0.f);
            a[i][3] = pk2(b1s[c2 + 1], 0.f);
        }
#pragma unroll 8
        for (int k = 0; k < 64; k += 4) {
            F4U xq[4];
#pragma unroll
            for (int i = 0; i < 4; i++)
                xq[i].v = *(const float4*)&xy[(r0 + i) * 68 + k];
#pragma unroll
            for (int kk2 = 0; kk2 < 2; kk2++) {
                ulonglong2 wA = *(const ulonglong2*)&Wp[(k / 2 + kk2) * 64 + c0];
                ulonglong2 wB = *(const ulonglong2*)&Wp[(k / 2 + kk2) * 64 + c2];
#pragma unroll
                for (int i = 0; i < 4; i++) {
                    u64 xp = xq[i].u[kk2];
                    a[i][0] = fma2(xp, wA.x, a[i][0]);
                    a[i][1] = fma2(xp, wA.y, a[i][1]);
                    a[i][2] = fma2(xp, wB.x, a[i][2]);
                    a[i][3] = fma2(xp, wB.y, a[i][3]);
                }
            }
        }
        __syncthreads();   // X reads done before Y overwrite
#pragma unroll
        for (int i = 0; i < 4; i++) {
            float2 q0 = unpk(a[i][0]), q1 = unpk(a[i][1]);
            float2 q2 = unpk(a[i][2]), q3 = unpk(a[i][3]);
            float2 vA = make_float2(fmaxf(q0.x + q0.y, 0.f), fmaxf(q1.x + q1.y, 0.f));
            float2 vB = make_float2(fmaxf(q2.x + q2.y, 0.f), fmaxf(q3.x + q3.y, 0.f));
            *(float2*)&xy[(r0 + i) * 68 + c0] = vA;
            *(float2*)&xy[(r0 + i) * 68 + c2] = vB;
        }
        __syncthreads();

        // GEMM2: 64 -> 2
        if (t < 128) {
            int row = t >> 1, col = t & 1;
            int node = base + row;
            if (node < n) {
                float acc = b2s[col];
                const float* yr = &xy[row * 68];
#pragma unroll 16
                for (int k = 0; k < 64; k++) acc += yr[k] * W2s[k * 2 + col];
                out[(size_t)node * 2 + col] = acc;
            }
        }
        __syncthreads();
    }
}

// ---------------------------------------------------------------------------
static inline int mini(long a, long b) { return (int)(a < b ? a : b); }

static constexpr size_t MLP_SMEM =
    (size_t)(32 * 64 * 8) * 2 + 128 * 4 + 64 * 68 * 4;   // ~49.5 KB
static constexpr size_t DEC_SMEM =
    (size_t)(32 * 64 * 8) + (64 + 128 + 4) * 4 + 64 * 68 * 4;  // ~34.5 KB

extern "C" void kernel_launch(void* const* d_in, const int* in_sizes, int n_in,
                              void* d_out, int out_size) {
    const float* x   = (const float*)d_in[0];
    const float* We1 = (const float*)d_in[1];
    const float* be1 = (const float*)d_in[2];
    const float* We2 = (const float*)d_in[3];
    const float* be2 = (const float*)d_in[4];
    const float* Wm1 = (const float*)d_in[5];
    const float* bm1 = (const float*)d_in[6];
    const float* Wm2 = (const float*)d_in[7];
    const float* bm2 = (const float*)d_in[8];
    const float* Wn1 = (const float*)d_in[9];
    const float* bn1 = (const float*)d_in[10];
    const float* Wn2 = (const float*)d_in[11];
    const float* bn2 = (const float*)d_in[12];
    const float* Wd1 = (const float*)d_in[13];
    const float* bd1 = (const float*)d_in[14];
    const float* Wd2 = (const float*)d_in[15];
    const float* bd2 = (const float*)d_in[16];
    const int* s_f  = (const int*)d_in[17];
    const int* r_f  = (const int*)d_in[18];
    const int* s_ds = (const int*)d_in[19];
    const int* r_ds = (const int*)d_in[20];
    const int* s_p  = (const int*)d_in[21];
    const int* r_p  = (const int*)d_in[22];
    const int* s_us = (const int*)d_in[23];
    const int* r_us = (const int*)d_in[24];
    const int* uppool   = (const int*)d_in[25];
    const int* downpool = (const int*)d_in[26];

    int N   = in_sizes[0] / 16;
    int NP  = in_sizes[26];
    int E   = in_sizes[17];
    int EDS = in_sizes[19];
    int EP  = in_sizes[21];
    int EUS = in_sizes[23];
    float* out = (float*)d_out;

    float *A, *B, *C, *M, *AG;
    cudaGetSymbolAddress((void**)&A, g_A);
    cudaGetSymbolAddress((void**)&B, g_B);
    cudaGetSymbolAddress((void**)&C, g_C);
    cudaGetSymbolAddress((void**)&M, g_M);
    cudaGetSymbolAddress((void**)&AG, g_AG);

    static bool attr_done = false;
    if (!attr_done) {
        cudaFuncSetAttribute(mlp2_tiled<16>, cudaFuncAttributeMaxDynamicSharedMemorySize,
                             (int)MLP_SMEM);
        cudaFuncSetAttribute(mlp2_tiled<64>, cudaFuncAttributeMaxDynamicSharedMemorySize,
                             (int)MLP_SMEM);
        cudaFuncSetAttribute(mlp2_tiled<128>, cudaFuncAttributeMaxDynamicSharedMemorySize,
                             (int)MLP_SMEM);
        cudaFuncSetAttribute(decode_tiled, cudaFuncAttributeMaxDynamicSharedMemorySize,
                             (int)DEC_SMEM);
        attr_done = true;
    }

    auto grid_for = [](int n) { return mini(((long)n + 63) / 64, 4096); };

    // one message-passing layer; node MLP optionally restricted to sel rows.
    // AG zeroing is fused into the message-MLP epilogue.
    auto mp = [&](int l, const float* hin, float* hout, const int* s, const int* r,
                  int Ecnt, int n, const float* skip, const int* sel, int nout) {
        mlp2_tiled<64><<<grid_for(n), 256, MLP_SMEM>>>(
            hin, nullptr, nullptr, Wm1 + (size_t)l * D * D, bm1 + (size_t)l * D,
            Wm2 + (size_t)l * D * D, bm2 + (size_t)l * D, nullptr, M, AG, n);
        long E16 = (long)Ecnt * 16;
        scatter_kernel<<<mini((E16 + 255) / 256, 8192), 256>>>(M, s, r, AG, E16);
        mlp2_tiled<128><<<grid_for(nout), 256, MLP_SMEM>>>(
            hin, AG, sel, Wn1 + (size_t)l * 128 * D, bn1 + (size_t)l * D,
            Wn2 + (size_t)l * D * D, bn2 + (size_t)l * D, skip, hout, nullptr, nout);
    };

    // encode
    mlp2_tiled<16><<<grid_for(N), 256, MLP_SMEM>>>(
        x, nullptr, nullptr, We1, be1, We2, be2, nullptr, A, nullptr, N);
    // two fine MP layers
    mp(0, A, B, s_f, r_f, E, N, nullptr, nullptr, N);
    mp(1, B, C, s_f, r_f, E, N, nullptr, nullptr, N);
    // skip = C
    // downsample: gather h[uppool], MP on ds graph, node MLP only on downpool rows
    gather_kernel<<<(N * 16 + 511) / 512, 512>>>(C, uppool, A, N);
    mp(2, A, B, s_ds, r_ds, EDS, N, nullptr, downpool, NP);   // B = hp [NP]
    // bottleneck
    mp(3, B, A, s_p, r_p, EP, NP, nullptr, nullptr, NP);
    mp(4, A, B, s_p, r_p, EP, NP, nullptr, nullptr, NP);
    // upsample path: gather by downpool, MP on upsampling graph
    gather_kernel<<<(NP * 16 + 511) / 512, 512>>>(B, downpool, A, NP);
    mp(5, A, B, s_us, r_us, EUS, NP, nullptr, nullptr, NP);
    // scatter back to fine level via uppool gather
    gather_kernel<<<(N * 16 + 511) / 512, 512>>>(B, uppool, A, N);
    // decode MP layers with skip connections
    mp(6, A, B, s_f, r_f, E, N, C, nullptr, N);
    mp(7, B, A, s_f, r_f, E, N, C, nullptr, N);
    // decode head (tiled)
    decode_tiled<<<grid_for(N), 256, DEC_SMEM>>>(A, Wd1, bd1, Wd2, bd2, out, N);
}

// round 12
// speedup vs baseline: 1.6243x; 1.0284x over previous
#include <cuda_runtime.h>
#include <cstddef>

#define D 64
#define MAXN 100000

typedef unsigned long long u64;

// Scratch buffers (no allocation allowed) -----------------------------------
__device__ float g_A[MAXN * D];
__device__ float g_B[MAXN * D];
__device__ float g_C[MAXN * D];
__device__ float g_M[MAXN * D];   // per-node messages
__device__ float g_AG[MAXN * D];  // aggregation

// ---------------------------------------------------------------------------
// packed f32x2 helpers (sm_103a: fma.rn.f32x2 doubles fp32 FMA throughput)
__device__ __forceinline__ u64 fma2(u64 a, u64 b, u64 c) {
    u64 d;
    asm("fma.rn.f32x2 %0, %1, %2, %3;" : "=l"(d) : "l"(a), "l"(b), "l"(c));
    return d;
}
__device__ __forceinline__ u64 pk2(float lo, float hi) {
    u64 r;
    asm("mov.b64 %0, {%1, %2};" : "=l"(r)
        : "r"(__float_as_uint(lo)), "r"(__float_as_uint(hi)));
    return r;
}
__device__ __forceinline__ float2 unpk(u64 p) {
    unsigned int lo, hi;
    asm("mov.b64 {%0, %1}, %2;" : "=r"(lo), "=r"(hi) : "l"(p));
    return make_float2(__uint_as_float(lo), __uint_as_float(hi));
}
union F4U { float4 v; u64 u[2]; };

// ---------------------------------------------------------------------------
__global__ __launch_bounds__(512) void zero_kernel(float4* __restrict__ p, int n4) {
    int i = blockIdx.x * blockDim.x + threadIdx.x;
    if (i < n4) p[i] = make_float4(0.f, 0.f, 0.f, 0.f);
}

// out[i,:] = in[idx[i],:]  (row width 64)
__global__ __launch_bounds__(512) void gather_kernel(const float* __restrict__ in,
                                                     const int* __restrict__ idx,
                                                     float* __restrict__ out, int n) {
    int i = blockIdx.x * blockDim.x + threadIdx.x;
    if (i < n * 16) {
        int row = i >> 4;
        int c = i & 15;
        ((float4*)out)[i] = ((const float4*)in)[(size_t)idx[row] * 16 + c];
    }
}

// aggr[r[e],:] += msg[s[e],:]   via red.global.add.v4.f32  (UNCHANGED from R10)
__global__ __launch_bounds__(256) void scatter_kernel(const float* __restrict__ msg,
                                                      const int* __restrict__ s,
                                                      const int* __restrict__ r,
                                                      float* __restrict__ aggr, long E16) {
    for (long i = (long)blockIdx.x * 256 + threadIdx.x; i < E16;
         i += (long)gridDim.x * 256) {
        int e = (int)(i >> 4);
        int c = (int)(i & 15);
        int se = __ldg(&s[e]);
        int re = __ldg(&r[e]);
        float4 v = __ldg((const float4*)msg + (size_t)se * 16 + c);
        float* dst = aggr + (size_t)re * 64 + c * 4;
        asm volatile("red.global.add.v4.f32 [%0], {%1,%2,%3,%4};"
                     :: "l"(dst), "f"(v.x), "f"(v.y), "f"(v.z), "f"(v.w)
                     : "memory");
    }
}

// ---------------------------------------------------------------------------
// Register-tiled 2-layer MLP (optionally fused with a second 2-layer MLP that
// consumes this kernel's output rows — the next layer's message MLP).
//   out[row] = relu(X[row]@W1+b1)@W2+b2 (+skip[row])
//   if Mout:  Mout[row] = relu(out_row@Wm1+bm1)@Wm2+bm2, and zero_out rows
//             are zeroed in the fused epilogue (else in the first epilogue).
// X rows: [in0 | in1] when IN==128 (two 64-col halves through one staging
// buffer), else in0 (row width IN). in0 rows via rowidx0 (if set), in1 rows
// via rowidx1 (if set). out/skip/Mout/zero_out rows are compact.
// NOTE: fused path clobbers W2p/b1s/b2s — requires grid == #tiles (true here:
// tiles <= 1563 < launch cap).
// 256 threads; tile = 64 rows x 64 cols; thread tile = 4 rows x 4 cols,
// cols {2tc, 2tc+1, 2tc+32, 2tc+33}; accumulator b64 halves = even/odd k.
// ---------------------------------------------------------------------------
template <int IN>
__global__ __launch_bounds__(256, 4) void mlp2_tiled(
    const float* __restrict__ in0, const float* __restrict__ in1,
    const int* __restrict__ rowidx0, const int* __restrict__ rowidx1,
    const float* __restrict__ W1, const float* __restrict__ b1,
    const float* __restrict__ W2, const float* __restrict__ b2,
    const float* __restrict__ skip, float* __restrict__ out,
    float* __restrict__ zero_out,
    const float* __restrict__ Wm1, const float* __restrict__ bm1,
    const float* __restrict__ Wm2, const float* __restrict__ bm2,
    float* __restrict__ Mout, int n) {
    extern __shared__ __align__(16) float sm[];
    u64* Wp  = (u64*)sm;                           // 32*64 u64
    u64* W2p = Wp + 32 * 64;                       // 32*64 u64
    float* b1s = (float*)(W2p + 32 * 64);          // 64
    float* b2s = b1s + 64;                         // 64
    float* xy  = b2s + 64;                         // 64*68 floats

    const int t = threadIdx.x;
    constexpr int XC = (IN < 64) ? IN : 64;
    constexpr int NH = (IN == 128) ? 2 : 1;

    for (int i = t; i < 32 * 64; i += 256) {
        int k2 = i >> 6, c = i & 63;
        W2p[i] = pk2(W2[(2 * k2) * 64 + c], W2[(2 * k2 + 1) * 64 + c]);
    }
    if (t < 64) { b1s[t] = b1[t]; b2s[t] = b2[t]; }
    __syncthreads();

    const int tc = t & 15;
    const int tr = t >> 4;
    const int c0 = tc * 2, c2 = c0 + 32;
    const int r0 = tr * 4;
    const int tiles = (n + 63) >> 6;

    for (int tile = blockIdx.x; tile < tiles; tile += gridDim.x) {
        const int base = tile * 64;

        u64 a[4][4];
#pragma unroll
        for (int i = 0; i < 4; i++) {
            a[i][0] = pk2(b1s[c0], 0.f);
            a[i][1] = pk2(b1s[c0 + 1], 0.f);
            a[i][2] = pk2(b1s[c2], 0.f);
            a[i][3] = pk2(b1s[c2 + 1], 0.f);
        }

#pragma unroll
        for (int h = 0; h < NH; h++) {
            for (int i = t; i < (XC / 2) * 64; i += 256) {
                int k2 = i >> 6, c = i & 63;
                const float* Ws = W1 + h * 64 * 64;
                Wp[i] = pk2(Ws[(2 * k2) * 64 + c], Ws[(2 * k2 + 1) * 64 + c]);
            }
            constexpr int C4 = XC / 4;
            for (int i = t; i < 64 * C4; i += 256) {
                int row = i / C4, col = (i % C4) * 4;
                int node = base + row;
                float4 v = make_float4(0.f, 0.f, 0.f, 0.f);
                if (node < n) {
                    const int* ridx = (h == 0) ? rowidx0 : rowidx1;
                    int src = ridx ? ridx[node] : node;
                    const float* p = (h == 0) ? in0 : in1;
                    v = *(const float4*)&p[(size_t)src * XC + col];
                }
                *(float4*)&xy[row * 68 + col] = v;
            }
            __syncthreads();
#pragma unroll 8
            for (int k = 0; k < XC; k += 4) {
                F4U xq[4];
#pragma unroll
                for (int i = 0; i < 4; i++)
                    xq[i].v = *(const float4*)&xy[(r0 + i) * 68 + k];
#pragma unroll
                for (int kk2 = 0; kk2 < 2; kk2++) {
                    ulonglong2 wA = *(const ulonglong2*)&Wp[(k / 2 + kk2) * 64 + c0];
                    ulonglong2 wB = *(const ulonglong2*)&Wp[(k / 2 + kk2) * 64 + c2];
#pragma unroll
                    for (int i = 0; i < 4; i++) {
                        u64 xp = xq[i].u[kk2];
                        a[i][0] = fma2(xp, wA.x, a[i][0]);
                        a[i][1] = fma2(xp, wA.y, a[i][1]);
                        a[i][2] = fma2(xp, wB.x, a[i][2]);
                        a[i][3] = fma2(xp, wB.y, a[i][3]);
                    }
                }
            }
            __syncthreads();
        }

        // relu + write Y into xy
#pragma unroll
        for (int i = 0; i < 4; i++) {
            float2 q0 = unpk(a[i][0]), q1 = unpk(a[i][1]);
            float2 q2 = unpk(a[i][2]), q3 = unpk(a[i][3]);
            float2 vA = make_float2(fmaxf(q0.x + q0.y, 0.f), fmaxf(q1.x + q1.y, 0.f));
            float2 vB = make_float2(fmaxf(q2.x + q2.y, 0.f), fmaxf(q3.x + q3.y, 0.f));
            *(float2*)&xy[(r0 + i) * 68 + c0] = vA;
            *(float2*)&xy[(r0 + i) * 68 + c2] = vB;
        }
        __syncthreads();

        // ---- GEMM2: h = Y @ W2 + b2 (+skip) ----
#pragma unroll
        for (int i = 0; i < 4; i++) {
            a[i][0] = pk2(b2s[c0], 0.f);
            a[i][1] = pk2(b2s[c0 + 1], 0.f);
            a[i][2] = pk2(b2s[c2], 0.f);
            a[i][3] = pk2(b2s[c2 + 1], 0.f);
        }
#pragma unroll 8
        for (int k = 0; k < 64; k += 4) {
            F4U xq[4];
#pragma unroll
            for (int i = 0; i < 4; i++)
                xq[i].v = *(const float4*)&xy[(r0 + i) * 68 + k];
#pragma unroll
            for (int kk2 = 0; kk2 < 2; kk2++) {
                ulonglong2 wA = *(const ulonglong2*)&W2p[(k / 2 + kk2) * 64 + c0];
                ulonglong2 wB = *(const ulonglong2*)&W2p[(k / 2 + kk2) * 64 + c2];
#pragma unroll
                for (int i = 0; i < 4; i++) {
                    u64 xp = xq[i].u[kk2];
                    a[i][0] = fma2(xp, wA.x, a[i][0]);
                    a[i][1] = fma2(xp, wA.y, a[i][1]);
                    a[i][2] = fma2(xp, wB.x, a[i][2]);
                    a[i][3] = fma2(xp, wB.y, a[i][3]);
                }
            }
        }
        float2 hA[4], hB[4];
#pragma unroll
        for (int i = 0; i < 4; i++) {
            float2 q0 = unpk(a[i][0]), q1 = unpk(a[i][1]);
            float2 q2 = unpk(a[i][2]), q3 = unpk(a[i][3]);
            hA[i] = make_float2(q0.x + q0.y, q1.x + q1.y);
            hB[i] = make_float2(q2.x + q2.y, q3.x + q3.y);
            int node = base + r0 + i;
            if (node < n) {
                if (skip) {
                    float2 sA = *(const float2*)&skip[(size_t)node * 64 + c0];
                    float2 sB = *(const float2*)&skip[(size_t)node * 64 + c2];
                    hA[i].x += sA.x; hA[i].y += sA.y;
                    hB[i].x += sB.x; hB[i].y += sB.y;
                }
                *(float2*)&out[(size_t)node * 64 + c0] = hA[i];
                *(float2*)&out[(size_t)node * 64 + c2] = hB[i];
                if (!Mout && zero_out) {
                    float2 z = make_float2(0.f, 0.f);
                    *(float2*)&zero_out[(size_t)node * 64 + c0] = z;
                    *(float2*)&zero_out[(size_t)node * 64 + c2] = z;
                }
            }
        }

        // ================= fused next-layer message MLP =================
        if (Mout) {
            __syncthreads();   // all Y reads of xy done
            // write h into xy (zeros for invalid rows)
#pragma unroll
            for (int i = 0; i < 4; i++) {
                bool valid = (base + r0 + i) < n;
                float2 vA = valid ? hA[i] : make_float2(0.f, 0.f);
                float2 vB = valid ? hB[i] : make_float2(0.f, 0.f);
                *(float2*)&xy[(r0 + i) * 68 + c0] = vA;
                *(float2*)&xy[(r0 + i) * 68 + c2] = vB;
            }
            // stage Wm1->Wp, Wm2->W2p, bm1->b1s, bm2->b2s (single-tile blocks)
            for (int i = t; i < 32 * 64; i += 256) {
                int k2 = i >> 6, c = i & 63;
                Wp[i]  = pk2(Wm1[(2 * k2) * 64 + c], Wm1[(2 * k2 + 1) * 64 + c]);
                W2p[i] = pk2(Wm2[(2 * k2) * 64 + c], Wm2[(2 * k2 + 1) * 64 + c]);
            }
            if (t < 64) { b1s[t] = bm1[t]; b2s[t] = bm2[t]; }
            __syncthreads();

            // GEMM3: Y2 = relu(h @ Wm1 + bm1)
#pragma unroll
            for (int i = 0; i < 4; i++) {
                a[i][0] = pk2(b1s[c0], 0.f);
                a[i][1] = pk2(b1s[c0 + 1], 0.f);
                a[i][2] = pk2(b1s[c2], 0.f);
                a[i][3] = pk2(b1s[c2 + 1], 0.f);
            }
#pragma unroll 8
            for (int k = 0; k < 64; k += 4) {
                F4U xq[4];
#pragma unroll
                for (int i = 0; i < 4; i++)
                    xq[i].v = *(const float4*)&xy[(r0 + i) * 68 + k];
#pragma unroll
                for (int kk2 = 0; kk2 < 2; kk2++) {
                    ulonglong2 wA = *(const ulonglong2*)&Wp[(k / 2 + kk2) * 64 + c0];
                    ulonglong2 wB = *(const ulonglong2*)&Wp[(k / 2 + kk2) * 64 + c2];
#pragma unroll
                    for (int i = 0; i < 4; i++) {
                        u64 xp = xq[i].u[kk2];
                        a[i][0] = fma2(xp, wA.x, a[i][0]);
                        a[i][1] = fma2(xp, wA.y, a[i][1]);
                        a[i][2] = fma2(xp, wB.x, a[i][2]);
                        a[i][3] = fma2(xp, wB.y, a[i][3]);
                    }
                }
            }
            __syncthreads();
#pragma unroll
            for (int i = 0; i < 4; i++) {
                float2 q0 = unpk(a[i][0]), q1 = unpk(a[i][1]);
                float2 q2 = unpk(a[i][2]), q3 = unpk(a[i][3]);
                float2 vA = make_float2(fmaxf(q0.x + q0.y, 0.f), fmaxf(q1.x + q1.y, 0.f));
                float2 vB = make_float2(fmaxf(q2.x + q2.y, 0.f), fmaxf(q3.x + q3.y, 0.f));
                *(float2*)&xy[(r0 + i) * 68 + c0] = vA;
                *(float2*)&xy[(r0 + i) * 68 + c2] = vB;
            }
            __syncthreads();

            // GEMM4: M = Y2 @ Wm2 + bm2; write Mout + zero AG rows
#pragma unroll
            for (int i = 0; i < 4; i++) {
                a[i][0] = pk2(b2s[c0], 0.f);
                a[i][1] = pk2(b2s[c0 + 1], 0.f);
                a[i][2] = pk2(b2s[c2], 0.f);
                a[i][3] = pk2(b2s[c2 + 1], 0.f);
            }
#pragma unroll 8
            for (int k = 0; k < 64; k += 4) {
                F4U xq[4];
#pragma unroll
                for (int i = 0; i < 4; i++)
                    xq[i].v = *(const float4*)&xy[(r0 + i) * 68 + k];
#pragma unroll
                for (int kk2 = 0; kk2 < 2; kk2++) {
                    ulonglong2 wA = *(const ulonglong2*)&W2p[(k / 2 + kk2) * 64 + c0];
                    ulonglong2 wB = *(const ulonglong2*)&W2p[(k / 2 + kk2) * 64 + c2];
#pragma unroll
                    for (int i = 0; i < 4; i++) {
                        u64 xp = xq[i].u[kk2];
                        a[i][0] = fma2(xp, wA.x, a[i][0]);
                        a[i][1] = fma2(xp, wA.y, a[i][1]);
                        a[i][2] = fma2(xp, wB.x, a[i][2]);
                        a[i][3] = fma2(xp, wB.y, a[i][3]);
                    }
                }
            }
#pragma unroll
            for (int i = 0; i < 4; i++) {
                int node = base + r0 + i;
                if (node < n) {
                    float2 q0 = unpk(a[i][0]), q1 = unpk(a[i][1]);
                    float2 q2 = unpk(a[i][2]), q3 = unpk(a[i][3]);
                    float2 vA = make_float2(q0.x + q0.y, q1.x + q1.y);
                    float2 vB = make_float2(q2.x + q2.y, q3.x + q3.y);
                    *(float2*)&Mout[(size_t)node * 64 + c0] = vA;
                    *(float2*)&Mout[(size_t)node * 64 + c2] = vB;
                    if (zero_out) {
                        float2 z = make_float2(0.f, 0.f);
                        *(float2*)&zero_out[(size_t)node * 64 + c0] = z;
                        *(float2*)&zero_out[(size_t)node * 64 + c2] = z;
                    }
                }
            }
        }
        __syncthreads();
    }
}

// ---------------------------------------------------------------------------
// Tiled decode: out[n,2] = relu(h@Wd1+bd1)@Wd2+bd2
// ---------------------------------------------------------------------------
__global__ __launch_bounds__(256, 4) void decode_tiled(const float* __restrict__ hin,
                                                       const float* __restrict__ W1,
                                                       const float* __restrict__ b1,
                                                       const float* __restrict__ W2,
                                                       const float* __restrict__ b2,
                                                       float* __restrict__ out, int n) {
    extern __shared__ __align__(16) float sm[];
    u64* Wp  = (u64*)sm;                           // 32*64 u64
    float* b1s = (float*)(Wp + 32 * 64);           // 64
    float* W2s = b1s + 64;                         // 128
    float* b2s = W2s + 128;                        // 2 (+pad)
    float* xy  = b2s + 4;                          // 64*68

    const int t = threadIdx.x;
    for (int i = t; i < 32 * 64; i += 256) {
        int k2 = i >> 6, c = i & 63;
        Wp[i] = pk2(W1[(2 * k2) * 64 + c], W1[(2 * k2 + 1) * 64 + c]);
    }
    if (t < 64) b1s[t] = b1[t];
    if (t < 128) W2s[t] = W2[t];
    if (t < 2) b2s[t] = b2[t];
    __syncthreads();

    const int tc = t & 15;
    const int tr = t >> 4;
    const int c0 = tc * 2, c2 = c0 + 32;
    const int r0 = tr * 4;
    const int tiles = (n + 63) >> 6;

    for (int tile = blockIdx.x; tile < tiles; tile += gridDim.x) {
        const int base = tile * 64;
        for (int i = t; i < 64 * 16; i += 256) {
            int row = i >> 4, col = (i & 15) * 4;
            int node = base + row;
            float4 v = make_float4(0.f, 0.f, 0.f, 0.f);
            if (node < n) v = *(const float4*)&hin[(size_t)node * 64 + col];
            *(float4*)&xy[row * 68 + col] = v;
        }
        __syncthreads();

        u64 a[4][4];
#pragma unroll
        for (int i = 0; i < 4; i++) {
            a[i][0] = pk2(b1s[c0], 0.f);
            a[i][1] = pk2(b1s[c0 + 1], 0.f);
            a[i][2] = pk2(b1s[c2], 0.f);
            a[i][3] = pk2(b1s[c2 + 1], 0.f);
        }
#pragma unroll 8
        for (int k = 0; k < 64; k += 4) {
            F4U xq[4];
#pragma unroll
            for (int i = 0; i < 4; i++)
                xq[i].v = *(const float4*)&xy[(r0 + i) * 68 + k];
#pragma unroll
            for (int kk2 = 0; kk2 < 2; kk2++) {
                ulonglong2 wA = *(const ulonglong2*)&Wp[(k / 2 + kk2) * 64 + c0];
                ulonglong2 wB = *(const ulonglong2*)&Wp[(k / 2 + kk2) * 64 + c2];
#pragma unroll
                for (int i = 0; i < 4; i++) {
                    u64 xp = xq[i].u[kk2];
                    a[i][0] = fma2(xp, wA.x, a[i][0]);
                    a[i][1] = fma2(xp, wA.y, a[i][1]);
                    a[i][2] = fma2(xp, wB.x, a[i][2]);
                    a[i][3] = fma2(xp, wB.y, a[i][3]);
                }
            }
        }
        __syncthreads();
#pragma unroll
        for (int i = 0; i < 4; i++) {
            float2 q0 = unpk(a[i][0]), q1 = unpk(a[i][1]);
            float2 q2 = unpk(a[i][2]), q3 = unpk(a[i][3]);
            float2 vA = make_float2(fmaxf(q0.x + q0.y, 0.f), fmaxf(q1.x + q1.y, 0.f));
            float2 vB = make_float2(fmaxf(q2.x + q2.y, 0.f), fmaxf(q3.x + q3.y, 0.f));
            *(float2*)&xy[(r0 + i) * 68 + c0] = vA;
            *(float2*)&xy[(r0 + i) * 68 + c2] = vB;
        }
        __syncthreads();

        if (t < 128) {
            int row = t >> 1, col = t & 1;
            int node = base + row;
            if (node < n) {
                float acc = b2s[col];
                const float* yr = &xy[row * 68];
#pragma unroll 16
                for (int k = 0; k < 64; k++) acc += yr[k] * W2s[k * 2 + col];
                out[(size_t)node * 2 + col] = acc;
            }
        }
        __syncthreads();
    }
}

// ---------------------------------------------------------------------------
static inline int mini(long a, long b) { return (int)(a < b ? a : b); }

static constexpr size_t MLP_SMEM =
    (size_t)(32 * 64 * 8) * 2 + 128 * 4 + 64 * 68 * 4;   // ~49.5 KB
static constexpr size_t DEC_SMEM =
    (size_t)(32 * 64 * 8) + (64 + 128 + 4) * 4 + 64 * 68 * 4;  // ~34.5 KB

extern "C" void kernel_launch(void* const* d_in, const int* in_sizes, int n_in,
                              void* d_out, int out_size) {
    const float* x   = (const float*)d_in[0];
    const float* We1 = (const float*)d_in[1];
    const float* be1 = (const float*)d_in[2];
    const float* We2 = (const float*)d_in[3];
    const float* be2 = (const float*)d_in[4];
    const float* Wm1 = (const float*)d_in[5];
    const float* bm1 = (const float*)d_in[6];
    const float* Wm2 = (const float*)d_in[7];
    const float* bm2 = (const float*)d_in[8];
    const float* Wn1 = (const float*)d_in[9];
    const float* bn1 = (const float*)d_in[10];
    const float* Wn2 = (const float*)d_in[11];
    const float* bn2 = (const float*)d_in[12];
    const float* Wd1 = (const float*)d_in[13];
    const float* bd1 = (const float*)d_in[14];
    const float* Wd2 = (const float*)d_in[15];
    const float* bd2 = (const float*)d_in[16];
    const int* s_f  = (const int*)d_in[17];
    const int* r_f  = (const int*)d_in[18];
    const int* s_ds = (const int*)d_in[19];
    const int* r_ds = (const int*)d_in[20];
    const int* s_p  = (const int*)d_in[21];
    const int* r_p  = (const int*)d_in[22];
    const int* s_us = (const int*)d_in[23];
    const int* r_us = (const int*)d_in[24];
    const int* uppool   = (const int*)d_in[25];
    const int* downpool = (const int*)d_in[26];

    int N   = in_sizes[0] / 16;
    int NP  = in_sizes[26];
    int E   = in_sizes[17];
    int EDS = in_sizes[19];
    int EP  = in_sizes[21];
    int EUS = in_sizes[23];
    float* out = (float*)d_out;

    float *A, *B, *C, *M, *AG;
    cudaGetSymbolAddress((void**)&A, g_A);
    cudaGetSymbolAddress((void**)&B, g_B);
    cudaGetSymbolAddress((void**)&C, g_C);
    cudaGetSymbolAddress((void**)&M, g_M);
    cudaGetSymbolAddress((void**)&AG, g_AG);

    static bool attr_done = false;
    if (!attr_done) {
        cudaFuncSetAttribute(mlp2_tiled<16>, cudaFuncAttributeMaxDynamicSharedMemorySize,
                             (int)MLP_SMEM);
        cudaFuncSetAttribute(mlp2_tiled<64>, cudaFuncAttributeMaxDynamicSharedMemorySize,
                             (int)MLP_SMEM);
        cudaFuncSetAttribute(mlp2_tiled<128>, cudaFuncAttributeMaxDynamicSharedMemorySize,
                             (int)MLP_SMEM);
        cudaFuncSetAttribute(decode_tiled, cudaFuncAttributeMaxDynamicSharedMemorySize,
                             (int)DEC_SMEM);
        attr_done = true;
    }

    auto grid_for = [](int n) { return mini(((long)n + 63) / 64, 4096); };
    auto scat = [&](const int* s, const int* r, int Ecnt) {
        long E16 = (long)Ecnt * 16;
        scatter_kernel<<<mini((E16 + 255) / 256, 8192), 256>>>(M, s, r, AG, E16);
    };
    // weight slices
    auto wm1 = [&](int l) { return Wm1 + (size_t)l * D * D; };
    auto wm2 = [&](int l) { return Wm2 + (size_t)l * D * D; };
    auto bm1l = [&](int l) { return bm1 + (size_t)l * D; };
    auto bm2l = [&](int l) { return bm2 + (size_t)l * D; };
    auto wn1 = [&](int l) { return Wn1 + (size_t)l * 128 * D; };
    auto wn2 = [&](int l) { return Wn2 + (size_t)l * D * D; };
    auto bn1l = [&](int l) { return bn1 + (size_t)l * D; };
    auto bn2l = [&](int l) { return bn2 + (size_t)l * D; };

    // 1. encode + fused msg0 -> A=h1, M=msg0, AG zeroed
    mlp2_tiled<16><<<grid_for(N), 256, MLP_SMEM>>>(
        x, nullptr, nullptr, nullptr, We1, be1, We2, be2, nullptr, A, AG,
        wm1(0), bm1l(0), wm2(0), bm2l(0), M, N);
    scat(s_f, r_f, E);
    // 3. node0 + fused msg1 -> B=h2, M=msg1, AG zeroed
    mlp2_tiled<128><<<grid_for(N), 256, MLP_SMEM>>>(
        A, AG, nullptr, nullptr, wn1(0), bn1l(0), wn2(0), bn2l(0), nullptr, B, AG,
        wm1(1), bm1l(1), wm2(1), bm2l(1), M, N);
    scat(s_f, r_f, E);
    // 5. node1 -> C = h3 (skip source); no fusion (msg2 rows differ)
    mlp2_tiled<128><<<grid_for(N), 256, MLP_SMEM>>>(
        B, AG, nullptr, nullptr, wn1(1), bn1l(1), wn2(1), bn2l(1), nullptr, C, nullptr,
        nullptr, nullptr, nullptr, nullptr, nullptr, N);
    // 6. gather h_ds = C[uppool] -> A (N rows)
    gather_kernel<<<(N * 16 + 511) / 512, 512>>>(C, uppool, A, N);
    // 7. msg2 standalone over A (zero AG fused)
    mlp2_tiled<64><<<grid_for(N), 256, MLP_SMEM>>>(
        A, nullptr, nullptr, nullptr, wm1(2), bm1l(2), wm2(2), bm2l(2), nullptr, M, AG,
        nullptr, nullptr, nullptr, nullptr, nullptr, N);
    scat(s_ds, r_ds, EDS);
    // 9. node2 (rows = downpool) + fused msg3 -> B=hp (NP), M=msg3
    //    AG zero NOT fused (indexed AG reads across blocks) -> explicit below
    mlp2_tiled<128><<<grid_for(NP), 256, MLP_SMEM>>>(
        A, AG, downpool, downpool, wn1(2), bn1l(2), wn2(2), bn2l(2), nullptr, B, nullptr,
        wm1(3), bm1l(3), wm2(3), bm2l(3), M, NP);
    zero_kernel<<<(NP * 16 + 511) / 512, 512>>>((float4*)AG, NP * 16);
    scat(s_p, r_p, EP);
    // 12. node3 + fused msg4 -> A (NP), M=msg4, AG zeroed
    mlp2_tiled<128><<<grid_for(NP), 256, MLP_SMEM>>>(
        B, AG, nullptr, nullptr, wn1(3), bn1l(3), wn2(3), bn2l(3), nullptr, A, AG,
        wm1(4), bm1l(4), wm2(4), bm2l(4), M, NP);
    scat(s_p, r_p, EP);
    // 14. node4 -> B (NP); no fusion (msg5 rows permuted)
    mlp2_tiled<128><<<grid_for(NP), 256, MLP_SMEM>>>(
        A, AG, nullptr, nullptr, wn1(4), bn1l(4), wn2(4), bn2l(4), nullptr, B, nullptr,
        nullptr, nullptr, nullptr, nullptr, nullptr, NP);
    // 15. msg5 standalone over B[downpool] (rowidx0), zero AG [0,NP)
    mlp2_tiled<64><<<grid_for(NP), 256, MLP_SMEM>>>(
        B, nullptr, downpool, nullptr, wm1(5), bm1l(5), wm2(5), bm2l(5), nullptr, M, AG,
        nullptr, nullptr, nullptr, nullptr, nullptr, NP);
    scat(s_us, r_us, EUS);
    // 17. node5: in0 = B[downpool], in1 = AG direct -> A = g_us (NP)
    mlp2_tiled<128><<<grid_for(NP), 256, MLP_SMEM>>>(
        B, AG, downpool, nullptr, wn1(5), bn1l(5), wn2(5), bn2l(5), nullptr, A, nullptr,
        nullptr, nullptr, nullptr, nullptr, nullptr, NP);
    // 18. gather h7in = A[uppool] -> B (N rows)
    gather_kernel<<<(N * 16 + 511) / 512, 512>>>(A, uppool, B, N);
    // 19. msg6 standalone over B, zero AG [0,N)
    mlp2_tiled<64><<<grid_for(N), 256, MLP_SMEM>>>(
        B, nullptr, nullptr, nullptr, wm1(6), bm1l(6), wm2(6), bm2l(6), nullptr, M, AG,
        nullptr, nullptr, nullptr, nullptr, nullptr, N);
    scat(s_f, r_f, E);
    // 21. node6 (skip=C) + fused msg7 -> A (N), M=msg7, AG zeroed
    mlp2_tiled<128><<<grid_for(N), 256, MLP_SMEM>>>(
        B, AG, nullptr, nullptr, wn1(6), bn1l(6), wn2(6), bn2l(6), C, A, AG,
        wm1(7), bm1l(7), wm2(7), bm2l(7), M, N);
    scat(s_f, r_f, E);
    // 23. node7 (skip=C) -> B (N)
    mlp2_tiled<128><<<grid_for(N), 256, MLP_SMEM>>>(
        A, AG, nullptr, nullptr, wn1(7), bn1l(7), wn2(7), bn2l(7), C, B, nullptr,
        nullptr, nullptr, nullptr, nullptr, nullptr, N);
    // 24. decode head
    decode_tiled<<<grid_for(N), 256, DEC_SMEM>>>(B, Wd1, bd1, Wd2, bd2, out, N);
}

// round 13
// speedup vs baseline: 1.6632x; 1.0240x over previous
#include <cuda_runtime.h>
#include <cuda_fp16.h>
#include <cstddef>

#define D 64
#define MAXN 100000

typedef unsigned long long u64;

// Scratch buffers (no allocation allowed) -----------------------------------
__device__ float  g_A[MAXN * D];
__device__ float  g_B[MAXN * D];
__device__ float  g_C[MAXN * D];
__device__ __half g_Mh[MAXN * D];  // per-node messages (fp16 storage)
__device__ float  g_AG[MAXN * D];  // aggregation (fp32)
__device__ int    g_IDX[MAXN];     // composite index scratch

// ---------------------------------------------------------------------------
// packed f32x2 helpers (sm_103a: fma.rn.f32x2 doubles fp32 FMA throughput)
__device__ __forceinline__ u64 fma2(u64 a, u64 b, u64 c) {
    u64 d;
    asm("fma.rn.f32x2 %0, %1, %2, %3;" : "=l"(d) : "l"(a), "l"(b), "l"(c));
    return d;
}
__device__ __forceinline__ u64 pk2(float lo, float hi) {
    u64 r;
    asm("mov.b64 %0, {%1, %2};" : "=l"(r)
        : "r"(__float_as_uint(lo)), "r"(__float_as_uint(hi)));
    return r;
}
__device__ __forceinline__ float2 unpk(u64 p) {
    unsigned int lo, hi;
    asm("mov.b64 {%0, %1}, %2;" : "=r"(lo), "=r"(hi) : "l"(p));
    return make_float2(__uint_as_float(lo), __uint_as_float(hi));
}
union F4U { float4 v; u64 u[2]; };

// ---------------------------------------------------------------------------
__global__ __launch_bounds__(512) void zero_kernel(float4* __restrict__ p, int n4) {
    int i = blockIdx.x * blockDim.x + threadIdx.x;
    if (i < n4) p[i] = make_float4(0.f, 0.f, 0.f, 0.f);
}

// cidx[i] = a[b[i]]
__global__ __launch_bounds__(256) void compose_idx_kernel(const int* __restrict__ a,
                                                          const int* __restrict__ b,
                                                          int* __restrict__ cidx, int n) {
    int i = blockIdx.x * blockDim.x + threadIdx.x;
    if (i < n) cidx[i] = a[b[i]];
}

// aggr[r[e],:] += float(msg_h[s[e],:])  via red.global.add.v4.f32
// msg rows are 64 halves = 128B = 16 uint2; thread (e,c) handles 4 values.
__global__ __launch_bounds__(256) void scatter_kernel(const uint2* __restrict__ msg,
                                                      const int* __restrict__ s,
                                                      const int* __restrict__ r,
                                                      float* __restrict__ aggr, long E16) {
    for (long i = (long)blockIdx.x * 256 + threadIdx.x; i < E16;
         i += (long)gridDim.x * 256) {
        int e = (int)(i >> 4);
        int c = (int)(i & 15);
        int se = __ldg(&s[e]);
        int re = __ldg(&r[e]);
        uint2 raw = __ldg(msg + (size_t)se * 16 + c);
        __half2 p0 = *reinterpret_cast<__half2*>(&raw.x);
        __half2 p1 = *reinterpret_cast<__half2*>(&raw.y);
        float2 f0 = __half22float2(p0);
        float2 f1 = __half22float2(p1);
        float* dst = aggr + (size_t)re * 64 + c * 4;
        asm volatile("red.global.add.v4.f32 [%0], {%1,%2,%3,%4};"
                     :: "l"(dst), "f"(f0.x), "f"(f0.y), "f"(f1.x), "f"(f1.y)
                     : "memory");
    }
}

// ---------------------------------------------------------------------------
// Register-tiled 2-layer MLP (optionally fused with the next layer's message
// MLP that consumes this kernel's output rows).
//   h[row] = relu(X[row]@W1+b1)@W2+b2 (+skip[row])
//   write h to out (fp32) and/or out_h (fp16).
//   if Mout_h: Mout_h[row] = fp16(relu(h_row@Wm1+bm1)@Wm2+bm2); zero_out rows
//              zeroed in the fused epilogue (else in the first epilogue).
// X rows: [in0 | in1] when IN==128 (two 64-col halves, one staging buffer),
// else in0 (row width IN). in0 rows via rowidx0 (if set), in1 rows via
// rowidx1 (if set). out/out_h/skip/Mout_h/zero_out rows are compact.
// Fused path clobbers W2p/b1s/b2s — requires grid == #tiles (true: <=1563).
// 256 threads; tile 64x64; thread tile 4x4, cols {2tc,2tc+1,2tc+32,2tc+33}.
// ---------------------------------------------------------------------------
template <int IN>
__global__ __launch_bounds__(256, 4) void mlp2_tiled(
    const float* __restrict__ in0, const float* __restrict__ in1,
    const int* __restrict__ rowidx0, const int* __restrict__ rowidx1,
    const float* __restrict__ W1, const float* __restrict__ b1,
    const float* __restrict__ W2, const float* __restrict__ b2,
    const float* __restrict__ skip, float* __restrict__ out,
    __half* __restrict__ out_h, float* __restrict__ zero_out,
    const float* __restrict__ Wm1, const float* __restrict__ bm1,
    const float* __restrict__ Wm2, const float* __restrict__ bm2,
    __half* __restrict__ Mout_h, int n) {
    extern __shared__ __align__(16) float sm[];
    u64* Wp  = (u64*)sm;                           // 32*64 u64
    u64* W2p = Wp + 32 * 64;                       // 32*64 u64
    float* b1s = (float*)(W2p + 32 * 64);          // 64
    float* b2s = b1s + 64;                         // 64
    float* xy  = b2s + 64;                         // 64*68 floats

    const int t = threadIdx.x;
    constexpr int XC = (IN < 64) ? IN : 64;
    constexpr int NH = (IN == 128) ? 2 : 1;

    for (int i = t; i < 32 * 64; i += 256) {
        int k2 = i >> 6, c = i & 63;
        W2p[i] = pk2(W2[(2 * k2) * 64 + c], W2[(2 * k2 + 1) * 64 + c]);
    }
    if (t < 64) { b1s[t] = b1[t]; b2s[t] = b2[t]; }
    __syncthreads();

    const int tc = t & 15;
    const int tr = t >> 4;
    const int c0 = tc * 2, c2 = c0 + 32;
    const int r0 = tr * 4;
    const int tiles = (n + 63) >> 6;

    for (int tile = blockIdx.x; tile < tiles; tile += gridDim.x) {
        const int base = tile * 64;

        u64 a[4][4];
#pragma unroll
        for (int i = 0; i < 4; i++) {
            a[i][0] = pk2(b1s[c0], 0.f);
            a[i][1] = pk2(b1s[c0 + 1], 0.f);
            a[i][2] = pk2(b1s[c2], 0.f);
            a[i][3] = pk2(b1s[c2 + 1], 0.f);
        }

#pragma unroll
        for (int h = 0; h < NH; h++) {
            for (int i = t; i < (XC / 2) * 64; i += 256) {
                int k2 = i >> 6, c = i & 63;
                const float* Ws = W1 + h * 64 * 64;
                Wp[i] = pk2(Ws[(2 * k2) * 64 + c], Ws[(2 * k2 + 1) * 64 + c]);
            }
            constexpr int C4 = XC / 4;
            for (int i = t; i < 64 * C4; i += 256) {
                int row = i / C4, col = (i % C4) * 4;
                int node = base + row;
                float4 v = make_float4(0.f, 0.f, 0.f, 0.f);
                if (node < n) {
                    const int* ridx = (h == 0) ? rowidx0 : rowidx1;
                    int src = ridx ? ridx[node] : node;
                    const float* p = (h == 0) ? in0 : in1;
                    v = *(const float4*)&p[(size_t)src * XC + col];
                }
                *(float4*)&xy[row * 68 + col] = v;
            }
            __syncthreads();
#pragma unroll 8
            for (int k = 0; k < XC; k += 4) {
                F4U xq[4];
#pragma unroll
                for (int i = 0; i < 4; i++)
                    xq[i].v = *(const float4*)&xy[(r0 + i) * 68 + k];
#pragma unroll
                for (int kk2 = 0; kk2 < 2; kk2++) {
                    ulonglong2 wA = *(const ulonglong2*)&Wp[(k / 2 + kk2) * 64 + c0];
                    ulonglong2 wB = *(const ulonglong2*)&Wp[(k / 2 + kk2) * 64 + c2];
#pragma unroll
                    for (int i = 0; i < 4; i++) {
                        u64 xp = xq[i].u[kk2];
                        a[i][0] = fma2(xp, wA.x, a[i][0]);
                        a[i][1] = fma2(xp, wA.y, a[i][1]);
                        a[i][2] = fma2(xp, wB.x, a[i][2]);
                        a[i][3] = fma2(xp, wB.y, a[i][3]);
                    }
                }
            }
            __syncthreads();
        }

        // relu + write Y into xy
#pragma unroll
        for (int i = 0; i < 4; i++) {
            float2 q0 = unpk(a[i][0]), q1 = unpk(a[i][1]);
            float2 q2 = unpk(a[i][2]), q3 = unpk(a[i][3]);
            float2 vA = make_float2(fmaxf(q0.x + q0.y, 0.f), fmaxf(q1.x + q1.y, 0.f));
            float2 vB = make_float2(fmaxf(q2.x + q2.y, 0.f), fmaxf(q3.x + q3.y, 0.f));
            *(float2*)&xy[(r0 + i) * 68 + c0] = vA;
            *(float2*)&xy[(r0 + i) * 68 + c2] = vB;
        }
        __syncthreads();

        // ---- GEMM2: h = Y @ W2 + b2 (+skip) ----
#pragma unroll
        for (int i = 0; i < 4; i++) {
            a[i][0] = pk2(b2s[c0], 0.f);
            a[i][1] = pk2(b2s[c0 + 1], 0.f);
            a[i][2] = pk2(b2s[c2], 0.f);
            a[i][3] = pk2(b2s[c2 + 1], 0.f);
        }
#pragma unroll 8
        for (int k = 0; k < 64; k += 4) {
            F4U xq[4];
#pragma unroll
            for (int i = 0; i < 4; i++)
                xq[i].v = *(const float4*)&xy[(r0 + i) * 68 + k];
#pragma unroll
            for (int kk2 = 0; kk2 < 2; kk2++) {
                ulonglong2 wA = *(const ulonglong2*)&W2p[(k / 2 + kk2) * 64 + c0];
                ulonglong2 wB = *(const ulonglong2*)&W2p[(k / 2 + kk2) * 64 + c2];
#pragma unroll
                for (int i = 0; i < 4; i++) {
                    u64 xp = xq[i].u[kk2];
                    a[i][0] = fma2(xp, wA.x, a[i][0]);
                    a[i][1] = fma2(xp, wA.y, a[i][1]);
                    a[i][2] = fma2(xp, wB.x, a[i][2]);
                    a[i][3] = fma2(xp, wB.y, a[i][3]);
                }
            }
        }
        float2 hA[4], hB[4];
#pragma unroll
        for (int i = 0; i < 4; i++) {
            float2 q0 = unpk(a[i][0]), q1 = unpk(a[i][1]);
            float2 q2 = unpk(a[i][2]), q3 = unpk(a[i][3]);
            hA[i] = make_float2(q0.x + q0.y, q1.x + q1.y);
            hB[i] = make_float2(q2.x + q2.y, q3.x + q3.y);
            int node = base + r0 + i;
            if (node < n) {
                if (skip) {
                    float2 sA = *(const float2*)&skip[(size_t)node * 64 + c0];
                    float2 sB = *(const float2*)&skip[(size_t)node * 64 + c2];
                    hA[i].x += sA.x; hA[i].y += sA.y;
                    hB[i].x += sB.x; hB[i].y += sB.y;
                }
                if (out) {
                    *(float2*)&out[(size_t)node * 64 + c0] = hA[i];
                    *(float2*)&out[(size_t)node * 64 + c2] = hB[i];
                }
                if (out_h) {
                    *(__half2*)&out_h[(size_t)node * 64 + c0] =
                        __floats2half2_rn(hA[i].x, hA[i].y);
                    *(__half2*)&out_h[(size_t)node * 64 + c2] =
                        __floats2half2_rn(hB[i].x, hB[i].y);
                }
                if (!Mout_h && zero_out) {
                    float2 z = make_float2(0.f, 0.f);
                    *(float2*)&zero_out[(size_t)node * 64 + c0] = z;
                    *(float2*)&zero_out[(size_t)node * 64 + c2] = z;
                }
            }
        }

        // ================= fused next-layer message MLP =================
        if (Mout_h) {
            __syncthreads();   // all Y reads of xy done
#pragma unroll
            for (int i = 0; i < 4; i++) {
                bool valid = (base + r0 + i) < n;
                float2 vA = valid ? hA[i] : make_float2(0.f, 0.f);
                float2 vB = valid ? hB[i] : make_float2(0.f, 0.f);
                *(float2*)&xy[(r0 + i) * 68 + c0] = vA;
                *(float2*)&xy[(r0 + i) * 68 + c2] = vB;
            }
            for (int i = t; i < 32 * 64; i += 256) {
                int k2 = i >> 6, c = i & 63;
                Wp[i]  = pk2(Wm1[(2 * k2) * 64 + c], Wm1[(2 * k2 + 1) * 64 + c]);
                W2p[i] = pk2(Wm2[(2 * k2) * 64 + c], Wm2[(2 * k2 + 1) * 64 + c]);
            }
            if (t < 64) { b1s[t] = bm1[t]; b2s[t] = bm2[t]; }
            __syncthreads();

            // GEMM3: Y2 = relu(h @ Wm1 + bm1)
#pragma unroll
            for (int i = 0; i < 4; i++) {
                a[i][0] = pk2(b1s[c0], 0.f);
                a[i][1] = pk2(b1s[c0 + 1], 0.f);
                a[i][2] = pk2(b1s[c2], 0.f);
                a[i][3] = pk2(b1s[c2 + 1], 0.f);
            }
#pragma unroll 8
            for (int k = 0; k < 64; k += 4) {
                F4U xq[4];
#pragma unroll
                for (int i = 0; i < 4; i++)
                    xq[i].v = *(const float4*)&xy[(r0 + i) * 68 + k];
#pragma unroll
                for (int kk2 = 0; kk2 < 2; kk2++) {
                    ulonglong2 wA = *(const ulonglong2*)&Wp[(k / 2 + kk2) * 64 + c0];
                    ulonglong2 wB = *(const ulonglong2*)&Wp[(k / 2 + kk2) * 64 + c2];
#pragma unroll
                    for (int i = 0; i < 4; i++) {
                        u64 xp = xq[i].u[kk2];
                        a[i][0] = fma2(xp, wA.x, a[i][0]);
                        a[i][1] = fma2(xp, wA.y, a[i][1]);
                        a[i][2] = fma2(xp, wB.x, a[i][2]);
                        a[i][3] = fma2(xp, wB.y, a[i][3]);
                    }
                }
            }
            __syncthreads();
#pragma unroll
            for (int i = 0; i < 4; i++) {
                float2 q0 = unpk(a[i][0]), q1 = unpk(a[i][1]);
                float2 q2 = unpk(a[i][2]), q3 = unpk(a[i][3]);
                float2 vA = make_float2(fmaxf(q0.x + q0.y, 0.f), fmaxf(q1.x + q1.y, 0.f));
                float2 vB = make_float2(fmaxf(q2.x + q2.y, 0.f), fmaxf(q3.x + q3.y, 0.f));
                *(float2*)&xy[(r0 + i) * 68 + c0] = vA;
                *(float2*)&xy[(r0 + i) * 68 + c2] = vB;
            }
            __syncthreads();

            // GEMM4: M = Y2 @ Wm2 + bm2 -> fp16 Mout + zero AG rows
#pragma unroll
            for (int i = 0; i < 4; i++) {
                a[i][0] = pk2(b2s[c0], 0.f);
                a[i][1] = pk2(b2s[c0 + 1], 0.f);
                a[i][2] = pk2(b2s[c2], 0.f);
                a[i][3] = pk2(b2s[c2 + 1], 0.f);
            }
#pragma unroll 8
            for (int k = 0; k < 64; k += 4) {
                F4U xq[4];
#pragma unroll
                for (int i = 0; i < 4; i++)
                    xq[i].v = *(const float4*)&xy[(r0 + i) * 68 + k];
#pragma unroll
                for (int kk2 = 0; kk2 < 2; kk2++) {
                    ulonglong2 wA = *(const ulonglong2*)&W2p[(k / 2 + kk2) * 64 + c0];
                    ulonglong2 wB = *(const ulonglong2*)&W2p[(k / 2 + kk2) * 64 + c2];
#pragma unroll
                    for (int i = 0; i < 4; i++) {
                        u64 xp = xq[i].u[kk2];
                        a[i][0] = fma2(xp, wA.x, a[i][0]);
                        a[i][1] = fma2(xp, wA.y, a[i][1]);
                        a[i][2] = fma2(xp, wB.x, a[i][2]);
                        a[i][3] = fma2(xp, wB.y, a[i][3]);
                    }
                }
            }
#pragma unroll
            for (int i = 0; i < 4; i++) {
                int node = base + r0 + i;
                if (node < n) {
                    float2 q0 = unpk(a[i][0]), q1 = unpk(a[i][1]);
                    float2 q2 = unpk(a[i][2]), q3 = unpk(a[i][3]);
                    *(__half2*)&Mout_h[(size_t)node * 64 + c0] =
                        __floats2half2_rn(q0.x + q0.y, q1.x + q1.y);
                    *(__half2*)&Mout_h[(size_t)node * 64 + c2] =
                        __floats2half2_rn(q2.x + q2.y, q3.x + q3.y);
                    if (zero_out) {
                        float2 z = make_float2(0.f, 0.f);
                        *(float2*)&zero_out[(size_t)node * 64 + c0] = z;
                        *(float2*)&zero_out[(size_t)node * 64 + c2] = z;
                    }
                }
            }
        }
        __syncthreads();
    }
}

// ---------------------------------------------------------------------------
// Tiled decode: out[n,2] = relu(h@Wd1+bd1)@Wd2+bd2
// ---------------------------------------------------------------------------
__global__ __launch_bounds__(256, 4) void decode_tiled(const float* __restrict__ hin,
                                                       const float* __restrict__ W1,
                                                       const float* __restrict__ b1,
                                                       const float* __restrict__ W2,
                                                       const float* __restrict__ b2,
                                                       float* __restrict__ out, int n) {
    extern __shared__ __align__(16) float sm[];
    u64* Wp  = (u64*)sm;                           // 32*64 u64
    float* b1s = (float*)(Wp + 32 * 64);           // 64
    float* W2s = b1s + 64;                         // 128
    float* b2s = W2s + 128;                        // 2 (+pad)
    float* xy  = b2s + 4;                          // 64*68

    const int t = threadIdx.x;
    for (int i = t; i < 32 * 64; i += 256) {
        int k2 = i >> 6, c = i & 63;
        Wp[i] = pk2(W1[(2 * k2) * 64 + c], W1[(2 * k2 + 1) * 64 + c]);
    }
    if (t < 64) b1s[t] = b1[t];
    if (t < 128) W2s[t] = W2[t];
    if (t < 2) b2s[t] = b2[t];
    __syncthreads();

    const int tc = t & 15;
    const int tr = t >> 4;
    const int c0 = tc * 2, c2 = c0 + 32;
    const int r0 = tr * 4;
    const int tiles = (n + 63) >> 6;

    for (int tile = blockIdx.x; tile < tiles; tile += gridDim.x) {
        const int base = tile * 64;
        for (int i = t; i < 64 * 16; i += 256) {
            int row = i >> 4, col = (i & 15) * 4;
            int node = base + row;
            float4 v = make_float4(0.f, 0.f, 0.f, 0.f);
            if (node < n) v = *(const float4*)&hin[(size_t)node * 64 + col];
            *(float4*)&xy[row * 68 + col] = v;
        }
        __syncthreads();

        u64 a[4][4];
#pragma unroll
        for (int i = 0; i < 4; i++) {
            a[i][0] = pk2(b1s[c0], 0.f);
            a[i][1] = pk2(b1s[c0 + 1], 0.f);
            a[i][2] = pk2(b1s[c2], 0.f);
            a[i][3] = pk2(b1s[c2 + 1], 0.f);
        }
#pragma unroll 8
        for (int k = 0; k < 64; k += 4) {
            F4U xq[4];
#pragma unroll
            for (int i = 0; i < 4; i++)
                xq[i].v = *(const float4*)&xy[(r0 + i) * 68 + k];
#pragma unroll
            for (int kk2 = 0; kk2 < 2; kk2++) {
                ulonglong2 wA = *(const ulonglong2*)&Wp[(k / 2 + kk2) * 64 + c0];
                ulonglong2 wB = *(const ulonglong2*)&Wp[(k / 2 + kk2) * 64 + c2];
#pragma unroll
                for (int i = 0; i < 4; i++) {
                    u64 xp = xq[i].u[kk2];
                    a[i][0] = fma2(xp, wA.x, a[i][0]);
                    a[i][1] = fma2(xp, wA.y, a[i][1]);
                    a[i][2] = fma2(xp, wB.x, a[i][2]);
                    a[i][3] = fma2(xp, wB.y, a[i][3]);
                }
            }
        }
        __syncthreads();
#pragma unroll
        for (int i = 0; i < 4; i++) {
            float2 q0 = unpk(a[i][0]), q1 = unpk(a[i][1]);
            float2 q2 = unpk(a[i][2]), q3 = unpk(a[i][3]);
            float2 vA = make_float2(fmaxf(q0.x + q0.y, 0.f), fmaxf(q1.x + q1.y, 0.f));
            float2 vB = make_float2(fmaxf(q2.x + q2.y, 0.f), fmaxf(q3.x + q3.y, 0.f));
            *(float2*)&xy[(r0 + i) * 68 + c0] = vA;
            *(float2*)&xy[(r0 + i) * 68 + c2] = vB;
        }
        __syncthreads();

        if (t < 128) {
            int row = t >> 1, col = t & 1;
            int node = base + row;
            if (node < n) {
                float acc = b2s[col];
                const float* yr = &xy[row * 68];
#pragma unroll 16
                for (int k = 0; k < 64; k++) acc += yr[k] * W2s[k * 2 + col];
                out[(size_t)node * 2 + col] = acc;
            }
        }
        __syncthreads();
    }
}

// ---------------------------------------------------------------------------
static inline int mini(long a, long b) { return (int)(a < b ? a : b); }

static constexpr size_t MLP_SMEM =
    (size_t)(32 * 64 * 8) * 2 + 128 * 4 + 64 * 68 * 4;   // ~49.5 KB
static constexpr size_t DEC_SMEM =
    (size_t)(32 * 64 * 8) + (64 + 128 + 4) * 4 + 64 * 68 * 4;  // ~34.5 KB

extern "C" void kernel_launch(void* const* d_in, const int* in_sizes, int n_in,
                              void* d_out, int out_size) {
    const float* x   = (const float*)d_in[0];
    const float* We1 = (const float*)d_in[1];
    const float* be1 = (const float*)d_in[2];
    const float* We2 = (const float*)d_in[3];
    const float* be2 = (const float*)d_in[4];
    const float* Wm1 = (const float*)d_in[5];
    const float* bm1 = (const float*)d_in[6];
    const float* Wm2 = (const float*)d_in[7];
    const float* bm2 = (const float*)d_in[8];
    const float* Wn1 = (const float*)d_in[9];
    const float* bn1 = (const float*)d_in[10];
    const float* Wn2 = (const float*)d_in[11];
    const float* bn2 = (const float*)d_in[12];
    const float* Wd1 = (const float*)d_in[13];
    const float* bd1 = (const float*)d_in[14];
    const float* Wd2 = (const float*)d_in[15];
    const float* bd2 = (const float*)d_in[16];
    const int* s_f  = (const int*)d_in[17];
    const int* r_f  = (const int*)d_in[18];
    const int* s_ds = (const int*)d_in[19];
    const int* r_ds = (const int*)d_in[20];
    const int* s_p  = (const int*)d_in[21];
    const int* r_p  = (const int*)d_in[22];
    const int* s_us = (const int*)d_in[23];
    const int* r_us = (const int*)d_in[24];
    const int* uppool   = (const int*)d_in[25];
    const int* downpool = (const int*)d_in[26];

    int N   = in_sizes[0] / 16;
    int NP  = in_sizes[26];
    int E   = in_sizes[17];
    int EDS = in_sizes[19];
    int EP  = in_sizes[21];
    int EUS = in_sizes[23];
    float* out = (float*)d_out;

    float *A, *B, *C, *AG;
    __half* Mh;
    int* IDX;
    cudaGetSymbolAddress((void**)&A, g_A);
    cudaGetSymbolAddress((void**)&B, g_B);
    cudaGetSymbolAddress((void**)&C, g_C);
    cudaGetSymbolAddress((void**)&Mh, g_Mh);
    cudaGetSymbolAddress((void**)&AG, g_AG);
    cudaGetSymbolAddress((void**)&IDX, g_IDX);

    static bool attr_done = false;
    if (!attr_done) {
        cudaFuncSetAttribute(mlp2_tiled<16>, cudaFuncAttributeMaxDynamicSharedMemorySize,
                             (int)MLP_SMEM);
        cudaFuncSetAttribute(mlp2_tiled<64>, cudaFuncAttributeMaxDynamicSharedMemorySize,
                             (int)MLP_SMEM);
        cudaFuncSetAttribute(mlp2_tiled<128>, cudaFuncAttributeMaxDynamicSharedMemorySize,
                             (int)MLP_SMEM);
        cudaFuncSetAttribute(decode_tiled, cudaFuncAttributeMaxDynamicSharedMemorySize,
                             (int)DEC_SMEM);
        attr_done = true;
    }

    auto grid_for = [](int n) { return mini(((long)n + 63) / 64, 4096); };
    auto scat = [&](const int* s, const int* r, int Ecnt) {
        long E16 = (long)Ecnt * 16;
        scatter_kernel<<<mini((E16 + 255) / 256, 8192), 256>>>(
            (const uint2*)Mh, s, r, AG, E16);
    };
    auto wm1 = [&](int l) { return Wm1 + (size_t)l * D * D; };
    auto wm2 = [&](int l) { return Wm2 + (size_t)l * D * D; };
    auto bm1l = [&](int l) { return bm1 + (size_t)l * D; };
    auto bm2l = [&](int l) { return bm2 + (size_t)l * D; };
    auto wn1 = [&](int l) { return Wn1 + (size_t)l * 128 * D; };
    auto wn2 = [&](int l) { return Wn2 + (size_t)l * D * D; };
    auto bn1l = [&](int l) { return bn1 + (size_t)l * D; };
    auto bn2l = [&](int l) { return bn2 + (size_t)l * D; };

    // IDX[i] = uppool[downpool[i]]  (for node2's in0 indexing)
    compose_idx_kernel<<<(NP + 255) / 256, 256>>>(uppool, downpool, IDX, NP);

    // encode + fused msg0 -> A=h1, Mh=msg0, AG zeroed
    mlp2_tiled<16><<<grid_for(N), 256, MLP_SMEM>>>(
        x, nullptr, nullptr, nullptr, We1, be1, We2, be2, nullptr, A, nullptr, AG,
        wm1(0), bm1l(0), wm2(0), bm2l(0), Mh, N);
    scat(s_f, r_f, E);
    // node0 + fused msg1 -> B=h2
    mlp2_tiled<128><<<grid_for(N), 256, MLP_SMEM>>>(
        A, AG, nullptr, nullptr, wn1(0), bn1l(0), wn2(0), bn2l(0), nullptr, B, nullptr, AG,
        wm1(1), bm1l(1), wm2(1), bm2l(1), Mh, N);
    scat(s_f, r_f, E);
    // node1 -> C = h3 (skip source)
    mlp2_tiled<128><<<grid_for(N), 256, MLP_SMEM>>>(
        B, AG, nullptr, nullptr, wn1(1), bn1l(1), wn2(1), bn2l(1), nullptr, C, nullptr,
        nullptr, nullptr, nullptr, nullptr, nullptr, nullptr, N);
    // msg2 over C[uppool[i]] (no gather), zero AG [0,N)
    mlp2_tiled<64><<<grid_for(N), 256, MLP_SMEM>>>(
        C, nullptr, uppool, nullptr, wm1(2), bm1l(2), wm2(2), bm2l(2), nullptr,
        nullptr, Mh, AG, nullptr, nullptr, nullptr, nullptr, nullptr, N);
    scat(s_ds, r_ds, EDS);
    // node2 (in0 = C[uppool[downpool[i]]], in1 = AG[downpool[i]]) + fused msg3
    //   AG zero NOT fused (indexed AG reads across blocks) -> explicit below
    mlp2_tiled<128><<<grid_for(NP), 256, MLP_SMEM>>>(
        C, AG, IDX, downpool, wn1(2), bn1l(2), wn2(2), bn2l(2), nullptr, B, nullptr,
        nullptr, wm1(3), bm1l(3), wm2(3), bm2l(3), Mh, NP);
    zero_kernel<<<(NP * 16 + 511) / 512, 512>>>((float4*)AG, NP * 16);
    scat(s_p, r_p, EP);
    // node3 + fused msg4 -> A (NP), AG zeroed
    mlp2_tiled<128><<<grid_for(NP), 256, MLP_SMEM>>>(
        B, AG, nullptr, nullptr, wn1(3), bn1l(3), wn2(3), bn2l(3), nullptr, A, nullptr, AG,
        wm1(4), bm1l(4), wm2(4), bm2l(4), Mh, NP);
    scat(s_p, r_p, EP);
    // node4 -> B (NP)
    mlp2_tiled<128><<<grid_for(NP), 256, MLP_SMEM>>>(
        A, AG, nullptr, nullptr, wn1(4), bn1l(4), wn2(4), bn2l(4), nullptr, B, nullptr,
        nullptr, nullptr, nullptr, nullptr, nullptr, nullptr, NP);
    // msg5 over B[downpool[i]], zero AG [0,NP)
    mlp2_tiled<64><<<grid_for(NP), 256, MLP_SMEM>>>(
        B, nullptr, downpool, nullptr, wm1(5), bm1l(5), wm2(5), bm2l(5), nullptr,
        nullptr, Mh, AG, nullptr, nullptr, nullptr, nullptr, nullptr, NP);
    scat(s_us, r_us, EUS);
    // node5: in0 = B[downpool[i]], in1 = AG -> A = g_us (NP)
    mlp2_tiled<128><<<grid_for(NP), 256, MLP_SMEM>>>(
        B, AG, downpool, nullptr, wn1(5), bn1l(5), wn2(5), bn2l(5), nullptr, A, nullptr,
        nullptr, nullptr, nullptr, nullptr, nullptr, nullptr, NP);
    // msg6 over A[uppool[i]] (no gather), zero AG [0,N)
    mlp2_tiled<64><<<grid_for(N), 256, MLP_SMEM>>>(
        A, nullptr, uppool, nullptr, wm1(6), bm1l(6), wm2(6), bm2l(6), nullptr,
        nullptr, Mh, AG, nullptr, nullptr, nullptr, nullptr, nullptr, N);
    scat(s_f, r_f, E);
    // node6 (in0 = A[uppool[i]], skip=C) + fused msg7 -> B (N), AG zeroed
    mlp2_tiled<128><<<grid_for(N), 256, MLP_SMEM>>>(
        A, AG, uppool, nullptr, wn1(6), bn1l(6), wn2(6), bn2l(6), C, B, nullptr, AG,
        wm1(7), bm1l(7), wm2(7), bm2l(7), Mh, N);
    scat(s_f, r_f, E);
    // node7 (skip=C) -> A (N)
    mlp2_tiled<128><<<grid_for(N), 256, MLP_SMEM>>>(
        B, AG, nullptr, nullptr, wn1(7), bn1l(7), wn2(7), bn2l(7), C, A, nullptr,
        nullptr, nullptr, nullptr, nullptr, nullptr, nullptr, N);
    // decode head
    decode_tiled<<<grid_for(N), 256, DEC_SMEM>>>(A, Wd1, bd1, Wd2, bd2, out, N);
}

// round 15
// speedup vs baseline: 1.6817x; 1.0111x over previous
#include <cuda_runtime.h>
#include <cuda_fp16.h>
#include <cstddef>

#define D 64
#define MAXN 100000

typedef unsigned long long u64;

// Scratch buffers (no allocation allowed) -----------------------------------
__device__ float  g_A[MAXN * D];
__device__ float  g_B[MAXN * D];
__device__ float  g_C[MAXN * D];
__device__ __half g_Mh[MAXN * D];  // per-node messages (fp16 storage)
__device__ float  g_AG[MAXN * D];  // aggregation (fp32)
__device__ int    g_IDX[MAXN];     // composite index scratch

// ---------------------------------------------------------------------------
// packed f32x2 helpers (sm_103a: fma.rn.f32x2 doubles fp32 FMA throughput)
__device__ __forceinline__ u64 fma2(u64 a, u64 b, u64 c) {
    u64 d;
    asm("fma.rn.f32x2 %0, %1, %2, %3;" : "=l"(d) : "l"(a), "l"(b), "l"(c));
    return d;
}
__device__ __forceinline__ u64 pk2(float lo, float hi) {
    u64 r;
    asm("mov.b64 %0, {%1, %2};" : "=l"(r)
        : "r"(__float_as_uint(lo)), "r"(__float_as_uint(hi)));
    return r;
}
__device__ __forceinline__ float2 unpk(u64 p) {
    unsigned int lo, hi;
    asm("mov.b64 {%0, %1}, %2;" : "=r"(lo), "=r"(hi) : "l"(p));
    return make_float2(__uint_as_float(lo), __uint_as_float(hi));
}
union F4U { float4 v; u64 u[2]; };

// ---------------------------------------------------------------------------
__global__ __launch_bounds__(512) void zero_kernel(float4* __restrict__ p, int n4) {
    int i = blockIdx.x * blockDim.x + threadIdx.x;
    if (i < n4) p[i] = make_float4(0.f, 0.f, 0.f, 0.f);
}

// cidx[i] = a[b[i]]
__global__ __launch_bounds__(256) void compose_idx_kernel(const int* __restrict__ a,
                                                          const int* __restrict__ b,
                                                          int* __restrict__ cidx, int n) {
    int i = blockIdx.x * blockDim.x + threadIdx.x;
    if (i < n) cidx[i] = a[b[i]];
}

// aggr[r[e],:] += float(msg_h[s[e],:])  via red.global.add.v4.f32
__global__ __launch_bounds__(256) void scatter_kernel(const uint2* __restrict__ msg,
                                                      const int* __restrict__ s,
                                                      const int* __restrict__ r,
                                                      float* __restrict__ aggr, long E16) {
    for (long i = (long)blockIdx.x * 256 + threadIdx.x; i < E16;
         i += (long)gridDim.x * 256) {
        int e = (int)(i >> 4);
        int c = (int)(i & 15);
        int se = __ldg(&s[e]);
        int re = __ldg(&r[e]);
        uint2 raw = __ldg(msg + (size_t)se * 16 + c);
        __half2 p0 = *reinterpret_cast<__half2*>(&raw.x);
        __half2 p1 = *reinterpret_cast<__half2*>(&raw.y);
        float2 f0 = __half22float2(p0);
        float2 f1 = __half22float2(p1);
        float* dst = aggr + (size_t)re * 64 + c * 4;
        asm volatile("red.global.add.v4.f32 [%0], {%1,%2,%3,%4};"
                     :: "l"(dst), "f"(f0.x), "f"(f0.y), "f"(f1.x), "f"(f1.y)
                     : "memory");
    }
}

// ---------------------------------------------------------------------------
// Register-tiled 2-layer MLP (optionally fused with the next layer's message
// MLP that consumes this kernel's output rows).   [R13, committed base]
// ---------------------------------------------------------------------------
template <int IN>
__global__ __launch_bounds__(256, 4) void mlp2_tiled(
    const float* __restrict__ in0, const float* __restrict__ in1,
    const int* __restrict__ rowidx0, const int* __restrict__ rowidx1,
    const float* __restrict__ W1, const float* __restrict__ b1,
    const float* __restrict__ W2, const float* __restrict__ b2,
    const float* __restrict__ skip, float* __restrict__ out,
    __half* __restrict__ out_h, float* __restrict__ zero_out,
    const float* __restrict__ Wm1, const float* __restrict__ bm1,
    const float* __restrict__ Wm2, const float* __restrict__ bm2,
    __half* __restrict__ Mout_h, int n) {
    extern __shared__ __align__(16) float sm[];
    u64* Wp  = (u64*)sm;                           // 32*64 u64
    u64* W2p = Wp + 32 * 64;                       // 32*64 u64
    float* b1s = (float*)(W2p + 32 * 64);          // 64
    float* b2s = b1s + 64;                         // 64
    float* xy  = b2s + 64;                         // 64*68 floats

    const int t = threadIdx.x;
    constexpr int XC = (IN < 64) ? IN : 64;
    constexpr int NH = (IN == 128) ? 2 : 1;

    for (int i = t; i < 32 * 64; i += 256) {
        int k2 = i >> 6, c = i & 63;
        W2p[i] = pk2(W2[(2 * k2) * 64 + c], W2[(2 * k2 + 1) * 64 + c]);
    }
    if (t < 64) { b1s[t] = b1[t]; b2s[t] = b2[t]; }
    __syncthreads();

    const int tc = t & 15;
    const int tr = t >> 4;
    const int c0 = tc * 2, c2 = c0 + 32;
    const int r0 = tr * 4;
    const int tiles = (n + 63) >> 6;

    for (int tile = blockIdx.x; tile < tiles; tile += gridDim.x) {
        const int base = tile * 64;

        u64 a[4][4];
#pragma unroll
        for (int i = 0; i < 4; i++) {
            a[i][0] = pk2(b1s[c0], 0.f);
            a[i][1] = pk2(b1s[c0 + 1], 0.f);
            a[i][2] = pk2(b1s[c2], 0.f);
            a[i][3] = pk2(b1s[c2 + 1], 0.f);
        }

#pragma unroll
        for (int h = 0; h < NH; h++) {
            for (int i = t; i < (XC / 2) * 64; i += 256) {
                int k2 = i >> 6, c = i & 63;
                const float* Ws = W1 + h * 64 * 64;
                Wp[i] = pk2(Ws[(2 * k2) * 64 + c], Ws[(2 * k2 + 1) * 64 + c]);
            }
            constexpr int C4 = XC / 4;
            for (int i = t; i < 64 * C4; i += 256) {
                int row = i / C4, col = (i % C4) * 4;
                int node = base + row;
                float4 v = make_float4(0.f, 0.f, 0.f, 0.f);
                if (node < n) {
                    const int* ridx = (h == 0) ? rowidx0 : rowidx1;
                    int src = ridx ? ridx[node] : node;
                    const float* p = (h == 0) ? in0 : in1;
                    v = *(const float4*)&p[(size_t)src * XC + col];
                }
                *(float4*)&xy[row * 68 + col] = v;
            }
            __syncthreads();
#pragma unroll 8
            for (int k = 0; k < XC; k += 4) {
                F4U xq[4];
#pragma unroll
                for (int i = 0; i < 4; i++)
                    xq[i].v = *(const float4*)&xy[(r0 + i) * 68 + k];
#pragma unroll
                for (int kk2 = 0; kk2 < 2; kk2++) {
                    ulonglong2 wA = *(const ulonglong2*)&Wp[(k / 2 + kk2) * 64 + c0];
                    ulonglong2 wB = *(const ulonglong2*)&Wp[(k / 2 + kk2) * 64 + c2];
#pragma unroll
                    for (int i = 0; i < 4; i++) {
                        u64 xp = xq[i].u[kk2];
                        a[i][0] = fma2(xp, wA.x, a[i][0]);
                        a[i][1] = fma2(xp, wA.y, a[i][1]);
                        a[i][2] = fma2(xp, wB.x, a[i][2]);
                        a[i][3] = fma2(xp, wB.y, a[i][3]);
                    }
                }
            }
            __syncthreads();
        }

        // relu + write Y into xy
#pragma unroll
        for (int i = 0; i < 4; i++) {
            float2 q0 = unpk(a[i][0]), q1 = unpk(a[i][1]);
            float2 q2 = unpk(a[i][2]), q3 = unpk(a[i][3]);
            float2 vA = make_float2(fmaxf(q0.x + q0.y, 0.f), fmaxf(q1.x + q1.y, 0.f));
            float2 vB = make_float2(fmaxf(q2.x + q2.y, 0.f), fmaxf(q3.x + q3.y, 0.f));
            *(float2*)&xy[(r0 + i) * 68 + c0] = vA;
            *(float2*)&xy[(r0 + i) * 68 + c2] = vB;
        }
        __syncthreads();

        // ---- GEMM2: h = Y @ W2 + b2 (+skip) ----
#pragma unroll
        for (int i = 0; i < 4; i++) {
            a[i][0] = pk2(b2s[c0], 0.f);
            a[i][1] = pk2(b2s[c0 + 1], 0.f);
            a[i][2] = pk2(b2s[c2], 0.f);
            a[i][3] = pk2(b2s[c2 + 1], 0.f);
        }
#pragma unroll 8
        for (int k = 0; k < 64; k += 4) {
            F4U xq[4];
#pragma unroll
            for (int i = 0; i < 4; i++)
                xq[i].v = *(const float4*)&xy[(r0 + i) * 68 + k];
#pragma unroll
            for (int kk2 = 0; kk2 < 2; kk2++) {
                ulonglong2 wA = *(const ulonglong2*)&W2p[(k / 2 + kk2) * 64 + c0];
                ulonglong2 wB = *(const ulonglong2*)&W2p[(k / 2 + kk2) * 64 + c2];
#pragma unroll
                for (int i = 0; i < 4; i++) {
                    u64 xp = xq[i].u[kk2];
                    a[i][0] = fma2(xp, wA.x, a[i][0]);
                    a[i][1] = fma2(xp, wA.y, a[i][1]);
                    a[i][2] = fma2(xp, wB.x, a[i][2]);
                    a[i][3] = fma2(xp, wB.y, a[i][3]);
                }
            }
        }
        float2 hA[4], hB[4];
#pragma unroll
        for (int i = 0; i < 4; i++) {
            float2 q0 = unpk(a[i][0]), q1 = unpk(a[i][1]);
            float2 q2 = unpk(a[i][2]), q3 = unpk(a[i][3]);
            hA[i] = make_float2(q0.x + q0.y, q1.x + q1.y);
            hB[i] = make_float2(q2.x + q2.y, q3.x + q3.y);
            int node = base + r0 + i;
            if (node < n) {
                if (skip) {
                    float2 sA = *(const float2*)&skip[(size_t)node * 64 + c0];
                    float2 sB = *(const float2*)&skip[(size_t)node * 64 + c2];
                    hA[i].x += sA.x; hA[i].y += sA.y;
                    hB[i].x += sB.x; hB[i].y += sB.y;
                }
                if (out) {
                    *(float2*)&out[(size_t)node * 64 + c0] = hA[i];
                    *(float2*)&out[(size_t)node * 64 + c2] = hB[i];
                }
                if (out_h) {
                    *(__half2*)&out_h[(size_t)node * 64 + c0] =
                        __floats2half2_rn(hA[i].x, hA[i].y);
                    *(__half2*)&out_h[(size_t)node * 64 + c2] =
                        __floats2half2_rn(hB[i].x, hB[i].y);
                }
                if (!Mout_h && zero_out) {
                    float2 z = make_float2(0.f, 0.f);
                    *(float2*)&zero_out[(size_t)node * 64 + c0] = z;
                    *(float2*)&zero_out[(size_t)node * 64 + c2] = z;
                }
            }
        }

        // ================= fused next-layer message MLP =================
        if (Mout_h) {
            __syncthreads();
#pragma unroll
            for (int i = 0; i < 4; i++) {
                bool valid = (base + r0 + i) < n;
                float2 vA = valid ? hA[i] : make_float2(0.f, 0.f);
                float2 vB = valid ? hB[i] : make_float2(0.f, 0.f);
                *(float2*)&xy[(r0 + i) * 68 + c0] = vA;
                *(float2*)&xy[(r0 + i) * 68 + c2] = vB;
            }
            for (int i = t; i < 32 * 64; i += 256) {
                int k2 = i >> 6, c = i & 63;
                Wp[i]  = pk2(Wm1[(2 * k2) * 64 + c], Wm1[(2 * k2 + 1) * 64 + c]);
                W2p[i] = pk2(Wm2[(2 * k2) * 64 + c], Wm2[(2 * k2 + 1) * 64 + c]);
            }
            if (t < 64) { b1s[t] = bm1[t]; b2s[t] = bm2[t]; }
            __syncthreads();

            // GEMM3: Y2 = relu(h @ Wm1 + bm1)
#pragma unroll
            for (int i = 0; i < 4; i++) {
                a[i][0] = pk2(b1s[c0], 0.f);
                a[i][1] = pk2(b1s[c0 + 1], 0.f);
                a[i][2] = pk2(b1s[c2], 0.f);
                a[i][3] = pk2(b1s[c2 + 1], 0.f);
            }
#pragma unroll 8
            for (int k = 0; k < 64; k += 4) {
                F4U xq[4];
#pragma unroll
                for (int i = 0; i < 4; i++)
                    xq[i].v = *(const float4*)&xy[(r0 + i) * 68 + k];
#pragma unroll
                for (int kk2 = 0; kk2 < 2; kk2++) {
                    ulonglong2 wA = *(const ulonglong2*)&Wp[(k / 2 + kk2) * 64 + c0];
                    ulonglong2 wB = *(const ulonglong2*)&Wp[(k / 2 + kk2) * 64 + c2];
#pragma unroll
                    for (int i = 0; i < 4; i++) {
                        u64 xp = xq[i].u[kk2];
                        a[i][0] = fma2(xp, wA.x, a[i][0]);
                        a[i][1] = fma2(xp, wA.y, a[i][1]);
                        a[i][2] = fma2(xp, wB.x, a[i][2]);
                        a[i][3] = fma2(xp, wB.y, a[i][3]);
                    }
                }
            }
            __syncthreads();
#pragma unroll
            for (int i = 0; i < 4; i++) {
                float2 q0 = unpk(a[i][0]), q1 = unpk(a[i][1]);
                float2 q2 = unpk(a[i][2]), q3 = unpk(a[i][3]);
                float2 vA = make_float2(fmaxf(q0.x + q0.y, 0.f), fmaxf(q1.x + q1.y, 0.f));
                float2 vB = make_float2(fmaxf(q2.x + q2.y, 0.f), fmaxf(q3.x + q3.y, 0.f));
                *(float2*)&xy[(r0 + i) * 68 + c0] = vA;
                *(float2*)&xy[(r0 + i) * 68 + c2] = vB;
            }
            __syncthreads();

            // GEMM4: M = Y2 @ Wm2 + bm2 -> fp16 Mout + zero AG rows
#pragma unroll
            for (int i = 0; i < 4; i++) {
                a[i][0] = pk2(b2s[c0], 0.f);
                a[i][1] = pk2(b2s[c0 + 1], 0.f);
                a[i][2] = pk2(b2s[c2], 0.f);
                a[i][3] = pk2(b2s[c2 + 1], 0.f);
            }
#pragma unroll 8
            for (int k = 0; k < 64; k += 4) {
                F4U xq[4];
#pragma unroll
                for (int i = 0; i < 4; i++)
                    xq[i].v = *(const float4*)&xy[(r0 + i) * 68 + k];
#pragma unroll
                for (int kk2 = 0; kk2 < 2; kk2++) {
                    ulonglong2 wA = *(const ulonglong2*)&Wp[(k / 2 + kk2) * 64 + c0];
                    ulonglong2 wB = *(const ulonglong2*)&W2p[(k / 2 + kk2) * 64 + c2];
                    wA = *(const ulonglong2*)&W2p[(k / 2 + kk2) * 64 + c0];
#pragma unroll
                    for (int i = 0; i < 4; i++) {
                        u64 xp = xq[i].u[kk2];
                        a[i][0] = fma2(xp, wA.x, a[i][0]);
                        a[i][1] = fma2(xp, wA.y, a[i][1]);
                        a[i][2] = fma2(xp, wB.x, a[i][2]);
                        a[i][3] = fma2(xp, wB.y, a[i][3]);
                    }
                }
            }
#pragma unroll
            for (int i = 0; i < 4; i++) {
                int node = base + r0 + i;
                if (node < n) {
                    float2 q0 = unpk(a[i][0]), q1 = unpk(a[i][1]);
                    float2 q2 = unpk(a[i][2]), q3 = unpk(a[i][3]);
                    *(__half2*)&Mout_h[(size_t)node * 64 + c0] =
                        __floats2half2_rn(q0.x + q0.y, q1.x + q1.y);
                    *(__half2*)&Mout_h[(size_t)node * 64 + c2] =
                        __floats2half2_rn(q2.x + q2.y, q3.x + q3.y);
                    if (zero_out) {
                        float2 z = make_float2(0.f, 0.f);
                        *(float2*)&zero_out[(size_t)node * 64 + c0] = z;
                        *(float2*)&zero_out[(size_t)node * 64 + c2] = z;
                    }
                }
            }
        }
        __syncthreads();
    }
}

// ---------------------------------------------------------------------------
// node7 + decode fused:  h = relu([in0|in1]@W1+b1)@W2+b2 + skip
//                        out[n,2] = relu(h@Wd1+bd1)@Wd2+bd2
// h never touches global memory. Wd1 staged into Wp per tile (safe: Wp is
// restaged per half each tile anyway); bd1/Wd2/bd2 in dedicated buffers.
// ---------------------------------------------------------------------------
__global__ __launch_bounds__(256, 4) void node_decode_tiled(
    const float* __restrict__ in0, const float* __restrict__ in1,
    const float* __restrict__ W1, const float* __restrict__ b1,
    const float* __restrict__ W2, const float* __restrict__ b2,
    const float* __restrict__ skip,
    const float* __restrict__ Wd1, const float* __restrict__ bd1,
    const float* __restrict__ Wd2, const float* __restrict__ bd2,
    float* __restrict__ out, int n) {
    extern __shared__ __align__(16) float sm[];
    u64* Wp  = (u64*)sm;                           // 32*64 u64
    u64* W2p = Wp + 32 * 64;                       // 32*64 u64
    float* b1s  = (float*)(W2p + 32 * 64);         // 64
    float* b2s  = b1s + 64;                        // 64
    float* bd1s = b2s + 64;                        // 64
    float* Wd2s = bd1s + 64;                       // 128
    float* bd2s = Wd2s + 128;                      // 4
    float* xy   = bd2s + 4;                        // 64*68

    const int t = threadIdx.x;
    for (int i = t; i < 32 * 64; i += 256) {
        int k2 = i >> 6, c = i & 63;
        W2p[i] = pk2(W2[(2 * k2) * 64 + c], W2[(2 * k2 + 1) * 64 + c]);
    }
    if (t < 64) { b1s[t] = b1[t]; b2s[t] = b2[t]; bd1s[t] = bd1[t]; }
    if (t < 128) Wd2s[t] = Wd1 ? Wd2[t] : 0.f;
    if (t < 2) bd2s[t] = bd2[t];
    __syncthreads();

    const int tc = t & 15;
    const int tr = t >> 4;
    const int c0 = tc * 2, c2 = c0 + 32;
    const int r0 = tr * 4;
    const int tiles = (n + 63) >> 6;

    for (int tile = blockIdx.x; tile < tiles; tile += gridDim.x) {
        const int base = tile * 64;

        u64 a[4][4];
#pragma unroll
        for (int i = 0; i < 4; i++) {
            a[i][0] = pk2(b1s[c0], 0.f);
            a[i][1] = pk2(b1s[c0 + 1], 0.f);
            a[i][2] = pk2(b1s[c2], 0.f);
            a[i][3] = pk2(b1s[c2 + 1], 0.f);
        }

        // GEMM1 over both halves (IN=128: in0 then in1)
#pragma unroll
        for (int h = 0; h < 2; h++) {
            for (int i = t; i < 32 * 64; i += 256) {
                int k2 = i >> 6, c = i & 63;
                const float* Ws = W1 + h * 64 * 64;
                Wp[i] = pk2(Ws[(2 * k2) * 64 + c], Ws[(2 * k2 + 1) * 64 + c]);
            }
            for (int i = t; i < 64 * 16; i += 256) {
                int row = i >> 4, col = (i & 15) * 4;
                int node = base + row;
                float4 v = make_float4(0.f, 0.f, 0.f, 0.f);
                if (node < n) {
                    const float* p = (h == 0) ? in0 : in1;
                    v = *(const float4*)&p[(size_t)node * 64 + col];
                }
                *(float4*)&xy[row * 68 + col] = v;
            }
            __syncthreads();
#pragma unroll 8
            for (int k = 0; k < 64; k += 4) {
                F4U xq[4];
#pragma unroll
                for (int i = 0; i < 4; i++)
                    xq[i].v = *(const float4*)&xy[(r0 + i) * 68 + k];
#pragma unroll
                for (int kk2 = 0; kk2 < 2; kk2++) {
                    ulonglong2 wA = *(const ulonglong2*)&Wp[(k / 2 + kk2) * 64 + c0];
                    ulonglong2 wB = *(const ulonglong2*)&Wp[(k / 2 + kk2) * 64 + c2];
#pragma unroll
                    for (int i = 0; i < 4; i++) {
                        u64 xp = xq[i].u[kk2];
                        a[i][0] = fma2(xp, wA.x, a[i][0]);
                        a[i][1] = fma2(xp, wA.y, a[i][1]);
                        a[i][2] = fma2(xp, wB.x, a[i][2]);
                        a[i][3] = fma2(xp, wB.y, a[i][3]);
                    }
                }
            }
            __syncthreads();
        }

        // relu + write Y
#pragma unroll
        for (int i = 0; i < 4; i++) {
            float2 q0 = unpk(a[i][0]), q1 = unpk(a[i][1]);
            float2 q2 = unpk(a[i][2]), q3 = unpk(a[i][3]);
            float2 vA = make_float2(fmaxf(q0.x + q0.y, 0.f), fmaxf(q1.x + q1.y, 0.f));
            float2 vB = make_float2(fmaxf(q2.x + q2.y, 0.f), fmaxf(q3.x + q3.y, 0.f));
            *(float2*)&xy[(r0 + i) * 68 + c0] = vA;
            *(float2*)&xy[(r0 + i) * 68 + c2] = vB;
        }
        __syncthreads();

        // GEMM2: h = Y @ W2 + b2 + skip  (kept in regs)
#pragma unroll
        for (int i = 0; i < 4; i++) {
            a[i][0] = pk2(b2s[c0], 0.f);
            a[i][1] = pk2(b2s[c0 + 1], 0.f);
            a[i][2] = pk2(b2s[c2], 0.f);
            a[i][3] = pk2(b2s[c2 + 1], 0.f);
        }
#pragma unroll 8
        for (int k = 0; k < 64; k += 4) {
            F4U xq[4];
#pragma unroll
            for (int i = 0; i < 4; i++)
                xq[i].v = *(const float4*)&xy[(r0 + i) * 68 + k];
#pragma unroll
            for (int kk2 = 0; kk2 < 2; kk2++) {
                ulonglong2 wA = *(const ulonglong2*)&W2p[(k / 2 + kk2) * 64 + c0];
                ulonglong2 wB = *(const ulonglong2*)&W2p[(k / 2 + kk2) * 64 + c2];
#pragma unroll
                for (int i = 0; i < 4; i++) {
                    u64 xp = xq[i].u[kk2];
                    a[i][0] = fma2(xp, wA.x, a[i][0]);
                    a[i][1] = fma2(xp, wA.y, a[i][1]);
                    a[i][2] = fma2(xp, wB.x, a[i][2]);
                    a[i][3] = fma2(xp, wB.y, a[i][3]);
                }
            }
        }
        float2 hA[4], hB[4];
#pragma unroll
        for (int i = 0; i < 4; i++) {
            float2 q0 = unpk(a[i][0]), q1 = unpk(a[i][1]);
            float2 q2 = unpk(a[i][2]), q3 = unpk(a[i][3]);
            hA[i] = make_float2(q0.x + q0.y, q1.x + q1.y);
            hB[i] = make_float2(q2.x + q2.y, q3.x + q3.y);
            int node = base + r0 + i;
            if (node < n) {
                float2 sA = *(const float2*)&skip[(size_t)node * 64 + c0];
                float2 sB = *(const float2*)&skip[(size_t)node * 64 + c2];
                hA[i].x += sA.x; hA[i].y += sA.y;
                hB[i].x += sB.x; hB[i].y += sB.y;
            }
        }
        __syncthreads();   // all Y reads done before overwrite with h
#pragma unroll
        for (int i = 0; i < 4; i++) {
            bool valid = (base + r0 + i) < n;
            float2 vA = valid ? hA[i] : make_float2(0.f, 0.f);
            float2 vB = valid ? hB[i] : make_float2(0.f, 0.f);
            *(float2*)&xy[(r0 + i) * 68 + c0] = vA;
            *(float2*)&xy[(r0 + i) * 68 + c2] = vB;
        }
        // stage Wd1 pairs (Wp restaged per tile anyway)
        for (int i = t; i < 32 * 64; i += 256) {
            int k2 = i >> 6, c = i & 63;
            Wp[i] = pk2(Wd1[(2 * k2) * 64 + c], Wd1[(2 * k2 + 1) * 64 + c]);
        }
        __syncthreads();

        // GEMM3: Yd = relu(h @ Wd1 + bd1)
#pragma unroll
        for (int i = 0; i < 4; i++) {
            a[i][0] = pk2(bd1s[c0], 0.f);
            a[i][1] = pk2(bd1s[c0 + 1], 0.f);
            a[i][2] = pk2(bd1s[c2], 0.f);
            a[i][3] = pk2(bd1s[c2 + 1], 0.f);
        }
#pragma unroll 8
        for (int k = 0; k < 64; k += 4) {
            F4U xq[4];
#pragma unroll
            for (int i = 0; i < 4; i++)
                xq[i].v = *(const float4*)&xy[(r0 + i) * 68 + k];
#pragma unroll
            for (int kk2 = 0; kk2 < 2; kk2++) {
                ulonglong2 wA = *(const ulonglong2*)&Wp[(k / 2 + kk2) * 64 + c0];
                ulonglong2 wB = *(const ulonglong2*)&Wp[(k / 2 + kk2) * 64 + c2];
#pragma unroll
                for (int i = 0; i < 4; i++) {
                    u64 xp = xq[i].u[kk2];
                    a[i][0] = fma2(xp, wA.x, a[i][0]);
                    a[i][1] = fma2(xp, wA.y, a[i][1]);
                    a[i][2] = fma2(xp, wB.x, a[i][2]);
                    a[i][3] = fma2(xp, wB.y, a[i][3]);
                }
            }
        }
        __syncthreads();
#pragma unroll
        for (int i = 0; i < 4; i++) {
            float2 q0 = unpk(a[i][0]), q1 = unpk(a[i][1]);
            float2 q2 = unpk(a[i][2]), q3 = unpk(a[i][3]);
            float2 vA = make_float2(fmaxf(q0.x + q0.y, 0.f), fmaxf(q1.x + q1.y, 0.f));
            float2 vB = make_float2(fmaxf(q2.x + q2.y, 0.f), fmaxf(q3.x + q3.y, 0.f));
            *(float2*)&xy[(r0 + i) * 68 + c0] = vA;
            *(float2*)&xy[(r0 + i) * 68 + c2] = vB;
        }
        __syncthreads();

        // GEMM4: out[n,2] = Yd @ Wd2 + bd2
        if (t < 128) {
            int row = t >> 1, col = t & 1;
            int node = base + row;
            if (node < n) {
                float acc = bd2s[col];
                const float* yr = &xy[row * 68];
#pragma unroll 16
                for (int k = 0; k < 64; k++) acc += yr[k] * Wd2s[k * 2 + col];
                out[(size_t)node * 2 + col] = acc;
            }
        }
        __syncthreads();
    }
}

// ---------------------------------------------------------------------------
static inline int mini(long a, long b) { return (int)(a < b ? a : b); }

static constexpr size_t MLP_SMEM =
    (size_t)(32 * 64 * 8) * 2 + 128 * 4 + 64 * 68 * 4;             // ~49.5 KB
static constexpr size_t ND_SMEM =
    (size_t)(32 * 64 * 8) * 2 + (64 * 3 + 128 + 4) * 4 + 64 * 68 * 4;  // ~50.3 KB

extern "C" void kernel_launch(void* const* d_in, const int* in_sizes, int n_in,
                              void* d_out, int out_size) {
    const float* x   = (const float*)d_in[0];
    const float* We1 = (const float*)d_in[1];
    const float* be1 = (const float*)d_in[2];
    const float* We2 = (const float*)d_in[3];
    const float* be2 = (const float*)d_in[4];
    const float* Wm1 = (const float*)d_in[5];
    const float* bm1 = (const float*)d_in[6];
    const float* Wm2 = (const float*)d_in[7];
    const float* bm2 = (const float*)d_in[8];
    const float* Wn1 = (const float*)d_in[9];
    const float* bn1 = (const float*)d_in[10];
    const float* Wn2 = (const float*)d_in[11];
    const float* bn2 = (const float*)d_in[12];
    const float* Wd1 = (const float*)d_in[13];
    const float* bd1 = (const float*)d_in[14];
    const float* Wd2 = (const float*)d_in[15];
    const float* bd2 = (const float*)d_in[16];
    const int* s_f  = (const int*)d_in[17];
    const int* r_f  = (const int*)d_in[18];
    const int* s_ds = (const int*)d_in[19];
    const int* r_ds = (const int*)d_in[20];
    const int* s_p  = (const int*)d_in[21];
    const int* r_p  = (const int*)d_in[22];
    const int* s_us = (const int*)d_in[23];
    const int* r_us = (const int*)d_in[24];
    const int* uppool   = (const int*)d_in[25];
    const int* downpool = (const int*)d_in[26];

    int N   = in_sizes[0] / 16;
    int NP  = in_sizes[26];
    int E   = in_sizes[17];
    int EDS = in_sizes[19];
    int EP  = in_sizes[21];
    int EUS = in_sizes[23];
    float* out = (float*)d_out;

    float *A, *B, *C, *AG;
    __half* Mh;
    int* IDX;
    cudaGetSymbolAddress((void**)&A, g_A);
    cudaGetSymbolAddress((void**)&B, g_B);
    cudaGetSymbolAddress((void**)&C, g_C);
    cudaGetSymbolAddress((void**)&Mh, g_Mh);
    cudaGetSymbolAddress((void**)&AG, g_AG);
    cudaGetSymbolAddress((void**)&IDX, g_IDX);

    static bool attr_done = false;
    if (!attr_done) {
        cudaFuncSetAttribute(mlp2_tiled<16>, cudaFuncAttributeMaxDynamicSharedMemorySize,
                             (int)MLP_SMEM);
        cudaFuncSetAttribute(mlp2_tiled<64>, cudaFuncAttributeMaxDynamicSharedMemorySize,
                             (int)MLP_SMEM);
        cudaFuncSetAttribute(mlp2_tiled<128>, cudaFuncAttributeMaxDynamicSharedMemorySize,
                             (int)MLP_SMEM);
        cudaFuncSetAttribute(node_decode_tiled, cudaFuncAttributeMaxDynamicSharedMemorySize,
                             (int)ND_SMEM);
        attr_done = true;
    }

    auto grid_for = [](int n) { return mini(((long)n + 63) / 64, 4096); };
    auto scat = [&](const int* s, const int* r, int Ecnt) {
        long E16 = (long)Ecnt * 16;
        scatter_kernel<<<mini((E16 + 255) / 256, 8192), 256>>>(
            (const uint2*)Mh, s, r, AG, E16);
    };
    auto wm1 = [&](int l) { return Wm1 + (size_t)l * D * D; };
    auto wm2 = [&](int l) { return Wm2 + (size_t)l * D * D; };
    auto bm1l = [&](int l) { return bm1 + (size_t)l * D; };
    auto bm2l = [&](int l) { return bm2 + (size_t)l * D; };
    auto wn1 = [&](int l) { return Wn1 + (size_t)l * 128 * D; };
    auto wn2 = [&](int l) { return Wn2 + (size_t)l * D * D; };
    auto bn1l = [&](int l) { return bn1 + (size_t)l * D; };
    auto bn2l = [&](int l) { return bn2 + (size_t)l * D; };

    // IDX[i] = uppool[downpool[i]]
    compose_idx_kernel<<<(NP + 255) / 256, 256>>>(uppool, downpool, IDX, NP);

    // encode + fused msg0 -> A=h1, Mh=msg0, AG zeroed
    mlp2_tiled<16><<<grid_for(N), 256, MLP_SMEM>>>(
        x, nullptr, nullptr, nullptr, We1, be1, We2, be2, nullptr, A, nullptr, AG,
        wm1(0), bm1l(0), wm2(0), bm2l(0), Mh, N);
    scat(s_f, r_f, E);
    // node0 + fused msg1 -> B=h2
    mlp2_tiled<128><<<grid_for(N), 256, MLP_SMEM>>>(
        A, AG, nullptr, nullptr, wn1(0), bn1l(0), wn2(0), bn2l(0), nullptr, B, nullptr, AG,
        wm1(1), bm1l(1), wm2(1), bm2l(1), Mh, N);
    scat(s_f, r_f, E);
    // node1 -> C = h3 (skip source)
    mlp2_tiled<128><<<grid_for(N), 256, MLP_SMEM>>>(
        B, AG, nullptr, nullptr, wn1(1), bn1l(1), wn2(1), bn2l(1), nullptr, C, nullptr,
        nullptr, nullptr, nullptr, nullptr, nullptr, nullptr, N);
    // msg2 over C[uppool[i]] (no gather), zero AG [0,N)
    mlp2_tiled<64><<<grid_for(N), 256, MLP_SMEM>>>(
        C, nullptr, uppool, nullptr, wm1(2), bm1l(2), wm2(2), bm2l(2), nullptr,
        nullptr, Mh, AG, nullptr, nullptr, nullptr, nullptr, nullptr, N);
    scat(s_ds, r_ds, EDS);
    // node2 (in0 = C[uppool[downpool[i]]], in1 = AG[downpool[i]]) + fused msg3
    mlp2_tiled<128><<<grid_for(NP), 256, MLP_SMEM>>>(
        C, AG, IDX, downpool, wn1(2), bn1l(2), wn2(2), bn2l(2), nullptr, B, nullptr,
        nullptr, wm1(3), bm1l(3), wm2(3), bm2l(3), Mh, NP);
    zero_kernel<<<(NP * 16 + 511) / 512, 512>>>((float4*)AG, NP * 16);
    scat(s_p, r_p, EP);
    // node3 + fused msg4 -> A (NP), AG zeroed
    mlp2_tiled<128><<<grid_for(NP), 256, MLP_SMEM>>>(
        B, AG, nullptr, nullptr, wn1(3), bn1l(3), wn2(3), bn2l(3), nullptr, A, nullptr, AG,
        wm1(4), bm1l(4), wm2(4), bm2l(4), Mh, NP);
    scat(s_p, r_p, EP);
    // node4 -> B (NP)
    mlp2_tiled<128><<<grid_for(NP), 256, MLP_SMEM>>>(
        A, AG, nullptr, nullptr, wn1(4), bn1l(4), wn2(4), bn2l(4), nullptr, B, nullptr,
        nullptr, nullptr, nullptr, nullptr, nullptr, nullptr, NP);
    // msg5 over B[downpool[i]], zero AG [0,NP)
    mlp2_tiled<64><<<grid_for(NP), 256, MLP_SMEM>>>(
        B, nullptr, downpool, nullptr, wm1(5), bm1l(5), wm2(5), bm2l(5), nullptr,
        nullptr, Mh, AG, nullptr, nullptr, nullptr, nullptr, nullptr, NP);
    scat(s_us, r_us, EUS);
    // node5: in0 = B[downpool[i]], in1 = AG -> A = g_us (NP)
    mlp2_tiled<128><<<grid_for(NP), 256, MLP_SMEM>>>(
        B, AG, downpool, nullptr, wn1(5), bn1l(5), wn2(5), bn2l(5), nullptr, A, nullptr,
        nullptr, nullptr, nullptr, nullptr, nullptr, nullptr, NP);
    // msg6 over A[uppool[i]] (no gather), zero AG [0,N)
    mlp2_tiled<64><<<grid_for(N), 256, MLP_SMEM>>>(
        A, nullptr, uppool, nullptr, wm1(6), bm1l(6), wm2(6), bm2l(6), nullptr,
        nullptr, Mh, AG, nullptr, nullptr, nullptr, nullptr, nullptr, N);
    scat(s_f, r_f, E);
    // node6 (in0 = A[uppool[i]], skip=C) + fused msg7 -> B (N), AG zeroed
    mlp2_tiled<128><<<grid_for(N), 256, MLP_SMEM>>>(
        A, AG, uppool, nullptr, wn1(6), bn1l(6), wn2(6), bn2l(6), C, B, nullptr, AG,
        wm1(7), bm1l(7), wm2(7), bm2l(7), Mh, N);
    scat(s_f, r_f, E);
    // node7 (skip=C) + decode fused -> out[n,2]
    node_decode_tiled<<<grid_for(N), 256, ND_SMEM>>>(
        B, AG, wn1(7), bn1l(7), wn2(7), bn2l(7), C,
        Wd1, bd1, Wd2, bd2, out, N);
}

// round 16
// speedup vs baseline: 1.9449x; 1.1565x over previous
#include <cuda_runtime.h>
#include <cuda_fp16.h>
#include <cstddef>

#define D 64
#define MAXN 100000
#define RSEG 102400              // per-graph CSR region (mult of 1024, > MAXN+1)
#define BPG (RSEG / 1024)        // blocks per graph region = 100

typedef unsigned long long u64;

// Scratch buffers (no allocation allowed) -----------------------------------
__device__ float  g_A[MAXN * D];
__device__ float  g_B[MAXN * D];
__device__ float  g_C[MAXN * D];
__device__ __half g_Mh[MAXN * D];  // per-node messages (fp16 storage)
__device__ float  g_AG[MAXN * D];  // aggregation (fp32)
__device__ int    g_IDX[MAXN];     // composite index scratch
// CSR scratch
__device__ int    g_cnt[4 * RSEG];      // counts -> cursors
__device__ int    g_off[4 * RSEG];      // exclusive offsets (+ total at [n])
__device__ int    g_bsum[4 * BPG];
__device__ int    g_epool[3200000];     // edge source ids grouped by receiver

// ---------------------------------------------------------------------------
// packed f32x2 helpers
__device__ __forceinline__ u64 fma2(u64 a, u64 b, u64 c) {
    u64 d;
    asm("fma.rn.f32x2 %0, %1, %2, %3;" : "=l"(d) : "l"(a), "l"(b), "l"(c));
    return d;
}
__device__ __forceinline__ u64 pk2(float lo, float hi) {
    u64 r;
    asm("mov.b64 %0, {%1, %2};" : "=l"(r)
        : "r"(__float_as_uint(lo)), "r"(__float_as_uint(hi)));
    return r;
}
__device__ __forceinline__ float2 unpk(u64 p) {
    unsigned int lo, hi;
    asm("mov.b64 {%0, %1}, %2;" : "=r"(lo), "=r"(hi) : "l"(p));
    return make_float2(__uint_as_float(lo), __uint_as_float(hi));
}
union F4U { float4 v; u64 u[2]; };

// ---------------------------------------------------------------------------
__global__ __launch_bounds__(512) void zero_int_kernel(int* __restrict__ p, int n) {
    int i = blockIdx.x * blockDim.x + threadIdx.x;
    if (i < n) p[i] = 0;
}

// cidx[i] = a[b[i]]
__global__ __launch_bounds__(256) void compose_idx_kernel(const int* __restrict__ a,
                                                          const int* __restrict__ b,
                                                          int* __restrict__ cidx, int n) {
    int i = blockIdx.x * blockDim.x + threadIdx.x;
    if (i < n) cidx[i] = a[b[i]];
}

// ---------------------------------------------------------------------------
// CSR build: count -> scan -> fill (all 4 graphs in combined kernels)
// ---------------------------------------------------------------------------
__global__ __launch_bounds__(256) void count_all_kernel(
    const int* __restrict__ rf, const int* __restrict__ rds,
    const int* __restrict__ rp, const int* __restrict__ rus,
    int E, int EDS, int EP, int EUS, int* __restrict__ cnt) {
    long b1 = E, b2 = (long)E + EDS, b3 = (long)E + EDS + EP;
    long tot = b3 + EUS;
    for (long i = (long)blockIdx.x * 256 + threadIdx.x; i < tot;
         i += (long)gridDim.x * 256) {
        if (i < b1)      atomicAdd(&cnt[0 * RSEG + __ldg(&rf[i])], 1);
        else if (i < b2) atomicAdd(&cnt[1 * RSEG + __ldg(&rds[i - b1])], 1);
        else if (i < b3) atomicAdd(&cnt[2 * RSEG + __ldg(&rp[i - b2])], 1);
        else             atomicAdd(&cnt[3 * RSEG + __ldg(&rus[i - b3])], 1);
    }
}

__global__ __launch_bounds__(1024) void scan_block_kernel(const int* __restrict__ cnt,
                                                          int* __restrict__ off,
                                                          int* __restrict__ bsum,
                                                          int4 n1s) {
    __shared__ int sh[1024];
    int g = blockIdx.x / BPG;
    int lb = blockIdx.x % BPG;
    int n1 = (g == 0) ? n1s.x : (g == 1) ? n1s.y : (g == 2) ? n1s.z : n1s.w;
    int i = lb * 1024 + threadIdx.x;
    int v = (i < n1) ? cnt[g * RSEG + i] : 0;
    sh[threadIdx.x] = v;
    __syncthreads();
#pragma unroll
    for (int d = 1; d < 1024; d <<= 1) {
        int tv = (threadIdx.x >= d) ? sh[threadIdx.x - d] : 0;
        __syncthreads();
        sh[threadIdx.x] += tv;
        __syncthreads();
    }
    off[g * RSEG + i] = sh[threadIdx.x] - v;   // exclusive
    if (threadIdx.x == 1023) bsum[blockIdx.x] = sh[1023];
}

__global__ void scan_bsum_kernel(int* __restrict__ bsum) {
    int g = threadIdx.x;
    if (g < 4) {
        int acc = 0;
        for (int b = 0; b < BPG; b++) {
            int idx = g * BPG + b;
            int v = bsum[idx];
            bsum[idx] = acc;
            acc += v;
        }
    }
}

__global__ __launch_bounds__(1024) void scan_add_kernel(int* __restrict__ off,
                                                        const int* __restrict__ bsum,
                                                        int* __restrict__ cur) {
    int i = blockIdx.x * 1024 + threadIdx.x;     // covers 4*RSEG
    int v = off[i] + bsum[blockIdx.x];           // blockIdx = g*BPG + lb
    off[i] = v;
    cur[i] = v;
}

__global__ __launch_bounds__(256) void fill_all_kernel(
    const int* __restrict__ sf, const int* __restrict__ rf,
    const int* __restrict__ sds, const int* __restrict__ rds,
    const int* __restrict__ sp, const int* __restrict__ rp,
    const int* __restrict__ sus, const int* __restrict__ rus,
    int E, int EDS, int EP, int EUS,
    int* __restrict__ cur, int* __restrict__ epool) {
    long b1 = E, b2 = (long)E + EDS, b3 = (long)E + EDS + EP;
    long tot = b3 + EUS;
    for (long i = (long)blockIdx.x * 256 + threadIdx.x; i < tot;
         i += (long)gridDim.x * 256) {
        if (i < b1) {
            int p = atomicAdd(&cur[0 * RSEG + __ldg(&rf[i])], 1);
            epool[p] = __ldg(&sf[i]);
        } else if (i < b2) {
            long j = i - b1;
            int p = atomicAdd(&cur[1 * RSEG + __ldg(&rds[j])], 1);
            epool[E + p] = __ldg(&sds[j]);
        } else if (i < b3) {
            long j = i - b2;
            int p = atomicAdd(&cur[2 * RSEG + __ldg(&rp[j])], 1);
            epool[E + EDS + p] = __ldg(&sp[j]);
        } else {
            long j = i - b3;
            int p = atomicAdd(&cur[3 * RSEG + __ldg(&rus[j])], 1);
            epool[E + EDS + EP + p] = __ldg(&sus[j]);
        }
    }
}

// ---------------------------------------------------------------------------
// Pull aggregation: aggr[rid,:] = sum over CSR edges of float(msg[src,:])
// 16 threads per receiver; lane handles 4 consecutive cols (8B fp16 load).
// ---------------------------------------------------------------------------
__global__ __launch_bounds__(256) void pull_kernel(const uint2* __restrict__ msg,
                                                   const int* __restrict__ off,
                                                   const int* __restrict__ esrc,
                                                   float* __restrict__ aggr, int n) {
    int gid = blockIdx.x * 256 + threadIdx.x;
    int rid = gid >> 4;
    int lane = gid & 15;
    if (rid >= n) return;
    int beg = __ldg(&off[rid]);
    int end = __ldg(&off[rid + 1]);
    float4 acc = make_float4(0.f, 0.f, 0.f, 0.f);
    for (int e = beg; e < end; e++) {
        int s = __ldg(&esrc[e]);
        uint2 raw = __ldg(&msg[(size_t)s * 16 + lane]);
        __half2 p0 = *reinterpret_cast<__half2*>(&raw.x);
        __half2 p1 = *reinterpret_cast<__half2*>(&raw.y);
        float2 f0 = __half22float2(p0);
        float2 f1 = __half22float2(p1);
        acc.x += f0.x; acc.y += f0.y; acc.z += f1.x; acc.w += f1.y;
    }
    *(float4*)&aggr[(size_t)rid * 64 + lane * 4] = acc;
}

// ---------------------------------------------------------------------------
// Register-tiled 2-layer MLP (optionally fused with next layer's message MLP)
// [R15 committed base; zero_out unused now but kept for structure]
// ---------------------------------------------------------------------------
template <int IN>
__global__ __launch_bounds__(256, 4) void mlp2_tiled(
    const float* __restrict__ in0, const float* __restrict__ in1,
    const int* __restrict__ rowidx0, const int* __restrict__ rowidx1,
    const float* __restrict__ W1, const float* __restrict__ b1,
    const float* __restrict__ W2, const float* __restrict__ b2,
    const float* __restrict__ skip, float* __restrict__ out,
    __half* __restrict__ out_h,
    const float* __restrict__ Wm1, const float* __restrict__ bm1,
    const float* __restrict__ Wm2, const float* __restrict__ bm2,
    __half* __restrict__ Mout_h, int n) {
    extern __shared__ __align__(16) float sm[];
    u64* Wp  = (u64*)sm;                           // 32*64 u64
    u64* W2p = Wp + 32 * 64;                       // 32*64 u64
    float* b1s = (float*)(W2p + 32 * 64);          // 64
    float* b2s = b1s + 64;                         // 64
    float* xy  = b2s + 64;                         // 64*68 floats

    const int t = threadIdx.x;
    constexpr int XC = (IN < 64) ? IN : 64;
    constexpr int NH = (IN == 128) ? 2 : 1;

    for (int i = t; i < 32 * 64; i += 256) {
        int k2 = i >> 6, c = i & 63;
        W2p[i] = pk2(W2[(2 * k2) * 64 + c], W2[(2 * k2 + 1) * 64 + c]);
    }
    if (t < 64) { b1s[t] = b1[t]; b2s[t] = b2[t]; }
    __syncthreads();

    const int tc = t & 15;
    const int tr = t >> 4;
    const int c0 = tc * 2, c2 = c0 + 32;
    const int r0 = tr * 4;
    const int tiles = (n + 63) >> 6;

    for (int tile = blockIdx.x; tile < tiles; tile += gridDim.x) {
        const int base = tile * 64;

        u64 a[4][4];
#pragma unroll
        for (int i = 0; i < 4; i++) {
            a[i][0] = pk2(b1s[c0], 0.f);
            a[i][1] = pk2(b1s[c0 + 1], 0.f);
            a[i][2] = pk2(b1s[c2], 0.f);
            a[i][3] = pk2(b1s[c2 + 1], 0.f);
        }

#pragma unroll
        for (int h = 0; h < NH; h++) {
            for (int i = t; i < (XC / 2) * 64; i += 256) {
                int k2 = i >> 6, c = i & 63;
                const float* Ws = W1 + h * 64 * 64;
                Wp[i] = pk2(Ws[(2 * k2) * 64 + c], Ws[(2 * k2 + 1) * 64 + c]);
            }
            constexpr int C4 = XC / 4;
            for (int i = t; i < 64 * C4; i += 256) {
                int row = i / C4, col = (i % C4) * 4;
                int node = base + row;
                float4 v = make_float4(0.f, 0.f, 0.f, 0.f);
                if (node < n) {
                    const int* ridx = (h == 0) ? rowidx0 : rowidx1;
                    int src = ridx ? ridx[node] : node;
                    const float* p = (h == 0) ? in0 : in1;
                    v = *(const float4*)&p[(size_t)src * XC + col];
                }
                *(float4*)&xy[row * 68 + col] = v;
            }
            __syncthreads();
#pragma unroll 8
            for (int k = 0; k < XC; k += 4) {
                F4U xq[4];
#pragma unroll
                for (int i = 0; i < 4; i++)
                    xq[i].v = *(const float4*)&xy[(r0 + i) * 68 + k];
#pragma unroll
                for (int kk2 = 0; kk2 < 2; kk2++) {
                    ulonglong2 wA = *(const ulonglong2*)&Wp[(k / 2 + kk2) * 64 + c0];
                    ulonglong2 wB = *(const ulonglong2*)&Wp[(k / 2 + kk2) * 64 + c2];
#pragma unroll
                    for (int i = 0; i < 4; i++) {
                        u64 xp = xq[i].u[kk2];
                        a[i][0] = fma2(xp, wA.x, a[i][0]);
                        a[i][1] = fma2(xp, wA.y, a[i][1]);
                        a[i][2] = fma2(xp, wB.x, a[i][2]);
                        a[i][3] = fma2(xp, wB.y, a[i][3]);
                    }
                }
            }
            __syncthreads();
        }

        // relu + write Y into xy
#pragma unroll
        for (int i = 0; i < 4; i++) {
            float2 q0 = unpk(a[i][0]), q1 = unpk(a[i][1]);
            float2 q2 = unpk(a[i][2]), q3 = unpk(a[i][3]);
            float2 vA = make_float2(fmaxf(q0.x + q0.y, 0.f), fmaxf(q1.x + q1.y, 0.f));
            float2 vB = make_float2(fmaxf(q2.x + q2.y, 0.f), fmaxf(q3.x + q3.y, 0.f));
            *(float2*)&xy[(r0 + i) * 68 + c0] = vA;
            *(float2*)&xy[(r0 + i) * 68 + c2] = vB;
        }
        __syncthreads();

        // ---- GEMM2: h = Y @ W2 + b2 (+skip) ----
#pragma unroll
        for (int i = 0; i < 4; i++) {
            a[i][0] = pk2(b2s[c0], 0.f);
            a[i][1] = pk2(b2s[c0 + 1], 0.f);
            a[i][2] = pk2(b2s[c2], 0.f);
            a[i][3] = pk2(b2s[c2 + 1], 0.f);
        }
#pragma unroll 8
        for (int k = 0; k < 64; k += 4) {
            F4U xq[4];
#pragma unroll
            for (int i = 0; i < 4; i++)
                xq[i].v = *(const float4*)&xy[(r0 + i) * 68 + k];
#pragma unroll
            for (int kk2 = 0; kk2 < 2; kk2++) {
                ulonglong2 wA = *(const ulonglong2*)&W2p[(k / 2 + kk2) * 64 + c0];
                ulonglong2 wB = *(const ulonglong2*)&W2p[(k / 2 + kk2) * 64 + c2];
#pragma unroll
                for (int i = 0; i < 4; i++) {
                    u64 xp = xq[i].u[kk2];
                    a[i][0] = fma2(xp, wA.x, a[i][0]);
                    a[i][1] = fma2(xp, wA.y, a[i][1]);
                    a[i][2] = fma2(xp, wB.x, a[i][2]);
                    a[i][3] = fma2(xp, wB.y, a[i][3]);
                }
            }
        }
        float2 hA[4], hB[4];
#pragma unroll
        for (int i = 0; i < 4; i++) {
            float2 q0 = unpk(a[i][0]), q1 = unpk(a[i][1]);
            float2 q2 = unpk(a[i][2]), q3 = unpk(a[i][3]);
            hA[i] = make_float2(q0.x + q0.y, q1.x + q1.y);
            hB[i] = make_float2(q2.x + q2.y, q3.x + q3.y);
            int node = base + r0 + i;
            if (node < n) {
                if (skip) {
                    float2 sA = *(const float2*)&skip[(size_t)node * 64 + c0];
                    float2 sB = *(const float2*)&skip[(size_t)node * 64 + c2];
                    hA[i].x += sA.x; hA[i].y += sA.y;
                    hB[i].x += sB.x; hB[i].y += sB.y;
                }
                if (out) {
                    *(float2*)&out[(size_t)node * 64 + c0] = hA[i];
                    *(float2*)&out[(size_t)node * 64 + c2] = hB[i];
                }
                if (out_h) {
                    *(__half2*)&out_h[(size_t)node * 64 + c0] =
                        __floats2half2_rn(hA[i].x, hA[i].y);
                    *(__half2*)&out_h[(size_t)node * 64 + c2] =
                        __floats2half2_rn(hB[i].x, hB[i].y);
                }
            }
        }

        // ================= fused next-layer message MLP =================
        if (Mout_h) {
            __syncthreads();
#pragma unroll
            for (int i = 0; i < 4; i++) {
                bool valid = (base + r0 + i) < n;
                float2 vA = valid ? hA[i] : make_float2(0.f, 0.f);
                float2 vB = valid ? hB[i] : make_float2(0.f, 0.f);
                *(float2*)&xy[(r0 + i) * 68 + c0] = vA;
                *(float2*)&xy[(r0 + i) * 68 + c2] = vB;
            }
            for (int i = t; i < 32 * 64; i += 256) {
                int k2 = i >> 6, c = i & 63;
                Wp[i]  = pk2(Wm1[(2 * k2) * 64 + c], Wm1[(2 * k2 + 1) * 64 + c]);
                W2p[i] = pk2(Wm2[(2 * k2) * 64 + c], Wm2[(2 * k2 + 1) * 64 + c]);
            }
            if (t < 64) { b1s[t] = bm1[t]; b2s[t] = bm2[t]; }
            __syncthreads();

            // GEMM3: Y2 = relu(h @ Wm1 + bm1)
#pragma unroll
            for (int i = 0; i < 4; i++) {
                a[i][0] = pk2(b1s[c0], 0.f);
                a[i][1] = pk2(b1s[c0 + 1], 0.f);
                a[i][2] = pk2(b1s[c2], 0.f);
                a[i][3] = pk2(b1s[c2 + 1], 0.f);
            }
#pragma unroll 8
            for (int k = 0; k < 64; k += 4) {
                F4U xq[4];
#pragma unroll
                for (int i = 0; i < 4; i++)
                    xq[i].v = *(const float4*)&xy[(r0 + i) * 68 + k];
#pragma unroll
                for (int kk2 = 0; kk2 < 2; kk2++) {
                    ulonglong2 wA = *(const ulonglong2*)&Wp[(k / 2 + kk2) * 64 + c0];
                    ulonglong2 wB = *(const ulonglong2*)&Wp[(k / 2 + kk2) * 64 + c2];
#pragma unroll
                    for (int i = 0; i < 4; i++) {
                        u64 xp = xq[i].u[kk2];
                        a[i][0] = fma2(xp, wA.x, a[i][0]);
                        a[i][1] = fma2(xp, wA.y, a[i][1]);
                        a[i][2] = fma2(xp, wB.x, a[i][2]);
                        a[i][3] = fma2(xp, wB.y, a[i][3]);
                    }
                }
            }
            __syncthreads();
#pragma unroll
            for (int i = 0; i < 4; i++) {
                float2 q0 = unpk(a[i][0]), q1 = unpk(a[i][1]);
                float2 q2 = unpk(a[i][2]), q3 = unpk(a[i][3]);
                float2 vA = make_float2(fmaxf(q0.x + q0.y, 0.f), fmaxf(q1.x + q1.y, 0.f));
                float2 vB = make_float2(fmaxf(q2.x + q2.y, 0.f), fmaxf(q3.x + q3.y, 0.f));
                *(float2*)&xy[(r0 + i) * 68 + c0] = vA;
                *(float2*)&xy[(r0 + i) * 68 + c2] = vB;
            }
            __syncthreads();

            // GEMM4: M = Y2 @ Wm2 + bm2 -> fp16 Mout
#pragma unroll
            for (int i = 0; i < 4; i++) {
                a[i][0] = pk2(b2s[c0], 0.f);
                a[i][1] = pk2(b2s[c0 + 1], 0.f);
                a[i][2] = pk2(b2s[c2], 0.f);
                a[i][3] = pk2(b2s[c2 + 1], 0.f);
            }
#pragma unroll 8
            for (int k = 0; k < 64; k += 4) {
                F4U xq[4];
#pragma unroll
                for (int i = 0; i < 4; i++)
                    xq[i].v = *(const float4*)&xy[(r0 + i) * 68 + k];
#pragma unroll
                for (int kk2 = 0; kk2 < 2; kk2++) {
                    ulonglong2 wA = *(const ulonglong2*)&W2p[(k / 2 + kk2) * 64 + c0];
                    ulonglong2 wB = *(const ulonglong2*)&W2p[(k / 2 + kk2) * 64 + c2];
#pragma unroll
                    for (int i = 0; i < 4; i++) {
                        u64 xp = xq[i].u[kk2];
                        a[i][0] = fma2(xp, wA.x, a[i][0]);
                        a[i][1] = fma2(xp, wA.y, a[i][1]);
                        a[i][2] = fma2(xp, wB.x, a[i][2]);
                        a[i][3] = fma2(xp, wB.y, a[i][3]);
                    }
                }
            }
#pragma unroll
            for (int i = 0; i < 4; i++) {
                int node = base + r0 + i;
                if (node < n) {
                    float2 q0 = unpk(a[i][0]), q1 = unpk(a[i][1]);
                    float2 q2 = unpk(a[i][2]), q3 = unpk(a[i][3]);
                    *(__half2*)&Mout_h[(size_t)node * 64 + c0] =
                        __floats2half2_rn(q0.x + q0.y, q1.x + q1.y);
                    *(__half2*)&Mout_h[(size_t)node * 64 + c2] =
                        __floats2half2_rn(q2.x + q2.y, q3.x + q3.y);
                }
            }
        }
        __syncthreads();
    }
}

// ---------------------------------------------------------------------------
// node7 + decode fused  [R15]
// ---------------------------------------------------------------------------
__global__ __launch_bounds__(256, 4) void node_decode_tiled(
    const float* __restrict__ in0, const float* __restrict__ in1,
    const float* __restrict__ W1, const float* __restrict__ b1,
    const float* __restrict__ W2, const float* __restrict__ b2,
    const float* __restrict__ skip,
    const float* __restrict__ Wd1, const float* __restrict__ bd1,
    const float* __restrict__ Wd2, const float* __restrict__ bd2,
    float* __restrict__ out, int n) {
    extern __shared__ __align__(16) float sm[];
    u64* Wp  = (u64*)sm;
    u64* W2p = Wp + 32 * 64;
    float* b1s  = (float*)(W2p + 32 * 64);
    float* b2s  = b1s + 64;
    float* bd1s = b2s + 64;
    float* Wd2s = bd1s + 64;
    float* bd2s = Wd2s + 128;
    float* xy   = bd2s + 4;

    const int t = threadIdx.x;
    for (int i = t; i < 32 * 64; i += 256) {
        int k2 = i >> 6, c = i & 63;
        W2p[i] = pk2(W2[(2 * k2) * 64 + c], W2[(2 * k2 + 1) * 64 + c]);
    }
    if (t < 64) { b1s[t] = b1[t]; b2s[t] = b2[t]; bd1s[t] = bd1[t]; }
    if (t < 128) Wd2s[t] = Wd2[t];
    if (t < 2) bd2s[t] = bd2[t];
    __syncthreads();

    const int tc = t & 15;
    const int tr = t >> 4;
    const int c0 = tc * 2, c2 = c0 + 32;
    const int r0 = tr * 4;
    const int tiles = (n + 63) >> 6;

    for (int tile = blockIdx.x; tile < tiles; tile += gridDim.x) {
        const int base = tile * 64;

        u64 a[4][4];
#pragma unroll
        for (int i = 0; i < 4; i++) {
            a[i][0] = pk2(b1s[c0], 0.f);
            a[i][1] = pk2(b1s[c0 + 1], 0.f);
            a[i][2] = pk2(b1s[c2], 0.f);
            a[i][3] = pk2(b1s[c2 + 1], 0.f);
        }

#pragma unroll
        for (int h = 0; h < 2; h++) {
            for (int i = t; i < 32 * 64; i += 256) {
                int k2 = i >> 6, c = i & 63;
                const float* Ws = W1 + h * 64 * 64;
                Wp[i] = pk2(Ws[(2 * k2) * 64 + c], Ws[(2 * k2 + 1) * 64 + c]);
            }
            for (int i = t; i < 64 * 16; i += 256) {
                int row = i >> 4, col = (i & 15) * 4;
                int node = base + row;
                float4 v = make_float4(0.f, 0.f, 0.f, 0.f);
                if (node < n) {
                    const float* p = (h == 0) ? in0 : in1;
                    v = *(const float4*)&p[(size_t)node * 64 + col];
                }
                *(float4*)&xy[row * 68 + col] = v;
            }
            __syncthreads();
#pragma unroll 8
            for (int k = 0; k < 64; k += 4) {
                F4U xq[4];
#pragma unroll
                for (int i = 0; i < 4; i++)
                    xq[i].v = *(const float4*)&xy[(r0 + i) * 68 + k];
#pragma unroll
                for (int kk2 = 0; kk2 < 2; kk2++) {
                    ulonglong2 wA = *(const ulonglong2*)&Wp[(k / 2 + kk2) * 64 + c0];
                    ulonglong2 wB = *(const ulonglong2*)&Wp[(k / 2 + kk2) * 64 + c2];
#pragma unroll
                    for (int i = 0; i < 4; i++) {
                        u64 xp = xq[i].u[kk2];
                        a[i][0] = fma2(xp, wA.x, a[i][0]);
                        a[i][1] = fma2(xp, wA.y, a[i][1]);
                        a[i][2] = fma2(xp, wB.x, a[i][2]);
                        a[i][3] = fma2(xp, wB.y, a[i][3]);
                    }
                }
            }
            __syncthreads();
        }

#pragma unroll
        for (int i = 0; i < 4; i++) {
            float2 q0 = unpk(a[i][0]), q1 = unpk(a[i][1]);
            float2 q2 = unpk(a[i][2]), q3 = unpk(a[i][3]);
            float2 vA = make_float2(fmaxf(q0.x + q0.y, 0.f), fmaxf(q1.x + q1.y, 0.f));
            float2 vB = make_float2(fmaxf(q2.x + q2.y, 0.f), fmaxf(q3.x + q3.y, 0.f));
            *(float2*)&xy[(r0 + i) * 68 + c0] = vA;
            *(float2*)&xy[(r0 + i) * 68 + c2] = vB;
        }
        __syncthreads();

        // GEMM2: h = Y @ W2 + b2 + skip (in regs)
#pragma unroll
        for (int i = 0; i < 4; i++) {
            a[i][0] = pk2(b2s[c0], 0.f);
            a[i][1] = pk2(b2s[c0 + 1], 0.f);
            a[i][2] = pk2(b2s[c2], 0.f);
            a[i][3] = pk2(b2s[c2 + 1], 0.f);
        }
#pragma unroll 8
        for (int k = 0; k < 64; k += 4) {
            F4U xq[4];
#pragma unroll
            for (int i = 0; i < 4; i++)
                xq[i].v = *(const float4*)&xy[(r0 + i) * 68 + k];
#pragma unroll
            for (int kk2 = 0; kk2 < 2; kk2++) {
                ulonglong2 wA = *(const ulonglong2*)&W2p[(k / 2 + kk2) * 64 + c0];
                ulonglong2 wB = *(const ulonglong2*)&W2p[(k / 2 + kk2) * 64 + c2];
#pragma unroll
                for (int i = 0; i < 4; i++) {
                    u64 xp = xq[i].u[kk2];
                    a[i][0] = fma2(xp, wA.x, a[i][0]);
                    a[i][1] = fma2(xp, wA.y, a[i][1]);
                    a[i][2] = fma2(xp, wB.x, a[i][2]);
                    a[i][3] = fma2(xp, wB.y, a[i][3]);
                }
            }
        }
        float2 hA[4], hB[4];
#pragma unroll
        for (int i = 0; i < 4; i++) {
            float2 q0 = unpk(a[i][0]), q1 = unpk(a[i][1]);
            float2 q2 = unpk(a[i][2]), q3 = unpk(a[i][3]);
            hA[i] = make_float2(q0.x + q0.y, q1.x + q1.y);
            hB[i] = make_float2(q2.x + q2.y, q3.x + q3.y);
            int node = base + r0 + i;
            if (node < n) {
                float2 sA = *(const float2*)&skip[(size_t)node * 64 + c0];
                float2 sB = *(const float2*)&skip[(size_t)node * 64 + c2];
                hA[i].x += sA.x; hA[i].y += sA.y;
                hB[i].x += sB.x; hB[i].y += sB.y;
            }
        }
        __syncthreads();
#pragma unroll
        for (int i = 0; i < 4; i++) {
            bool valid = (base + r0 + i) < n;
            float2 vA = valid ? hA[i] : make_float2(0.f, 0.f);
            float2 vB = valid ? hB[i] : make_float2(0.f, 0.f);
            *(float2*)&xy[(r0 + i) * 68 + c0] = vA;
            *(float2*)&xy[(r0 + i) * 68 + c2] = vB;
        }
        for (int i = t; i < 32 * 64; i += 256) {
            int k2 = i >> 6, c = i & 63;
            Wp[i] = pk2(Wd1[(2 * k2) * 64 + c], Wd1[(2 * k2 + 1) * 64 + c]);
        }
        __syncthreads();

        // GEMM3: Yd = relu(h @ Wd1 + bd1)
#pragma unroll
        for (int i = 0; i < 4; i++) {
            a[i][0] = pk2(bd1s[c0], 0.f);
            a[i][1] = pk2(bd1s[c0 + 1], 0.f);
            a[i][2] = pk2(bd1s[c2], 0.f);
            a[i][3] = pk2(bd1s[c2 + 1], 0.f);
        }
#pragma unroll 8
        for (int k = 0; k < 64; k += 4) {
            F4U xq[4];
#pragma unroll
            for (int i = 0; i < 4; i++)
                xq[i].v = *(const float4*)&xy[(r0 + i) * 68 + k];
#pragma unroll
            for (int kk2 = 0; kk2 < 2; kk2++) {
                ulonglong2 wA = *(const ulonglong2*)&Wp[(k / 2 + kk2) * 64 + c0];
                ulonglong2 wB = *(const ulonglong2*)&Wp[(k / 2 + kk2) * 64 + c2];
#pragma unroll
                for (int i = 0; i < 4; i++) {
                    u64 xp = xq[i].u[kk2];
                    a[i][0] = fma2(xp, wA.x, a[i][0]);
                    a[i][1] = fma2(xp, wA.y, a[i][1]);
                    a[i][2] = fma2(xp, wB.x, a[i][2]);
                    a[i][3] = fma2(xp, wB.y, a[i][3]);
                }
            }
        }
        __syncthreads();
#pragma unroll
        for (int i = 0; i < 4; i++) {
            float2 q0 = unpk(a[i][0]), q1 = unpk(a[i][1]);
            float2 q2 = unpk(a[i][2]), q3 = unpk(a[i][3]);
            float2 vA = make_float2(fmaxf(q0.x + q0.y, 0.f), fmaxf(q1.x + q1.y, 0.f));
            float2 vB = make_float2(fmaxf(q2.x + q2.y, 0.f), fmaxf(q3.x + q3.y, 0.f));
            *(float2*)&xy[(r0 + i) * 68 + c0] = vA;
            *(float2*)&xy[(r0 + i) * 68 + c2] = vB;
        }
        __syncthreads();

        // GEMM4: out[n,2] = Yd @ Wd2 + bd2
        if (t < 128) {
            int row = t >> 1, col = t & 1;
            int node = base + row;
            if (node < n) {
                float acc = bd2s[col];
                const float* yr = &xy[row * 68];
#pragma unroll 16
                for (int k = 0; k < 64; k++) acc += yr[k] * Wd2s[k * 2 + col];
                out[(size_t)node * 2 + col] = acc;
            }
        }
        __syncthreads();
    }
}

// ---------------------------------------------------------------------------
static inline int mini(long a, long b) { return (int)(a < b ? a : b); }

static constexpr size_t MLP_SMEM =
    (size_t)(32 * 64 * 8) * 2 + 128 * 4 + 64 * 68 * 4;
static constexpr size_t ND_SMEM =
    (size_t)(32 * 64 * 8) * 2 + (64 * 3 + 128 + 4) * 4 + 64 * 68 * 4;

extern "C" void kernel_launch(void* const* d_in, const int* in_sizes, int n_in,
                              void* d_out, int out_size) {
    const float* x   = (const float*)d_in[0];
    const float* We1 = (const float*)d_in[1];
    const float* be1 = (const float*)d_in[2];
    const float* We2 = (const float*)d_in[3];
    const float* be2 = (const float*)d_in[4];
    const float* Wm1 = (const float*)d_in[5];
    const float* bm1 = (const float*)d_in[6];
    const float* Wm2 = (const float*)d_in[7];
    const float* bm2 = (const float*)d_in[8];
    const float* Wn1 = (const float*)d_in[9];
    const float* bn1 = (const float*)d_in[10];
    const float* Wn2 = (const float*)d_in[11];
    const float* bn2 = (const float*)d_in[12];
    const float* Wd1 = (const float*)d_in[13];
    const float* bd1 = (const float*)d_in[14];
    const float* Wd2 = (const float*)d_in[15];
    const float* bd2 = (const float*)d_in[16];
    const int* s_f  = (const int*)d_in[17];
    const int* r_f  = (const int*)d_in[18];
    const int* s_ds = (const int*)d_in[19];
    const int* r_ds = (const int*)d_in[20];
    const int* s_p  = (const int*)d_in[21];
    const int* r_p  = (const int*)d_in[22];
    const int* s_us = (const int*)d_in[23];
    const int* r_us = (const int*)d_in[24];
    const int* uppool   = (const int*)d_in[25];
    const int* downpool = (const int*)d_in[26];

    int N   = in_sizes[0] / 16;
    int NP  = in_sizes[26];
    int E   = in_sizes[17];
    int EDS = in_sizes[19];
    int EP  = in_sizes[21];
    int EUS = in_sizes[23];
    float* out = (float*)d_out;

    float *A, *B, *C, *AG;
    __half* Mh;
    int *IDX, *CNT, *OFF, *BSUM, *EPOOL;
    cudaGetSymbolAddress((void**)&A, g_A);
    cudaGetSymbolAddress((void**)&B, g_B);
    cudaGetSymbolAddress((void**)&C, g_C);
    cudaGetSymbolAddress((void**)&Mh, g_Mh);
    cudaGetSymbolAddress((void**)&AG, g_AG);
    cudaGetSymbolAddress((void**)&IDX, g_IDX);
    cudaGetSymbolAddress((void**)&CNT, g_cnt);
    cudaGetSymbolAddress((void**)&OFF, g_off);
    cudaGetSymbolAddress((void**)&BSUM, g_bsum);
    cudaGetSymbolAddress((void**)&EPOOL, g_epool);

    static bool attr_done = false;
    if (!attr_done) {
        cudaFuncSetAttribute(mlp2_tiled<16>, cudaFuncAttributeMaxDynamicSharedMemorySize,
                             (int)MLP_SMEM);
        cudaFuncSetAttribute(mlp2_tiled<64>, cudaFuncAttributeMaxDynamicSharedMemorySize,
                             (int)MLP_SMEM);
        cudaFuncSetAttribute(mlp2_tiled<128>, cudaFuncAttributeMaxDynamicSharedMemorySize,
                             (int)MLP_SMEM);
        cudaFuncSetAttribute(node_decode_tiled, cudaFuncAttributeMaxDynamicSharedMemorySize,
                             (int)ND_SMEM);
        attr_done = true;
    }

    auto grid_for = [](int n) { return mini(((long)n + 63) / 64, 4096); };
    auto wm1 = [&](int l) { return Wm1 + (size_t)l * D * D; };
    auto wm2 = [&](int l) { return Wm2 + (size_t)l * D * D; };
    auto bm1l = [&](int l) { return bm1 + (size_t)l * D; };
    auto bm2l = [&](int l) { return bm2 + (size_t)l * D; };
    auto wn1 = [&](int l) { return Wn1 + (size_t)l * 128 * D; };
    auto wn2 = [&](int l) { return Wn2 + (size_t)l * D * D; };
    auto bn1l = [&](int l) { return bn1 + (size_t)l * D; };
    auto bn2l = [&](int l) { return bn2 + (size_t)l * D; };

    // ---- CSR build for all 4 graphs ----
    long Etot = (long)E + EDS + EP + EUS;
    zero_int_kernel<<<(4 * RSEG + 511) / 512, 512>>>(CNT, 4 * RSEG);
    count_all_kernel<<<mini((Etot + 255) / 256, 4096), 256>>>(
        r_f, r_ds, r_p, r_us, E, EDS, EP, EUS, CNT);
    scan_block_kernel<<<4 * BPG, 1024>>>(CNT, OFF, BSUM,
                                         make_int4(N + 1, N + 1, NP + 1, NP + 1));
    scan_bsum_kernel<<<1, 32>>>(BSUM);
    scan_add_kernel<<<4 * BPG, 1024>>>(OFF, BSUM, CNT);
    fill_all_kernel<<<mini((Etot + 255) / 256, 4096), 256>>>(
        s_f, r_f, s_ds, r_ds, s_p, r_p, s_us, r_us, E, EDS, EP, EUS, CNT, EPOOL);

    // pull helpers: off region + epool segment per graph
    const int* off_f  = OFF + 0 * RSEG;  const int* es_f  = EPOOL;
    const int* off_ds = OFF + 1 * RSEG;  const int* es_ds = EPOOL + E;
    const int* off_p  = OFF + 2 * RSEG;  const int* es_p  = EPOOL + E + EDS;
    const int* off_us = OFF + 3 * RSEG;  const int* es_us = EPOOL + (size_t)E + EDS + EP;
    auto pull = [&](const int* off, const int* es, int n) {
        pull_kernel<<<(n * 16 + 255) / 256, 256>>>((const uint2*)Mh, off, es, AG, n);
    };

    // IDX[i] = uppool[downpool[i]]
    compose_idx_kernel<<<(NP + 255) / 256, 256>>>(uppool, downpool, IDX, NP);

    // encode + fused msg0 -> A=h1, Mh=msg0
    mlp2_tiled<16><<<grid_for(N), 256, MLP_SMEM>>>(
        x, nullptr, nullptr, nullptr, We1, be1, We2, be2, nullptr, A, nullptr,
        wm1(0), bm1l(0), wm2(0), bm2l(0), Mh, N);
    pull(off_f, es_f, N);
    // node0 + fused msg1 -> B=h2
    mlp2_tiled<128><<<grid_for(N), 256, MLP_SMEM>>>(
        A, AG, nullptr, nullptr, wn1(0), bn1l(0), wn2(0), bn2l(0), nullptr, B, nullptr,
        wm1(1), bm1l(1), wm2(1), bm2l(1), Mh, N);
    pull(off_f, es_f, N);
    // node1 -> C = h3 (skip source)
    mlp2_tiled<128><<<grid_for(N), 256, MLP_SMEM>>>(
        B, AG, nullptr, nullptr, wn1(1), bn1l(1), wn2(1), bn2l(1), nullptr, C, nullptr,
        nullptr, nullptr, nullptr, nullptr, nullptr, N);
    // msg2 over C[uppool[i]]
    mlp2_tiled<64><<<grid_for(N), 256, MLP_SMEM>>>(
        C, nullptr, uppool, nullptr, wm1(2), bm1l(2), wm2(2), bm2l(2), nullptr,
        nullptr, Mh, nullptr, nullptr, nullptr, nullptr, nullptr, N);
    pull(off_ds, es_ds, N);
    // node2 (in0 = C[uppool[downpool[i]]], in1 = AG[downpool[i]]) + fused msg3
    mlp2_tiled<128><<<grid_for(NP), 256, MLP_SMEM>>>(
        C, AG, IDX, downpool, wn1(2), bn1l(2), wn2(2), bn2l(2), nullptr, B, nullptr,
        wm1(3), bm1l(3), wm2(3), bm2l(3), Mh, NP);
    pull(off_p, es_p, NP);
    // node3 + fused msg4 -> A (NP)
    mlp2_tiled<128><<<grid_for(NP), 256, MLP_SMEM>>>(
        B, AG, nullptr, nullptr, wn1(3), bn1l(3), wn2(3), bn2l(3), nullptr, A, nullptr,
        wm1(4), bm1l(4), wm2(4), bm2l(4), Mh, NP);
    pull(off_p, es_p, NP);
    // node4 -> B (NP)
    mlp2_tiled<128><<<grid_for(NP), 256, MLP_SMEM>>>(
        A, AG, nullptr, nullptr, wn1(4), bn1l(4), wn2(4), bn2l(4), nullptr, B, nullptr,
        nullptr, nullptr, nullptr, nullptr, nullptr, NP);
    // msg5 over B[downpool[i]]
    mlp2_tiled<64><<<grid_for(NP), 256, MLP_SMEM>>>(
        B, nullptr, downpool, nullptr, wm1(5), bm1l(5), wm2(5), bm2l(5), nullptr,
        nullptr, Mh, nullptr, nullptr, nullptr, nullptr, nullptr, NP);
    pull(off_us, es_us, NP);
    // node5: in0 = B[downpool[i]], in1 = AG -> A = g_us (NP)
    mlp2_tiled<128><<<grid_for(NP), 256, MLP_SMEM>>>(
        B, AG, downpool, nullptr, wn1(5), bn1l(5), wn2(5), bn2l(5), nullptr, A, nullptr,
        nullptr, nullptr, nullptr, nullptr, nullptr, NP);
    // msg6 over A[uppool[i]]
    mlp2_tiled<64><<<grid_for(N), 256, MLP_SMEM>>>(
        A, nullptr, uppool, nullptr, wm1(6), bm1l(6), wm2(6), bm2l(6), nullptr,
        nullptr, Mh, nullptr, nullptr, nullptr, nullptr, nullptr, N);
    pull(off_f, es_f, N);
    // node6 (in0 = A[uppool[i]], skip=C) + fused msg7 -> B (N)
    mlp2_tiled<128><<<grid_for(N), 256, MLP_SMEM>>>(
        A, AG, uppool, nullptr, wn1(6), bn1l(6), wn2(6), bn2l(6), C, B, nullptr,
        wm1(7), bm1l(7), wm2(7), bm2l(7), Mh, N);
    pull(off_f, es_f, N);
    // node7 (skip=C) + decode fused -> out[n,2]
    node_decode_tiled<<<grid_for(N), 256, ND_SMEM>>>(
        B, AG, wn1(7), bn1l(7), wn2(7), bn2l(7), C,
        Wd1, bd1, Wd2, bd2, out, N);
}

// round 17
// speedup vs baseline: 2.0717x; 1.0652x over previous
#include <cuda_runtime.h>
#include <cuda_fp16.h>
#include <cstddef>

#define D 64
#define MAXN 100000
#define RSEG 102400              // per-graph CSR region (mult of 1024, > MAXN+1)
#define BPG (RSEG / 1024)        // blocks per graph region = 100

typedef unsigned long long u64;

// Scratch buffers (no allocation allowed) -----------------------------------
__device__ float  g_A[MAXN * D];
__device__ float  g_B[MAXN * D];
__device__ float  g_C[MAXN * D];
__device__ __half g_Mh[MAXN * D];  // per-node messages (fp16 storage)
__device__ float  g_AG[MAXN * D];  // aggregation (fp32)
__device__ int    g_IDX[MAXN];     // composite index scratch
// CSR scratch
__device__ int    g_cnt[4 * RSEG];      // counts -> cursors
__device__ int    g_off[4 * RSEG];      // exclusive offsets (+ total at [n])
__device__ int    g_bsum[4 * BPG];
__device__ int    g_epool[3200000];     // edge source ids grouped by receiver
__device__ int    g_epool2[2400000];    // uppool-composed sources (fine + ds)

// ---------------------------------------------------------------------------
// packed f32x2 helpers
__device__ __forceinline__ u64 fma2(u64 a, u64 b, u64 c) {
    u64 d;
    asm("fma.rn.f32x2 %0, %1, %2, %3;" : "=l"(d) : "l"(a), "l"(b), "l"(c));
    return d;
}
__device__ __forceinline__ u64 pk2(float lo, float hi) {
    u64 r;
    asm("mov.b64 %0, {%1, %2};" : "=l"(r)
        : "r"(__float_as_uint(lo)), "r"(__float_as_uint(hi)));
    return r;
}
__device__ __forceinline__ float2 unpk(u64 p) {
    unsigned int lo, hi;
    asm("mov.b64 {%0, %1}, %2;" : "=r"(lo), "=r"(hi) : "l"(p));
    return make_float2(__uint_as_float(lo), __uint_as_float(hi));
}
union F4U { float4 v; u64 u[2]; };

// ---------------------------------------------------------------------------
__global__ __launch_bounds__(512) void zero_int_kernel(int* __restrict__ p, int n) {
    int i = blockIdx.x * blockDim.x + threadIdx.x;
    if (i < n) p[i] = 0;
}

// cidx[i] = a[b[i]]
__global__ __launch_bounds__(256) void compose_idx_kernel(const int* __restrict__ a,
                                                          const int* __restrict__ b,
                                                          int* __restrict__ cidx, int n) {
    int i = blockIdx.x * blockDim.x + threadIdx.x;
    if (i < n) cidx[i] = a[b[i]];
}

// out[i] = map[ep[i]]  (grid-stride, long count)
__global__ __launch_bounds__(256) void compose_esrc_kernel(const int* __restrict__ ep,
                                                           const int* __restrict__ map,
                                                           int* __restrict__ outp, long n) {
    for (long i = (long)blockIdx.x * 256 + threadIdx.x; i < n;
         i += (long)gridDim.x * 256)
        outp[i] = __ldg(&map[__ldg(&ep[i])]);
}

// ---------------------------------------------------------------------------
// CSR build: count -> scan -> fill (all 4 graphs in combined kernels)
// ---------------------------------------------------------------------------
__global__ __launch_bounds__(256) void count_all_kernel(
    const int* __restrict__ rf, const int* __restrict__ rds,
    const int* __restrict__ rp, const int* __restrict__ rus,
    int E, int EDS, int EP, int EUS, int* __restrict__ cnt) {
    long b1 = E, b2 = (long)E + EDS, b3 = (long)E + EDS + EP;
    long tot = b3 + EUS;
    for (long i = (long)blockIdx.x * 256 + threadIdx.x; i < tot;
         i += (long)gridDim.x * 256) {
        if (i < b1)      atomicAdd(&cnt[0 * RSEG + __ldg(&rf[i])], 1);
        else if (i < b2) atomicAdd(&cnt[1 * RSEG + __ldg(&rds[i - b1])], 1);
        else if (i < b3) atomicAdd(&cnt[2 * RSEG + __ldg(&rp[i - b2])], 1);
        else             atomicAdd(&cnt[3 * RSEG + __ldg(&rus[i - b3])], 1);
    }
}

__global__ __launch_bounds__(1024) void scan_block_kernel(const int* __restrict__ cnt,
                                                          int* __restrict__ off,
                                                          int* __restrict__ bsum,
                                                          int4 n1s) {
    __shared__ int sh[1024];
    int g = blockIdx.x / BPG;
    int lb = blockIdx.x % BPG;
    int n1 = (g == 0) ? n1s.x : (g == 1) ? n1s.y : (g == 2) ? n1s.z : n1s.w;
    int i = lb * 1024 + threadIdx.x;
    int v = (i < n1) ? cnt[g * RSEG + i] : 0;
    sh[threadIdx.x] = v;
    __syncthreads();
#pragma unroll
    for (int d = 1; d < 1024; d <<= 1) {
        int tv = (threadIdx.x >= d) ? sh[threadIdx.x - d] : 0;
        __syncthreads();
        sh[threadIdx.x] += tv;
        __syncthreads();
    }
    off[g * RSEG + i] = sh[threadIdx.x] - v;   // exclusive
    if (threadIdx.x == 1023) bsum[blockIdx.x] = sh[1023];
}

__global__ void scan_bsum_kernel(int* __restrict__ bsum) {
    int g = threadIdx.x;
    if (g < 4) {
        int acc = 0;
        for (int b = 0; b < BPG; b++) {
            int idx = g * BPG + b;
            int v = bsum[idx];
            bsum[idx] = acc;
            acc += v;
        }
    }
}

__global__ __launch_bounds__(1024) void scan_add_kernel(int* __restrict__ off,
                                                        const int* __restrict__ bsum,
                                                        int* __restrict__ cur) {
    int i = blockIdx.x * 1024 + threadIdx.x;     // covers 4*RSEG
    int v = off[i] + bsum[blockIdx.x];           // blockIdx = g*BPG + lb
    off[i] = v;
    cur[i] = v;
}

__global__ __launch_bounds__(256) void fill_all_kernel(
    const int* __restrict__ sf, const int* __restrict__ rf,
    const int* __restrict__ sds, const int* __restrict__ rds,
    const int* __restrict__ sp, const int* __restrict__ rp,
    const int* __restrict__ sus, const int* __restrict__ rus,
    int E, int EDS, int EP, int EUS,
    int* __restrict__ cur, int* __restrict__ epool) {
    long b1 = E, b2 = (long)E + EDS, b3 = (long)E + EDS + EP;
    long tot = b3 + EUS;
    for (long i = (long)blockIdx.x * 256 + threadIdx.x; i < tot;
         i += (long)gridDim.x * 256) {
        if (i < b1) {
            int p = atomicAdd(&cur[0 * RSEG + __ldg(&rf[i])], 1);
            epool[p] = __ldg(&sf[i]);
        } else if (i < b2) {
            long j = i - b1;
            int p = atomicAdd(&cur[1 * RSEG + __ldg(&rds[j])], 1);
            epool[E + p] = __ldg(&sds[j]);
        } else if (i < b3) {
            long j = i - b2;
            int p = atomicAdd(&cur[2 * RSEG + __ldg(&rp[j])], 1);
            epool[E + EDS + p] = __ldg(&sp[j]);
        } else {
            long j = i - b3;
            int p = atomicAdd(&cur[3 * RSEG + __ldg(&rus[j])], 1);
            epool[E + EDS + EP + p] = __ldg(&sus[j]);
        }
    }
}

// ---------------------------------------------------------------------------
// Pull aggregation: aggr[rid,:] = sum over CSR edges of float(msg[src,:])
// 16 threads per receiver; lane handles 4 consecutive cols (8B fp16 load).
// ---------------------------------------------------------------------------
__global__ __launch_bounds__(256) void pull_kernel(const uint2* __restrict__ msg,
                                                   const int* __restrict__ off,
                                                   const int* __restrict__ esrc,
                                                   float* __restrict__ aggr, int n) {
    int gid = blockIdx.x * 256 + threadIdx.x;
    int rid = gid >> 4;
    int lane = gid & 15;
    if (rid >= n) return;
    int beg = __ldg(&off[rid]);
    int end = __ldg(&off[rid + 1]);
    float4 acc = make_float4(0.f, 0.f, 0.f, 0.f);
    for (int e = beg; e < end; e++) {
        int s = __ldg(&esrc[e]);
        uint2 raw = __ldg(&msg[(size_t)s * 16 + lane]);
        __half2 p0 = *reinterpret_cast<__half2*>(&raw.x);
        __half2 p1 = *reinterpret_cast<__half2*>(&raw.y);
        float2 f0 = __half22float2(p0);
        float2 f1 = __half22float2(p1);
        acc.x += f0.x; acc.y += f0.y; acc.z += f1.x; acc.w += f1.y;
    }
    *(float4*)&aggr[(size_t)rid * 64 + lane * 4] = acc;
}

// ---------------------------------------------------------------------------
// Register-tiled 2-layer MLP (optionally fused with next layer's message MLP)
// ---------------------------------------------------------------------------
template <int IN>
__global__ __launch_bounds__(256, 4) void mlp2_tiled(
    const float* __restrict__ in0, const float* __restrict__ in1,
    const int* __restrict__ rowidx0, const int* __restrict__ rowidx1,
    const float* __restrict__ W1, const float* __restrict__ b1,
    const float* __restrict__ W2, const float* __restrict__ b2,
    const float* __restrict__ skip, float* __restrict__ out,
    __half* __restrict__ out_h,
    const float* __restrict__ Wm1, const float* __restrict__ bm1,
    const float* __restrict__ Wm2, const float* __restrict__ bm2,
    __half* __restrict__ Mout_h, int n) {
    extern __shared__ __align__(16) float sm[];
    u64* Wp  = (u64*)sm;                           // 32*64 u64
    u64* W2p = Wp + 32 * 64;                       // 32*64 u64
    float* b1s = (float*)(W2p + 32 * 64);          // 64
    float* b2s = b1s + 64;                         // 64
    float* xy  = b2s + 64;                         // 64*68 floats

    const int t = threadIdx.x;
    constexpr int XC = (IN < 64) ? IN : 64;
    constexpr int NH = (IN == 128) ? 2 : 1;

    for (int i = t; i < 32 * 64; i += 256) {
        int k2 = i >> 6, c = i & 63;
        W2p[i] = pk2(W2[(2 * k2) * 64 + c], W2[(2 * k2 + 1) * 64 + c]);
    }
    if (t < 64) { b1s[t] = b1[t]; b2s[t] = b2[t]; }
    __syncthreads();

    const int tc = t & 15;
    const int tr = t >> 4;
    const int c0 = tc * 2, c2 = c0 + 32;
    const int r0 = tr * 4;
    const int tiles = (n + 63) >> 6;

    for (int tile = blockIdx.x; tile < tiles; tile += gridDim.x) {
        const int base = tile * 64;

        u64 a[4][4];
#pragma unroll
        for (int i = 0; i < 4; i++) {
            a[i][0] = pk2(b1s[c0], 0.f);
            a[i][1] = pk2(b1s[c0 + 1], 0.f);
            a[i][2] = pk2(b1s[c2], 0.f);
            a[i][3] = pk2(b1s[c2 + 1], 0.f);
        }

#pragma unroll
        for (int h = 0; h < NH; h++) {
            for (int i = t; i < (XC / 2) * 64; i += 256) {
                int k2 = i >> 6, c = i & 63;
                const float* Ws = W1 + h * 64 * 64;
                Wp[i] = pk2(Ws[(2 * k2) * 64 + c], Ws[(2 * k2 + 1) * 64 + c]);
            }
            constexpr int C4 = XC / 4;
            for (int i = t; i < 64 * C4; i += 256) {
                int row = i / C4, col = (i % C4) * 4;
                int node = base + row;
                float4 v = make_float4(0.f, 0.f, 0.f, 0.f);
                if (node < n) {
                    const int* ridx = (h == 0) ? rowidx0 : rowidx1;
                    int src = ridx ? ridx[node] : node;
                    const float* p = (h == 0) ? in0 : in1;
                    v = *(const float4*)&p[(size_t)src * XC + col];
                }
                *(float4*)&xy[row * 68 + col] = v;
            }
            __syncthreads();
#pragma unroll 8
            for (int k = 0; k < XC; k += 4) {
                F4U xq[4];
#pragma unroll
                for (int i = 0; i < 4; i++)
                    xq[i].v = *(const float4*)&xy[(r0 + i) * 68 + k];
#pragma unroll
                for (int kk2 = 0; kk2 < 2; kk2++) {
                    ulonglong2 wA = *(const ulonglong2*)&Wp[(k / 2 + kk2) * 64 + c0];
                    ulonglong2 wB = *(const ulonglong2*)&Wp[(k / 2 + kk2) * 64 + c2];
#pragma unroll
                    for (int i = 0; i < 4; i++) {
                        u64 xp = xq[i].u[kk2];
                        a[i][0] = fma2(xp, wA.x, a[i][0]);
                        a[i][1] = fma2(xp, wA.y, a[i][1]);
                        a[i][2] = fma2(xp, wB.x, a[i][2]);
                        a[i][3] = fma2(xp, wB.y, a[i][3]);
                    }
                }
            }
            __syncthreads();
        }

        // relu + write Y into xy
#pragma unroll
        for (int i = 0; i < 4; i++) {
            float2 q0 = unpk(a[i][0]), q1 = unpk(a[i][1]);
            float2 q2 = unpk(a[i][2]), q3 = unpk(a[i][3]);
            float2 vA = make_float2(fmaxf(q0.x + q0.y, 0.f), fmaxf(q1.x + q1.y, 0.f));
            float2 vB = make_float2(fmaxf(q2.x + q2.y, 0.f), fmaxf(q3.x + q3.y, 0.f));
            *(float2*)&xy[(r0 + i) * 68 + c0] = vA;
            *(float2*)&xy[(r0 + i) * 68 + c2] = vB;
        }
        __syncthreads();

        // ---- GEMM2: h = Y @ W2 + b2 (+skip) ----
#pragma unroll
        for (int i = 0; i < 4; i++) {
            a[i][0] = pk2(b2s[c0], 0.f);
            a[i][1] = pk2(b2s[c0 + 1], 0.f);
            a[i][2] = pk2(b2s[c2], 0.f);
            a[i][3] = pk2(b2s[c2 + 1], 0.f);
        }
#pragma unroll 8
        for (int k = 0; k < 64; k += 4) {
            F4U xq[4];
#pragma unroll
            for (int i = 0; i < 4; i++)
                xq[i].v = *(const float4*)&xy[(r0 + i) * 68 + k];
#pragma unroll
            for (int kk2 = 0; kk2 < 2; kk2++) {
                ulonglong2 wA = *(const ulonglong2*)&W2p[(k / 2 + kk2) * 64 + c0];
                ulonglong2 wB = *(const ulonglong2*)&W2p[(k / 2 + kk2) * 64 + c2];
#pragma unroll
                for (int i = 0; i < 4; i++) {
                    u64 xp = xq[i].u[kk2];
                    a[i][0] = fma2(xp, wA.x, a[i][0]);
                    a[i][1] = fma2(xp, wA.y, a[i][1]);
                    a[i][2] = fma2(xp, wB.x, a[i][2]);
                    a[i][3] = fma2(xp, wB.y, a[i][3]);
                }
            }
        }
        float2 hA[4], hB[4];
#pragma unroll
        for (int i = 0; i < 4; i++) {
            float2 q0 = unpk(a[i][0]), q1 = unpk(a[i][1]);
            float2 q2 = unpk(a[i][2]), q3 = unpk(a[i][3]);
            hA[i] = make_float2(q0.x + q0.y, q1.x + q1.y);
            hB[i] = make_float2(q2.x + q2.y, q3.x + q3.y);
            int node = base + r0 + i;
            if (node < n) {
                if (skip) {
                    float2 sA = *(const float2*)&skip[(size_t)node * 64 + c0];
                    float2 sB = *(const float2*)&skip[(size_t)node * 64 + c2];
                    hA[i].x += sA.x; hA[i].y += sA.y;
                    hB[i].x += sB.x; hB[i].y += sB.y;
                }
                if (out) {
                    *(float2*)&out[(size_t)node * 64 + c0] = hA[i];
                    *(float2*)&out[(size_t)node * 64 + c2] = hB[i];
                }
                if (out_h) {
                    *(__half2*)&out_h[(size_t)node * 64 + c0] =
                        __floats2half2_rn(hA[i].x, hA[i].y);
                    *(__half2*)&out_h[(size_t)node * 64 + c2] =
                        __floats2half2_rn(hB[i].x, hB[i].y);
                }
            }
        }

        // ================= fused next-layer message MLP =================
        if (Mout_h) {
            __syncthreads();
#pragma unroll
            for (int i = 0; i < 4; i++) {
                bool valid = (base + r0 + i) < n;
                float2 vA = valid ? hA[i] : make_float2(0.f, 0.f);
                float2 vB = valid ? hB[i] : make_float2(0.f, 0.f);
                *(float2*)&xy[(r0 + i) * 68 + c0] = vA;
                *(float2*)&xy[(r0 + i) * 68 + c2] = vB;
            }
            for (int i = t; i < 32 * 64; i += 256) {
                int k2 = i >> 6, c = i & 63;
                Wp[i]  = pk2(Wm1[(2 * k2) * 64 + c], Wm1[(2 * k2 + 1) * 64 + c]);
                W2p[i] = pk2(Wm2[(2 * k2) * 64 + c], Wm2[(2 * k2 + 1) * 64 + c]);
            }
            if (t < 64) { b1s[t] = bm1[t]; b2s[t] = bm2[t]; }
            __syncthreads();

            // GEMM3: Y2 = relu(h @ Wm1 + bm1)
#pragma unroll
            for (int i = 0; i < 4; i++) {
                a[i][0] = pk2(b1s[c0], 0.f);
                a[i][1] = pk2(b1s[c0 + 1], 0.f);
                a[i][2] = pk2(b1s[c2], 0.f);
                a[i][3] = pk2(b1s[c2 + 1], 0.f);
            }
#pragma unroll 8
            for (int k = 0; k < 64; k += 4) {
                F4U xq[4];
#pragma unroll
                for (int i = 0; i < 4; i++)
                    xq[i].v = *(const float4*)&xy[(r0 + i) * 68 + k];
#pragma unroll
                for (int kk2 = 0; kk2 < 2; kk2++) {
                    ulonglong2 wA = *(const ulonglong2*)&Wp[(k / 2 + kk2) * 64 + c0];
                    ulonglong2 wB = *(const ulonglong2*)&Wp[(k / 2 + kk2) * 64 + c2];
#pragma unroll
                    for (int i = 0; i < 4; i++) {
                        u64 xp = xq[i].u[kk2];
                        a[i][0] = fma2(xp, wA.x, a[i][0]);
                        a[i][1] = fma2(xp, wA.y, a[i][1]);
                        a[i][2] = fma2(xp, wB.x, a[i][2]);
                        a[i][3] = fma2(xp, wB.y, a[i][3]);
                    }
                }
            }
            __syncthreads();
#pragma unroll
            for (int i = 0; i < 4; i++) {
                float2 q0 = unpk(a[i][0]), q1 = unpk(a[i][1]);
                float2 q2 = unpk(a[i][2]), q3 = unpk(a[i][3]);
                float2 vA = make_float2(fmaxf(q0.x + q0.y, 0.f), fmaxf(q1.x + q1.y, 0.f));
                float2 vB = make_float2(fmaxf(q2.x + q2.y, 0.f), fmaxf(q3.x + q3.y, 0.f));
                *(float2*)&xy[(r0 + i) * 68 + c0] = vA;
                *(float2*)&xy[(r0 + i) * 68 + c2] = vB;
            }
            __syncthreads();

            // GEMM4: M = Y2 @ Wm2 + bm2 -> fp16 Mout
#pragma unroll
            for (int i = 0; i < 4; i++) {
                a[i][0] = pk2(b2s[c0], 0.f);
                a[i][1] = pk2(b2s[c0 + 1], 0.f);
                a[i][2] = pk2(b2s[c2], 0.f);
                a[i][3] = pk2(b2s[c2 + 1], 0.f);
            }
#pragma unroll 8
            for (int k = 0; k < 64; k += 4) {
                F4U xq[4];
#pragma unroll
                for (int i = 0; i < 4; i++)
                    xq[i].v = *(const float4*)&xy[(r0 + i) * 68 + k];
#pragma unroll
                for (int kk2 = 0; kk2 < 2; kk2++) {
                    ulonglong2 wA = *(const ulonglong2*)&W2p[(k / 2 + kk2) * 64 + c0];
                    ulonglong2 wB = *(const ulonglong2*)&W2p[(k / 2 + kk2) * 64 + c2];
#pragma unroll
                    for (int i = 0; i < 4; i++) {
                        u64 xp = xq[i].u[kk2];
                        a[i][0] = fma2(xp, wA.x, a[i][0]);
                        a[i][1] = fma2(xp, wA.y, a[i][1]);
                        a[i][2] = fma2(xp, wB.x, a[i][2]);
                        a[i][3] = fma2(xp, wB.y, a[i][3]);
                    }
                }
            }
#pragma unroll
            for (int i = 0; i < 4; i++) {
                int node = base + r0 + i;
                if (node < n) {
                    float2 q0 = unpk(a[i][0]), q1 = unpk(a[i][1]);
                    float2 q2 = unpk(a[i][2]), q3 = unpk(a[i][3]);
                    *(__half2*)&Mout_h[(size_t)node * 64 + c0] =
                        __floats2half2_rn(q0.x + q0.y, q1.x + q1.y);
                    *(__half2*)&Mout_h[(size_t)node * 64 + c2] =
                        __floats2half2_rn(q2.x + q2.y, q3.x + q3.y);
                }
            }
        }
        __syncthreads();
    }
}

// ---------------------------------------------------------------------------
// node7 + decode fused
// ---------------------------------------------------------------------------
__global__ __launch_bounds__(256, 4) void node_decode_tiled(
    const float* __restrict__ in0, const float* __restrict__ in1,
    const float* __restrict__ W1, const float* __restrict__ b1,
    const float* __restrict__ W2, const float* __restrict__ b2,
    const float* __restrict__ skip,
    const float* __restrict__ Wd1, const float* __restrict__ bd1,
    const float* __restrict__ Wd2, const float* __restrict__ bd2,
    float* __restrict__ out, int n) {
    extern __shared__ __align__(16) float sm[];
    u64* Wp  = (u64*)sm;
    u64* W2p = Wp + 32 * 64;
    float* b1s  = (float*)(W2p + 32 * 64);
    float* b2s  = b1s + 64;
    float* bd1s = b2s + 64;
    float* Wd2s = bd1s + 64;
    float* bd2s = Wd2s + 128;
    float* xy   = bd2s + 4;

    const int t = threadIdx.x;
    for (int i = t; i < 32 * 64; i += 256) {
        int k2 = i >> 6, c = i & 63;
        W2p[i] = pk2(W2[(2 * k2) * 64 + c], W2[(2 * k2 + 1) * 64 + c]);
    }
    if (t < 64) { b1s[t] = b1[t]; b2s[t] = b2[t]; bd1s[t] = bd1[t]; }
    if (t < 128) Wd2s[t] = Wd2[t];
    if (t < 2) bd2s[t] = bd2[t];
    __syncthreads();

    const int tc = t & 15;
    const int tr = t >> 4;
    const int c0 = tc * 2, c2 = c0 + 32;
    const int r0 = tr * 4;
    const int tiles = (n + 63) >> 6;

    for (int tile = blockIdx.x; tile < tiles; tile += gridDim.x) {
        const int base = tile * 64;

        u64 a[4][4];
#pragma unroll
        for (int i = 0; i < 4; i++) {
            a[i][0] = pk2(b1s[c0], 0.f);
            a[i][1] = pk2(b1s[c0 + 1], 0.f);
            a[i][2] = pk2(b1s[c2], 0.f);
            a[i][3] = pk2(b1s[c2 + 1], 0.f);
        }

#pragma unroll
        for (int h = 0; h < 2; h++) {
            for (int i = t; i < 32 * 64; i += 256) {
                int k2 = i >> 6, c = i & 63;
                const float* Ws = W1 + h * 64 * 64;
                Wp[i] = pk2(Ws[(2 * k2) * 64 + c], Ws[(2 * k2 + 1) * 64 + c]);
            }
            for (int i = t; i < 64 * 16; i += 256) {
                int row = i >> 4, col = (i & 15) * 4;
                int node = base + row;
                float4 v = make_float4(0.f, 0.f, 0.f, 0.f);
                if (node < n) {
                    const float* p = (h == 0) ? in0 : in1;
                    v = *(const float4*)&p[(size_t)node * 64 + col];
                }
                *(float4*)&xy[row * 68 + col] = v;
            }
            __syncthreads();
#pragma unroll 8
            for (int k = 0; k < 64; k += 4) {
                F4U xq[4];
#pragma unroll
                for (int i = 0; i < 4; i++)
                    xq[i].v = *(const float4*)&xy[(r0 + i) * 68 + k];
#pragma unroll
                for (int kk2 = 0; kk2 < 2; kk2++) {
                    ulonglong2 wA = *(const ulonglong2*)&Wp[(k / 2 + kk2) * 64 + c0];
                    ulonglong2 wB = *(const ulonglong2*)&Wp[(k / 2 + kk2) * 64 + c2];
#pragma unroll
                    for (int i = 0; i < 4; i++) {
                        u64 xp = xq[i].u[kk2];
                        a[i][0] = fma2(xp, wA.x, a[i][0]);
                        a[i][1] = fma2(xp, wA.y, a[i][1]);
                        a[i][2] = fma2(xp, wB.x, a[i][2]);
                        a[i][3] = fma2(xp, wB.y, a[i][3]);
                    }
                }
            }
            __syncthreads();
        }

#pragma unroll
        for (int i = 0; i < 4; i++) {
            float2 q0 = unpk(a[i][0]), q1 = unpk(a[i][1]);
            float2 q2 = unpk(a[i][2]), q3 = unpk(a[i][3]);
            float2 vA = make_float2(fmaxf(q0.x + q0.y, 0.f), fmaxf(q1.x + q1.y, 0.f));
            float2 vB = make_float2(fmaxf(q2.x + q2.y, 0.f), fmaxf(q3.x + q3.y, 0.f));
            *(float2*)&xy[(r0 + i) * 68 + c0] = vA;
            *(float2*)&xy[(r0 + i) * 68 + c2] = vB;
        }
        __syncthreads();

        // GEMM2: h = Y @ W2 + b2 + skip (in regs)
#pragma unroll
        for (int i = 0; i < 4; i++) {
            a[i][0] = pk2(b2s[c0], 0.f);
            a[i][1] = pk2(b2s[c0 + 1], 0.f);
            a[i][2] = pk2(b2s[c2], 0.f);
            a[i][3] = pk2(b2s[c2 + 1], 0.f);
        }
#pragma unroll 8
        for (int k = 0; k < 64; k += 4) {
            F4U xq[4];
#pragma unroll
            for (int i = 0; i < 4; i++)
                xq[i].v = *(const float4*)&xy[(r0 + i) * 68 + k];
#pragma unroll
            for (int kk2 = 0; kk2 < 2; kk2++) {
                ulonglong2 wA = *(const ulonglong2*)&W2p[(k / 2 + kk2) * 64 + c0];
                ulonglong2 wB = *(const ulonglong2*)&W2p[(k / 2 + kk2) * 64 + c2];
#pragma unroll
                for (int i = 0; i < 4; i++) {
                    u64 xp = xq[i].u[kk2];
                    a[i][0] = fma2(xp, wA.x, a[i][0]);
                    a[i][1] = fma2(xp, wA.y, a[i][1]);
                    a[i][2] = fma2(xp, wB.x, a[i][2]);
                    a[i][3] = fma2(xp, wB.y, a[i][3]);
                }
            }
        }
        float2 hA[4], hB[4];
#pragma unroll
        for (int i = 0; i < 4; i++) {
            float2 q0 = unpk(a[i][0]), q1 = unpk(a[i][1]);
            float2 q2 = unpk(a[i][2]), q3 = unpk(a[i][3]);
            hA[i] = make_float2(q0.x + q0.y, q1.x + q1.y);
            hB[i] = make_float2(q2.x + q2.y, q3.x + q3.y);
            int node = base + r0 + i;
            if (node < n) {
                float2 sA = *(const float2*)&skip[(size_t)node * 64 + c0];
                float2 sB = *(const float2*)&skip[(size_t)node * 64 + c2];
                hA[i].x += sA.x; hA[i].y += sA.y;
                hB[i].x += sB.x; hB[i].y += sB.y;
            }
        }
        __syncthreads();
#pragma unroll
        for (int i = 0; i < 4; i++) {
            bool valid = (base + r0 + i) < n;
            float2 vA = valid ? hA[i] : make_float2(0.f, 0.f);
            float2 vB = valid ? hB[i] : make_float2(0.f, 0.f);
            *(float2*)&xy[(r0 + i) * 68 + c0] = vA;
            *(float2*)&xy[(r0 + i) * 68 + c2] = vB;
        }
        for (int i = t; i < 32 * 64; i += 256) {
            int k2 = i >> 6, c = i & 63;
            Wp[i] = pk2(Wd1[(2 * k2) * 64 + c], Wd1[(2 * k2 + 1) * 64 + c]);
        }
        __syncthreads();

        // GEMM3: Yd = relu(h @ Wd1 + bd1)
#pragma unroll
        for (int i = 0; i < 4; i++) {
            a[i][0] = pk2(bd1s[c0], 0.f);
            a[i][1] = pk2(bd1s[c0 + 1], 0.f);
            a[i][2] = pk2(bd1s[c2], 0.f);
            a[i][3] = pk2(bd1s[c2 + 1], 0.f);
        }
#pragma unroll 8
        for (int k = 0; k < 64; k += 4) {
            F4U xq[4];
#pragma unroll
            for (int i = 0; i < 4; i++)
                xq[i].v = *(const float4*)&xy[(r0 + i) * 68 + k];
#pragma unroll
            for (int kk2 = 0; kk2 < 2; kk2++) {
                ulonglong2 wA = *(const ulonglong2*)&Wp[(k / 2 + kk2) * 64 + c0];
                ulonglong2 wB = *(const ulonglong2*)&Wp[(k / 2 + kk2) * 64 + c2];
#pragma unroll
                for (int i = 0; i < 4; i++) {
                    u64 xp = xq[i].u[kk2];
                    a[i][0] = fma2(xp, wA.x, a[i][0]);
                    a[i][1] = fma2(xp, wA.y, a[i][1]);
                    a[i][2] = fma2(xp, wB.x, a[i][2]);
                    a[i][3] = fma2(xp, wB.y, a[i][3]);
                }
            }
        }
        __syncthreads();
#pragma unroll
        for (int i = 0; i < 4; i++) {
            float2 q0 = unpk(a[i][0]), q1 = unpk(a[i][1]);
            float2 q2 = unpk(a[i][2]), q3 = unpk(a[i][3]);
            float2 vA = make_float2(fmaxf(q0.x + q0.y, 0.f), fmaxf(q1.x + q1.y, 0.f));
            float2 vB = make_float2(fmaxf(q2.x + q2.y, 0.f), fmaxf(q3.x + q3.y, 0.f));
            *(float2*)&xy[(r0 + i) * 68 + c0] = vA;
            *(float2*)&xy[(r0 + i) * 68 + c2] = vB;
        }
        __syncthreads();

        // GEMM4: out[n,2] = Yd @ Wd2 + bd2
        if (t < 128) {
            int row = t >> 1, col = t & 1;
            int node = base + row;
            if (node < n) {
                float acc = bd2s[col];
                const float* yr = &xy[row * 68];
#pragma unroll 16
                for (int k = 0; k < 64; k++) acc += yr[k] * Wd2s[k * 2 + col];
                out[(size_t)node * 2 + col] = acc;
            }
        }
        __syncthreads();
    }
}

// ---------------------------------------------------------------------------
static inline int mini(long a, long b) { return (int)(a < b ? a : b); }

static constexpr size_t MLP_SMEM =
    (size_t)(32 * 64 * 8) * 2 + 128 * 4 + 64 * 68 * 4;
static constexpr size_t ND_SMEM =
    (size_t)(32 * 64 * 8) * 2 + (64 * 3 + 128 + 4) * 4 + 64 * 68 * 4;

extern "C" void kernel_launch(void* const* d_in, const int* in_sizes, int n_in,
                              void* d_out, int out_size) {
    const float* x   = (const float*)d_in[0];
    const float* We1 = (const float*)d_in[1];
    const float* be1 = (const float*)d_in[2];
    const float* We2 = (const float*)d_in[3];
    const float* be2 = (const float*)d_in[4];
    const float* Wm1 = (const float*)d_in[5];
    const float* bm1 = (const float*)d_in[6];
    const float* Wm2 = (const float*)d_in[7];
    const float* bm2 = (const float*)d_in[8];
    const float* Wn1 = (const float*)d_in[9];
    const float* bn1 = (const float*)d_in[10];
    const float* Wn2 = (const float*)d_in[11];
    const float* bn2 = (const float*)d_in[12];
    const float* Wd1 = (const float*)d_in[13];
    const float* bd1 = (const float*)d_in[14];
    const float* Wd2 = (const float*)d_in[15];
    const float* bd2 = (const float*)d_in[16];
    const int* s_f  = (const int*)d_in[17];
    const int* r_f  = (const int*)d_in[18];
    const int* s_ds = (const int*)d_in[19];
    const int* r_ds = (const int*)d_in[20];
    const int* s_p  = (const int*)d_in[21];
    const int* r_p  = (const int*)d_in[22];
    const int* s_us = (const int*)d_in[23];
    const int* r_us = (const int*)d_in[24];
    const int* uppool   = (const int*)d_in[25];
    const int* downpool = (const int*)d_in[26];

    int N   = in_sizes[0] / 16;
    int NP  = in_sizes[26];
    int E   = in_sizes[17];
    int EDS = in_sizes[19];
    int EP  = in_sizes[21];
    int EUS = in_sizes[23];
    float* out = (float*)d_out;

    float *A, *B, *C, *AG;
    __half* Mh;
    int *IDX, *CNT, *OFF, *BSUM, *EPOOL, *EPOOL2;
    cudaGetSymbolAddress((void**)&A, g_A);
    cudaGetSymbolAddress((void**)&B, g_B);
    cudaGetSymbolAddress((void**)&C, g_C);
    cudaGetSymbolAddress((void**)&Mh, g_Mh);
    cudaGetSymbolAddress((void**)&AG, g_AG);
    cudaGetSymbolAddress((void**)&IDX, g_IDX);
    cudaGetSymbolAddress((void**)&CNT, g_cnt);
    cudaGetSymbolAddress((void**)&OFF, g_off);
    cudaGetSymbolAddress((void**)&BSUM, g_bsum);
    cudaGetSymbolAddress((void**)&EPOOL, g_epool);
    cudaGetSymbolAddress((void**)&EPOOL2, g_epool2);

    static bool attr_done = false;
    if (!attr_done) {
        cudaFuncSetAttribute(mlp2_tiled<16>, cudaFuncAttributeMaxDynamicSharedMemorySize,
                             (int)MLP_SMEM);
        cudaFuncSetAttribute(mlp2_tiled<64>, cudaFuncAttributeMaxDynamicSharedMemorySize,
                             (int)MLP_SMEM);
        cudaFuncSetAttribute(mlp2_tiled<128>, cudaFuncAttributeMaxDynamicSharedMemorySize,
                             (int)MLP_SMEM);
        cudaFuncSetAttribute(node_decode_tiled, cudaFuncAttributeMaxDynamicSharedMemorySize,
                             (int)ND_SMEM);
        attr_done = true;
    }

    auto grid_for = [](int n) { return mini(((long)n + 63) / 64, 4096); };
    auto wm1 = [&](int l) { return Wm1 + (size_t)l * D * D; };
    auto wm2 = [&](int l) { return Wm2 + (size_t)l * D * D; };
    auto bm1l = [&](int l) { return bm1 + (size_t)l * D; };
    auto bm2l = [&](int l) { return bm2 + (size_t)l * D; };
    auto wn1 = [&](int l) { return Wn1 + (size_t)l * 128 * D; };
    auto wn2 = [&](int l) { return Wn2 + (size_t)l * D * D; };
    auto bn1l = [&](int l) { return bn1 + (size_t)l * D; };
    auto bn2l = [&](int l) { return bn2 + (size_t)l * D; };

    // ---- CSR build for all 4 graphs ----
    long Etot = (long)E + EDS + EP + EUS;
    zero_int_kernel<<<(4 * RSEG + 511) / 512, 512>>>(CNT, 4 * RSEG);
    count_all_kernel<<<mini((Etot + 255) / 256, 4096), 256>>>(
        r_f, r_ds, r_p, r_us, E, EDS, EP, EUS, CNT);
    scan_block_kernel<<<4 * BPG, 1024>>>(CNT, OFF, BSUM,
                                         make_int4(N + 1, N + 1, NP + 1, NP + 1));
    scan_bsum_kernel<<<1, 32>>>(BSUM);
    scan_add_kernel<<<4 * BPG, 1024>>>(OFF, BSUM, CNT);
    fill_all_kernel<<<mini((Etot + 255) / 256, 4096), 256>>>(
        s_f, r_f, s_ds, r_ds, s_p, r_p, s_us, r_us, E, EDS, EP, EUS, CNT, EPOOL);

    // uppool-composed edge sources for msg2/msg6 dedup:
    //   EPOOL2[0..E)      = uppool[epool_fine[p]]
    //   EPOOL2[E..E+EDS)  = uppool[epool_ds[p]]
    compose_esrc_kernel<<<mini(((long)E + 255) / 256, 4096), 256>>>(
        EPOOL, uppool, EPOOL2, E);
    compose_esrc_kernel<<<mini(((long)EDS + 255) / 256, 4096), 256>>>(
        EPOOL + E, uppool, EPOOL2 + E, EDS);

    // pull helpers
    const int* off_f  = OFF + 0 * RSEG;  const int* es_f   = EPOOL;
    const int* off_ds = OFF + 1 * RSEG;  const int* es_ds2 = EPOOL2 + E;
    const int* off_p  = OFF + 2 * RSEG;  const int* es_p   = EPOOL + E + EDS;
    const int* off_us = OFF + 3 * RSEG;  const int* es_us  = EPOOL + (size_t)E + EDS + EP;
    const int* es_f2  = EPOOL2;
    auto pull = [&](const int* off, const int* es, int n) {
        pull_kernel<<<(n * 16 + 255) / 256, 256>>>((const uint2*)Mh, off, es, AG, n);
    };

    // IDX[i] = uppool[downpool[i]]
    compose_idx_kernel<<<(NP + 255) / 256, 256>>>(uppool, downpool, IDX, NP);

    // encode + fused msg0 -> A=h1, Mh=msg0
    mlp2_tiled<16><<<grid_for(N), 256, MLP_SMEM>>>(
        x, nullptr, nullptr, nullptr, We1, be1, We2, be2, nullptr, A, nullptr,
        wm1(0), bm1l(0), wm2(0), bm2l(0), Mh, N);
    pull(off_f, es_f, N);
    // node0 + fused msg1 -> B=h2
    mlp2_tiled<128><<<grid_for(N), 256, MLP_SMEM>>>(
        A, AG, nullptr, nullptr, wn1(0), bn1l(0), wn2(0), bn2l(0), nullptr, B, nullptr,
        wm1(1), bm1l(1), wm2(1), bm2l(1), Mh, N);
    pull(off_f, es_f, N);
    // node1 -> C = h3 (skip source)
    mlp2_tiled<128><<<grid_for(N), 256, MLP_SMEM>>>(
        B, AG, nullptr, nullptr, wn1(1), bn1l(1), wn2(1), bn2l(1), nullptr, C, nullptr,
        nullptr, nullptr, nullptr, nullptr, nullptr, N);
    // msg2 DEDUP: compute over C[0..NP) only; pull maps src through uppool
    mlp2_tiled<64><<<grid_for(NP), 256, MLP_SMEM>>>(
        C, nullptr, nullptr, nullptr, wm1(2), bm1l(2), wm2(2), bm2l(2), nullptr,
        nullptr, Mh, nullptr, nullptr, nullptr, nullptr, nullptr, NP);
    pull(off_ds, es_ds2, N);
    // node2 (in0 = C[uppool[downpool[i]]], in1 = AG[downpool[i]]) + fused msg3
    mlp2_tiled<128><<<grid_for(NP), 256, MLP_SMEM>>>(
        C, AG, IDX, downpool, wn1(2), bn1l(2), wn2(2), bn2l(2), nullptr, B, nullptr,
        wm1(3), bm1l(3), wm2(3), bm2l(3), Mh, NP);
    pull(off_p, es_p, NP);
    // node3 + fused msg4 -> A (NP)
    mlp2_tiled<128><<<grid_for(NP), 256, MLP_SMEM>>>(
        B, AG, nullptr, nullptr, wn1(3), bn1l(3), wn2(3), bn2l(3), nullptr, A, nullptr,
        wm1(4), bm1l(4), wm2(4), bm2l(4), Mh, NP);
    pull(off_p, es_p, NP);
    // node4 -> B (NP)
    mlp2_tiled<128><<<grid_for(NP), 256, MLP_SMEM>>>(
        A, AG, nullptr, nullptr, wn1(4), bn1l(4), wn2(4), bn2l(4), nullptr, B, nullptr,
        nullptr, nullptr, nullptr, nullptr, nullptr, NP);
    // msg5 over B[downpool[i]]
    mlp2_tiled<64><<<grid_for(NP), 256, MLP_SMEM>>>(
        B, nullptr, downpool, nullptr, wm1(5), bm1l(5), wm2(5), bm2l(5), nullptr,
        nullptr, Mh, nullptr, nullptr, nullptr, nullptr, nullptr, NP);
    pull(off_us, es_us, NP);
    // node5: in0 = B[downpool[i]], in1 = AG -> A = g_us (NP)
    mlp2_tiled<128><<<grid_for(NP), 256, MLP_SMEM>>>(
        B, AG, downpool, nullptr, wn1(5), bn1l(5), wn2(5), bn2l(5), nullptr, A, nullptr,
        nullptr, nullptr, nullptr, nullptr, nullptr, NP);
    // msg6 DEDUP: compute over A[0..NP) only; pull maps src through uppool
    mlp2_tiled<64><<<grid_for(NP), 256, MLP_SMEM>>>(
        A, nullptr, nullptr, nullptr, wm1(6), bm1l(6), wm2(6), bm2l(6), nullptr,
        nullptr, Mh, nullptr, nullptr, nullptr, nullptr, nullptr, NP);
    pull(off_f, es_f2, N);
    // node6 (in0 = A[uppool[i]], skip=C) + fused msg7 -> B (N)
    mlp2_tiled<128><<<grid_for(N), 256, MLP_SMEM>>>(
        A, AG, uppool, nullptr, wn1(6), bn1l(6), wn2(6), bn2l(6), C, B, nullptr,
        wm1(7), bm1l(7), wm2(7), bm2l(7), Mh, N);
    pull(off_f, es_f, N);
    // node7 (skip=C) + decode fused -> out[n,2]
    node_decode_tiled<<<grid_for(N), 256, ND_SMEM>>>(
        B, AG, wn1(7), bn1l(7), wn2(7), bn2l(7), C,
        Wd1, bd1, Wd2, bd2, out, N);
}